// round 4
// baseline (speedup 1.0000x reference)
#include <cuda_runtime.h>
#include <cuda_bf16.h>
#include <math.h>
#include <cstdint>

// ---------------- problem constants ----------------
#define Bc    4
#define Tc    2048
#define Cc    1024
#define Hc    64
#define HSc   16
#define NTOK  (Bc*Tc)            // 8192
#define C4    (Cc/4)             // 256
#define NC    (NTOK*Cc)
#define DM4   128
#define DDEC  64
#define K3C   (3*Cc)             // 3072

// ---------------- scratch ----------------
// fp32
__device__ __align__(16) float g_xx [NC];          // xx, reused as y
__device__ __align__(16) float g_r  [NC];
__device__ __align__(16) float g_k  [NC];
__device__ __align__(16) float g_v  [NC];
__device__ __align__(16) float g_we [NC];
// split-bf16 activations (K-tripled layout)
__device__ __align__(16) __nv_bfloat16 g3_xxx[NTOK*K3C];   // reused as yn3
__device__ __align__(16) __nv_bfloat16 g3_xw [NTOK*K3C];
__device__ __align__(16) __nv_bfloat16 g3_xk [NTOK*K3C];
__device__ __align__(16) __nv_bfloat16 g3_xv [NTOK*K3C];
__device__ __align__(16) __nv_bfloat16 g3_xr [NTOK*K3C];
__device__ __align__(16) __nv_bfloat16 g3_h  [NTOK*3*DM4];
__device__ __align__(16) __nv_bfloat16 g3_t1 [NTOK*3*DDEC];
// split-bf16 weights
__device__ __align__(16) __nv_bfloat16 g3_wr [K3C*Cc];
__device__ __align__(16) __nv_bfloat16 g3_wk [K3C*Cc];
__device__ __align__(16) __nv_bfloat16 g3_wv [K3C*Cc];
__device__ __align__(16) __nv_bfloat16 g3_wo [K3C*Cc];
__device__ __align__(16) __nv_bfloat16 g3_w1 [K3C*DM4];
__device__ __align__(16) __nv_bfloat16 g3_dw1[K3C*DDEC];
__device__ __align__(16) __nv_bfloat16 g3_dw2[3*DDEC*Cc];
__device__ __align__(16) __nv_bfloat16 g3_w2 [4*96*Cc];

// ---------------- helpers ----------------
__device__ __forceinline__ uint32_t smem_u32(const void* p) {
    uint32_t a;
    asm("{ .reg .u64 t; cvta.to.shared.u64 t, %1; cvt.u32.u64 %0, t; }" : "=r"(a) : "l"(p));
    return a;
}
__device__ __forceinline__ void ldsm4(uint32_t* r, uint32_t addr) {
    asm volatile("ldmatrix.sync.aligned.m8n8.x4.shared.b16 {%0,%1,%2,%3}, [%4];"
        : "=r"(r[0]), "=r"(r[1]), "=r"(r[2]), "=r"(r[3]) : "r"(addr));
}
__device__ __forceinline__ void ldsm4t(uint32_t* r, uint32_t addr) {
    asm volatile("ldmatrix.sync.aligned.m8n8.x4.trans.shared.b16 {%0,%1,%2,%3}, [%4];"
        : "=r"(r[0]), "=r"(r[1]), "=r"(r[2]), "=r"(r[3]) : "r"(addr));
}
__device__ __forceinline__ void mma16816(float* d, const uint32_t* a, const uint32_t* b) {
    asm volatile(
        "mma.sync.aligned.m16n8k16.row.col.f32.bf16.bf16.f32 "
        "{%0,%1,%2,%3}, {%4,%5,%6,%7}, {%8,%9}, {%0,%1,%2,%3};"
        : "+f"(d[0]), "+f"(d[1]), "+f"(d[2]), "+f"(d[3])
        : "r"(a[0]), "r"(a[1]), "r"(a[2]), "r"(a[3]), "r"(b[0]), "r"(b[1]));
}
__device__ __forceinline__ void cp16(uint32_t sdst, const void* gsrc) {
    asm volatile("cp.async.cg.shared.global [%0], [%1], 16;" :: "r"(sdst), "l"(gsrc));
}
#define CP_COMMIT() asm volatile("cp.async.commit_group;")
#define CP_WAIT2()  asm volatile("cp.async.wait_group 2;")

__device__ __forceinline__ unsigned short bfb(float f) {
    __nv_bfloat16 b = __float2bfloat16_rn(f);
    return *reinterpret_cast<unsigned short*>(&b);
}
__device__ __forceinline__ float bff(unsigned short u) {
    __nv_bfloat16 b = *reinterpret_cast<__nv_bfloat16*>(&u);
    return __bfloat162float(b);
}
// split-store of 2 consecutive cols into K-tripled layout [hi,hi,lo]
__device__ __forceinline__ void split_store2(__nv_bfloat16* dst, int row, int ldc,
                                             int col, float v0, float v1) {
    unsigned short h0 = bfb(v0), h1 = bfb(v1);
    unsigned short l0 = bfb(v0 - bff(h0)), l1 = bfb(v1 - bff(h1));
    uint32_t* p = (uint32_t*)(dst + (size_t)row * (3 * ldc) + 3 * col);
    p[0] = (uint32_t)h0 | ((uint32_t)h0 << 16);
    p[1] = (uint32_t)l0 | ((uint32_t)h1 << 16);
    p[2] = (uint32_t)h1 | ((uint32_t)l1 << 16);
}
// split-store of 4 consecutive cols (col % 4 == 0)
__device__ __forceinline__ void split_store4(__nv_bfloat16* dst, int row, int ldc,
                                             int col, float4 v) {
    unsigned short h0 = bfb(v.x), h1 = bfb(v.y), h2 = bfb(v.z), h3 = bfb(v.w);
    unsigned short l0 = bfb(v.x - bff(h0)), l1 = bfb(v.y - bff(h1));
    unsigned short l2 = bfb(v.z - bff(h2)), l3 = bfb(v.w - bff(h3));
    uint2* p = (uint2*)(dst + (size_t)row * (3 * ldc) + 3 * col);
    p[0] = make_uint2((uint32_t)h0 | ((uint32_t)h0 << 16), (uint32_t)l0 | ((uint32_t)h1 << 16));
    p[1] = make_uint2((uint32_t)h1 | ((uint32_t)l1 << 16), (uint32_t)h2 | ((uint32_t)h2 << 16));
    p[2] = make_uint2((uint32_t)l2 | ((uint32_t)h3 << 16), (uint32_t)h3 | ((uint32_t)l3 << 16));
}

// ---------------- weight convert: B3 rows per k = [hi, lo, hi] ----------------
__global__ void __launch_bounds__(256) k_wconv(const float4* __restrict__ W,
                                               uint2* __restrict__ W3, int total, int N4)
{
    int idx = blockIdx.x * 256 + threadIdx.x;
    if (idx >= total) return;
    int k = idx / N4, c = idx % N4;
    float4 v = W[idx];
    unsigned short h0 = bfb(v.x), h1 = bfb(v.y), h2 = bfb(v.z), h3 = bfb(v.w);
    unsigned short l0 = bfb(v.x - bff(h0)), l1 = bfb(v.y - bff(h1));
    unsigned short l2 = bfb(v.z - bff(h2)), l3 = bfb(v.w - bff(h3));
    uint2 hw = make_uint2((uint32_t)h0 | ((uint32_t)h1 << 16), (uint32_t)h2 | ((uint32_t)h3 << 16));
    uint2 lw = make_uint2((uint32_t)l0 | ((uint32_t)l1 << 16), (uint32_t)l2 | ((uint32_t)l3 << 16));
    W3[(size_t)(3 * k + 0) * N4 + c] = hw;
    W3[(size_t)(3 * k + 1) * N4 + c] = lw;
    W3[(size_t)(3 * k + 2) * N4 + c] = hw;
}

// ---------------- GEMM: bf16 K'=3K, cp.async 4-stage, mma.sync ----------------
enum { EPI_NONE = 0, EPI_TANH = 1, EPI_WEXP = 2, EPI_MIX = 3 };

template<int BM, int BN, int EPI, int OSPL>
__global__ void __launch_bounds__(256, 2)
gemm3(const __nv_bfloat16* __restrict__ A3, const __nv_bfloat16* __restrict__ B3,
      void* __restrict__ C, int nT, int lda3, int ldb, int ldc,
      const float* __restrict__ bias,
      const float* __restrict__ px, const float* __restrict__ pxx)
{
    constexpr int S    = 4;
    constexpr int ASTR = 40;           // u16 per A row (32 data + 8 pad)
    constexpr int BSTR = BN + 8;       // u16 per B row
    constexpr int ABYT = BM * ASTR * 2;
    constexpr int BBYT = 32 * BSTR * 2;
    constexpr int MFR  = BM / 32;
    constexpr int NFR  = BN / 32;
    constexpr int A_CH = BM * 4 / 256; // 16B chunks per thread (A)
    constexpr int B_CH = 32 * (BN / 8) / 256;
    constexpr int BSH  = (BN == 128) ? 4 : 3;

    extern __shared__ char smem[];
    char* As = smem;
    char* Bs = smem + S * ABYT;

    const int tid  = threadIdx.x;
    const int wid  = tid >> 5;
    const int lane = tid & 31;
    const int warpM = (wid >> 2) * (BM / 2);
    const int warpN = (wid & 3) * (BN / 4);
    const int rowBase = blockIdx.x * BM;
    const int colBase = blockIdx.y * BN;

    const uint32_t aBase = smem_u32(As);
    const uint32_t bBase = smem_u32(Bs);
    const int lrow  = lane & 15;
    const int lhalf = (lane >> 4) * 8;
    const uint32_t aLane = (uint32_t)((warpM + lrow) * ASTR + lhalf) * 2;
    const uint32_t bLane = (uint32_t)(lrow * BSTR + warpN + lhalf) * 2;

    float acc[MFR][NFR][4];
#pragma unroll
    for (int i = 0; i < MFR; i++)
#pragma unroll
        for (int j = 0; j < NFR; j++)
#pragma unroll
            for (int e = 0; e < 4; e++) acc[i][j][e] = 0.f;

    auto issue = [&](int t) {
        const int kt = t * 32;
        const int sb = t & (S - 1);
        uint32_t ad = aBase + sb * ABYT;
        uint32_t bd = bBase + sb * BBYT;
#pragma unroll
        for (int i = 0; i < A_CH; i++) {
            int idx = i * 256 + tid;
            int r = idx >> 2, ch = idx & 3;
            cp16(ad + (uint32_t)(r * ASTR + ch * 8) * 2,
                 A3 + (size_t)(rowBase + r) * lda3 + kt + ch * 8);
        }
#pragma unroll
        for (int i = 0; i < B_CH; i++) {
            int idx = i * 256 + tid;
            int r = idx >> BSH, ch = idx & ((1 << BSH) - 1);
            cp16(bd + (uint32_t)(r * BSTR + ch * 8) * 2,
                 B3 + (size_t)(kt + r) * ldb + colBase + ch * 8);
        }
    };

    // prologue: stages 0..2
#pragma unroll
    for (int s = 0; s < S - 1; ++s) {
        if (s < nT) issue(s);
        CP_COMMIT();
    }

    for (int t = 0; t < nT; ++t) {
        CP_WAIT2();
        __syncthreads();
        if (t + S - 1 < nT) issue(t + S - 1);
        CP_COMMIT();

        const int sb = t & (S - 1);
        const uint32_t ad = aBase + sb * ABYT;
        const uint32_t bd = bBase + sb * BBYT;
#pragma unroll
        for (int k16 = 0; k16 < 2; ++k16) {
            uint32_t af[MFR][4];
            uint32_t bf[NFR][2];
#pragma unroll
            for (int mi = 0; mi < MFR; mi++)
                ldsm4(af[mi], ad + aLane + (uint32_t)(mi * 16 * ASTR + k16 * 16) * 2);
#pragma unroll
            for (int p = 0; p < NFR / 2; p++)
                ldsm4t(&bf[p * 2][0], bd + bLane + (uint32_t)(k16 * 16 * BSTR + p * 16) * 2);
#pragma unroll
            for (int mi = 0; mi < MFR; mi++)
#pragma unroll
                for (int ni = 0; ni < NFR; ni++)
                    mma16816(acc[mi][ni], af[mi], bf[ni]);
        }
    }

    // ---- epilogue ----
    const int row0 = rowBase + warpM + (lane >> 2);
    const int col0 = colBase + warpN + (lane & 3) * 2;
#pragma unroll
    for (int mi = 0; mi < MFR; mi++) {
#pragma unroll
        for (int ni = 0; ni < NFR; ni++) {
#pragma unroll
            for (int half = 0; half < 2; half++) {
                int row = row0 + mi * 16 + half * 8;
                int col = col0 + ni * 8;
                float v0 = acc[mi][ni][half * 2 + 0];
                float v1 = acc[mi][ni][half * 2 + 1];
                if (EPI == EPI_TANH) {
                    v0 = tanhf(v0); v1 = tanhf(v1);
                } else if (EPI == EPI_WEXP) {
                    v0 = expf(-expf(bias[col] + v0));
                    v1 = expf(-expf(bias[col + 1] + v1));
                } else if (EPI == EPI_MIX) {
                    float2 xv  = *(const float2*)(px  + (size_t)row * ldc + col);
                    float2 xxv = *(const float2*)(pxx + (size_t)row * ldc + col);
                    v0 = fmaf(xxv.x, bias[col] + v0, xv.x);
                    v1 = fmaf(xxv.y, bias[col + 1] + v1, xv.y);
                }
                if (OSPL) {
                    split_store2((__nv_bfloat16*)C, row, ldc, col, v0, v1);
                } else {
                    float* co = (float*)C + (size_t)row * ldc + col;
                    co[0] = v0; co[1] = v1;
                }
            }
        }
    }
}

// ---------------- token shift: xx fp32 + xxx split ----------------
__global__ void __launch_bounds__(256) k_shift(const float4* __restrict__ x,
                                               const float4* __restrict__ tmx,
                                               float4* __restrict__ oxx,
                                               __nv_bfloat16* __restrict__ oxxx3)
{
    int i = blockIdx.x * 256 + threadIdx.x;
    int c4 = i & (C4 - 1);
    int n  = i >> 8;
    int t  = n & (Tc - 1);
    float4 xv = x[i];
    float4 xp = make_float4(0.f, 0.f, 0.f, 0.f);
    if (t != 0) xp = x[i - C4];
    float4 d;
    d.x = xp.x - xv.x; d.y = xp.y - xv.y; d.z = xp.z - xv.z; d.w = xp.w - xv.w;
    float4 tm = tmx[c4];
    float4 o;
    o.x = fmaf(d.x, tm.x, xv.x); o.y = fmaf(d.y, tm.y, xv.y);
    o.z = fmaf(d.z, tm.z, xv.z); o.w = fmaf(d.w, tm.w, xv.w);
    oxx[i] = d;
    split_store4(oxxx3, n, Cc, c4 * 4, o);
}

// ---------------- WKV6 recurrence ----------------
#define WKV_CT 64
__global__ void __launch_bounds__(32) k_wkv(const float* __restrict__ u_faaaa,
                                            const float* __restrict__ r,
                                            const float* __restrict__ k,
                                            const float* __restrict__ v,
                                            const float* __restrict__ w,
                                            float* __restrict__ y)
{
    const int head_id = blockIdx.x;
    const int b = head_id >> 6;
    const int h = head_id & 63;
    const int lane = threadIdx.x;
    const int ih = lane >> 4;
    const int j  = lane & 15;
    const int base = (b * Tc) * (Hc * HSc) + h * HSc;

    float S[8];
#pragma unroll
    for (int q = 0; q < 8; q++) S[q] = 0.f;
    float u[8];
#pragma unroll
    for (int q = 0; q < 8; q++) u[q] = u_faaaa[h * HSc + ih * 8 + q];

    __shared__ float4 rkw[WKV_CT][HSc];
    __shared__ float  vsh[WKV_CT][HSc];

    for (int t0 = 0; t0 < Tc; t0 += WKV_CT) {
#pragma unroll 4
        for (int idx = lane; idx < WKV_CT * HSc; idx += 32) {
            int tt = idx >> 4;
            int i  = idx & 15;
            int off = base + (t0 + tt) * (Hc * HSc) + i;
            rkw[tt][i] = make_float4(r[off], k[off], w[off], 0.f);
            vsh[tt][i] = v[off];
        }
        __syncwarp();
        for (int tt = 0; tt < WKV_CT; ++tt) {
            float vj  = vsh[tt][j];
            float acc = 0.f;
#pragma unroll
            for (int q = 0; q < 8; q++) {
                float4 e = rkw[tt][ih * 8 + q];
                float kv = e.y * vj;
                acc  = fmaf(e.x, fmaf(u[q], kv, S[q]), acc);
                S[q] = fmaf(e.z, S[q], kv);
            }
            acc += __shfl_xor_sync(0xffffffffu, acc, 16);
            if (ih == 0) y[base + (t0 + tt) * (Hc * HSc) + j] = acc;
        }
        __syncwarp();
    }
}

// ---------------- LayerNorm -> split bf16 ----------------
__global__ void __launch_bounds__(256) k_ln(const float* __restrict__ y,
                                            const float* __restrict__ g,
                                            const float* __restrict__ bb,
                                            __nv_bfloat16* __restrict__ out3)
{
    const int n   = blockIdx.x;
    const int tid = threadIdx.x;
    const float4* yr = (const float4*)(y + (size_t)n * Cc);
    float4 vv = yr[tid];
    float s = vv.x + vv.y + vv.z + vv.w;
    float q = vv.x * vv.x + vv.y * vv.y + vv.z * vv.z + vv.w * vv.w;
#pragma unroll
    for (int o = 16; o > 0; o >>= 1) {
        s += __shfl_xor_sync(0xffffffffu, s, o);
        q += __shfl_xor_sync(0xffffffffu, q, o);
    }
    __shared__ float ssh[8], qsh[8];
    if ((tid & 31) == 0) { ssh[tid >> 5] = s; qsh[tid >> 5] = q; }
    __syncthreads();
    float st = 0.f, qt = 0.f;
#pragma unroll
    for (int wix = 0; wix < 8; wix++) { st += ssh[wix]; qt += qsh[wix]; }
    float mean = st * (1.0f / Cc);
    float var  = qt * (1.0f / Cc) - mean * mean;
    float rstd = rsqrtf(var + 1e-5f);
    float4 gg = ((const float4*)g)[tid];
    float4 b4 = ((const float4*)bb)[tid];
    float4 o;
    o.x = (vv.x - mean) * rstd * gg.x + b4.x;
    o.y = (vv.y - mean) * rstd * gg.y + b4.y;
    o.z = (vv.z - mean) * rstd * gg.z + b4.z;
    o.w = (vv.w - mean) * rstd * gg.w + b4.w;
    split_store4(out3, n, Cc, tid * 4, o);
}

// ---------------- launcher ----------------
#define SM128 (4*(128*40*2 + 32*136*2))
#define SM64  (4*(64*40*2 + 32*72*2))

extern "C" void kernel_launch(void* const* d_in, const int* in_sizes, int n_in,
                              void* d_out, int out_size)
{
    (void)in_sizes; (void)n_in; (void)out_size;
    const float* x     = (const float*)d_in[0];
    const float* tmx   = (const float*)d_in[1];
    const float* tmw   = (const float*)d_in[2];
    const float* tmk   = (const float*)d_in[3];
    const float* tmv   = (const float*)d_in[4];
    const float* tmr   = (const float*)d_in[5];
    const float* w1    = (const float*)d_in[6];
    const float* w2    = (const float*)d_in[7];
    const float* tdec  = (const float*)d_in[8];
    const float* dw1   = (const float*)d_in[9];
    const float* dw2   = (const float*)d_in[10];
    const float* faaaa = (const float*)d_in[11];
    const float* Wr    = (const float*)d_in[12];
    const float* Wk    = (const float*)d_in[13];
    const float* Wv    = (const float*)d_in[14];
    const float* Wo    = (const float*)d_in[15];
    const float* lng   = (const float*)d_in[16];
    const float* lnb   = (const float*)d_in[17];
    float* out = (float*)d_out;

    static float *p_xx = nullptr, *p_r, *p_k, *p_v, *p_we;
    static __nv_bfloat16 *p3_xxx, *p3_xw, *p3_xk, *p3_xv, *p3_xr, *p3_h, *p3_t1,
                         *p3_wr, *p3_wk, *p3_wv, *p3_wo, *p3_w1, *p3_dw1, *p3_dw2, *p3_w2;
    if (!p_xx) {
        cudaGetSymbolAddress((void**)&p_xx,   g_xx);
        cudaGetSymbolAddress((void**)&p_r,    g_r);
        cudaGetSymbolAddress((void**)&p_k,    g_k);
        cudaGetSymbolAddress((void**)&p_v,    g_v);
        cudaGetSymbolAddress((void**)&p_we,   g_we);
        cudaGetSymbolAddress((void**)&p3_xxx, g3_xxx);
        cudaGetSymbolAddress((void**)&p3_xw,  g3_xw);
        cudaGetSymbolAddress((void**)&p3_xk,  g3_xk);
        cudaGetSymbolAddress((void**)&p3_xv,  g3_xv);
        cudaGetSymbolAddress((void**)&p3_xr,  g3_xr);
        cudaGetSymbolAddress((void**)&p3_h,   g3_h);
        cudaGetSymbolAddress((void**)&p3_t1,  g3_t1);
        cudaGetSymbolAddress((void**)&p3_wr,  g3_wr);
        cudaGetSymbolAddress((void**)&p3_wk,  g3_wk);
        cudaGetSymbolAddress((void**)&p3_wv,  g3_wv);
        cudaGetSymbolAddress((void**)&p3_wo,  g3_wo);
        cudaGetSymbolAddress((void**)&p3_w1,  g3_w1);
        cudaGetSymbolAddress((void**)&p3_dw1, g3_dw1);
        cudaGetSymbolAddress((void**)&p3_dw2, g3_dw2);
        cudaGetSymbolAddress((void**)&p3_w2,  g3_w2);
        cudaFuncSetAttribute(gemm3<128,128,EPI_NONE,0>, cudaFuncAttributeMaxDynamicSharedMemorySize, SM128);
        cudaFuncSetAttribute(gemm3<128,128,EPI_WEXP,0>, cudaFuncAttributeMaxDynamicSharedMemorySize, SM128);
        cudaFuncSetAttribute(gemm3<128,128,EPI_MIX,1>,  cudaFuncAttributeMaxDynamicSharedMemorySize, SM128);
        cudaFuncSetAttribute(gemm3<64,64,EPI_TANH,1>,   cudaFuncAttributeMaxDynamicSharedMemorySize, SM64);
    }
    float* p_y = p_xx;               // y overwrites xx (dead after mix epilogues)
    __nv_bfloat16* p3_yn = p3_xxx;   // yn3 overwrites xxx3 (dead after h gemm)

    // 0) weight converts
    k_wconv<<<(Cc*Cc/4 + 255)/256, 256>>>((const float4*)Wr,  (uint2*)p3_wr,  Cc*Cc/4,  Cc/4);
    k_wconv<<<(Cc*Cc/4 + 255)/256, 256>>>((const float4*)Wk,  (uint2*)p3_wk,  Cc*Cc/4,  Cc/4);
    k_wconv<<<(Cc*Cc/4 + 255)/256, 256>>>((const float4*)Wv,  (uint2*)p3_wv,  Cc*Cc/4,  Cc/4);
    k_wconv<<<(Cc*Cc/4 + 255)/256, 256>>>((const float4*)Wo,  (uint2*)p3_wo,  Cc*Cc/4,  Cc/4);
    k_wconv<<<(Cc*DM4/4 + 255)/256, 256>>>((const float4*)w1, (uint2*)p3_w1,  Cc*DM4/4, DM4/4);
    k_wconv<<<(Cc*DDEC/4 + 255)/256, 256>>>((const float4*)dw1,(uint2*)p3_dw1, Cc*DDEC/4, DDEC/4);
    k_wconv<<<(DDEC*Cc/4 + 255)/256, 256>>>((const float4*)dw2,(uint2*)p3_dw2, DDEC*Cc/4, Cc/4);
    for (int f = 0; f < 4; ++f)
        k_wconv<<<(32*Cc/4 + 255)/256, 256>>>((const float4*)(w2 + (size_t)f*32*Cc),
                                              (uint2*)(p3_w2 + (size_t)f*96*Cc), 32*Cc/4, Cc/4);

    // 1) token shift
    k_shift<<<NTOK, 256>>>((const float4*)x, (const float4*)tmx,
                           (float4*)p_xx, p3_xxx);

    // 2) h = tanh(xxx @ w1)  [8192 x 128], K'=3072
    gemm3<64,64,EPI_TANH,1><<<dim3(NTOK/64, DM4/64), 256, SM64>>>(
        p3_xxx, p3_w1, p3_h, K3C/32, K3C, DM4, DM4, nullptr, nullptr, nullptr);

    // 3) x{w,k,v,r} = x + xx*(tm + h_f @ w2[f]), K'=96
    {
        const float* tms[4] = { tmw, tmk, tmv, tmr };
        __nv_bfloat16* outs[4] = { p3_xw, p3_xk, p3_xv, p3_xr };
        for (int f = 0; f < 4; ++f)
            gemm3<128,128,EPI_MIX,1><<<dim3(NTOK/128, Cc/128), 256, SM128>>>(
                p3_h + 96*f, p3_w2 + (size_t)f*96*Cc, outs[f],
                3, 3*DM4, Cc, Cc, tms[f], x, p_xx);
    }

    // 4) t1 = tanh(xw @ dw1), K'=3072, N=64
    gemm3<64,64,EPI_TANH,1><<<dim3(NTOK/64, 1), 256, SM64>>>(
        p3_xw, p3_dw1, p3_t1, K3C/32, K3C, DDEC, DDEC, nullptr, nullptr, nullptr);

    // 5) we = exp(-exp(tdec + t1 @ dw2)), K'=192
    gemm3<128,128,EPI_WEXP,0><<<dim3(NTOK/128, Cc/128), 256, SM128>>>(
        p3_t1, p3_dw2, p_we, 6, 3*DDEC, Cc, Cc, tdec, nullptr, nullptr);

    // 6) r/k/v projections, K'=3072
    gemm3<128,128,EPI_NONE,0><<<dim3(NTOK/128, Cc/128), 256, SM128>>>(
        p3_xr, p3_wr, p_r, K3C/32, K3C, Cc, Cc, nullptr, nullptr, nullptr);
    gemm3<128,128,EPI_NONE,0><<<dim3(NTOK/128, Cc/128), 256, SM128>>>(
        p3_xk, p3_wk, p_k, K3C/32, K3C, Cc, Cc, nullptr, nullptr, nullptr);
    gemm3<128,128,EPI_NONE,0><<<dim3(NTOK/128, Cc/128), 256, SM128>>>(
        p3_xv, p3_wv, p_v, K3C/32, K3C, Cc, Cc, nullptr, nullptr, nullptr);

    // 7) WKV6
    k_wkv<<<Bc * Hc, 32>>>(faaaa, p_r, p_k, p_v, p_we, p_y);

    // 8) LayerNorm -> split
    k_ln<<<NTOK, 256>>>(p_y, lng, lnb, p3_yn);

    // 9) out = yn @ Wo
    gemm3<128,128,EPI_NONE,0><<<dim3(NTOK/128, Cc/128), 256, SM128>>>(
        p3_yn, p3_wo, out, K3C/32, K3C, Cc, Cc, nullptr, nullptr, nullptr);
}

// round 5
// speedup vs baseline: 1.8213x; 1.8213x over previous
#include <cuda_runtime.h>
#include <cuda_fp16.h>
#include <math.h>
#include <cstdint>

// ---------------- problem constants ----------------
#define Bc    4
#define Tc    2048
#define Cc    1024
#define Hc    64
#define HSc   16
#define NTOK  (Bc*Tc)            // 8192
#define C4    (Cc/4)             // 256
#define NC    (NTOK*Cc)
#define DM4   128
#define DDEC  64

// ---------------- scratch ----------------
// fp32
__device__ __align__(16) float g_xx [NC];          // xx, reused as y
__device__ __align__(16) float g_r  [NC];
__device__ __align__(16) float g_k  [NC];
__device__ __align__(16) float g_v  [NC];
__device__ __align__(16) float g_we [NC];
// fp16 activations
__device__ __align__(16) __half g16_xxx[NC];       // reused as yn
__device__ __align__(16) __half g16_xw [NC];
__device__ __align__(16) __half g16_xk [NC];
__device__ __align__(16) __half g16_xv [NC];
__device__ __align__(16) __half g16_xr [NC];
__device__ __align__(16) __half g16_h  [NTOK*DM4];
__device__ __align__(16) __half g16_t1 [NTOK*DDEC];
// fp16 weights
__device__ __align__(16) __half g16_wr [Cc*Cc];
__device__ __align__(16) __half g16_wk [Cc*Cc];
__device__ __align__(16) __half g16_wv [Cc*Cc];
__device__ __align__(16) __half g16_wo [Cc*Cc];
__device__ __align__(16) __half g16_w1 [Cc*DM4];
__device__ __align__(16) __half g16_dw1[Cc*DDEC];
__device__ __align__(16) __half g16_dw2[DDEC*Cc];
__device__ __align__(16) __half g16_w2 [4*32*Cc];

// ---------------- helpers ----------------
__device__ __forceinline__ uint32_t smem_u32(const void* p) {
    uint32_t a;
    asm("{ .reg .u64 t; cvta.to.shared.u64 t, %1; cvt.u32.u64 %0, t; }" : "=r"(a) : "l"(p));
    return a;
}
__device__ __forceinline__ void ldsm4(uint32_t* r, uint32_t addr) {
    asm volatile("ldmatrix.sync.aligned.m8n8.x4.shared.b16 {%0,%1,%2,%3}, [%4];"
        : "=r"(r[0]), "=r"(r[1]), "=r"(r[2]), "=r"(r[3]) : "r"(addr));
}
__device__ __forceinline__ void ldsm4t(uint32_t* r, uint32_t addr) {
    asm volatile("ldmatrix.sync.aligned.m8n8.x4.trans.shared.b16 {%0,%1,%2,%3}, [%4];"
        : "=r"(r[0]), "=r"(r[1]), "=r"(r[2]), "=r"(r[3]) : "r"(addr));
}
__device__ __forceinline__ void mma16816(float* d, const uint32_t* a, const uint32_t* b) {
    asm volatile(
        "mma.sync.aligned.m16n8k16.row.col.f32.f16.f16.f32 "
        "{%0,%1,%2,%3}, {%4,%5,%6,%7}, {%8,%9}, {%0,%1,%2,%3};"
        : "+f"(d[0]), "+f"(d[1]), "+f"(d[2]), "+f"(d[3])
        : "r"(a[0]), "r"(a[1]), "r"(a[2]), "r"(a[3]), "r"(b[0]), "r"(b[1]));
}
__device__ __forceinline__ void cp16(uint32_t sdst, const void* gsrc) {
    asm volatile("cp.async.cg.shared.global [%0], [%1], 16;" :: "r"(sdst), "l"(gsrc));
}
#define CP_COMMIT() asm volatile("cp.async.commit_group;")
#define CP_WAIT2()  asm volatile("cp.async.wait_group 2;")

__device__ __forceinline__ uint32_t h2u(float a, float b) {
    __half2 h = __floats2half2_rn(a, b);
    return *reinterpret_cast<uint32_t*>(&h);
}
__device__ __forceinline__ uint2 f4toh(float4 v) {
    return make_uint2(h2u(v.x, v.y), h2u(v.z, v.w));
}

// ---------------- one-shot weight convert (8 segments) ----------------
struct CvtArgs {
    const float4* s[8];
    uint2* d[8];
    int off[9];
};
__global__ void __launch_bounds__(256) k_cvt(CvtArgs a) {
    int i = blockIdx.x * 256 + threadIdx.x;
    if (i >= a.off[8]) return;
#pragma unroll
    for (int sg = 0; sg < 8; sg++) {
        if (i < a.off[sg + 1]) {
            int j = i - a.off[sg];
            a.d[sg][j] = f4toh(a.s[sg][j]);
            return;
        }
    }
}

// ---------------- GEMM: fp16, cp.async 4-stage, mma.sync ----------------
enum { EPI_NONE = 0, EPI_TANH = 1, EPI_WEXP = 2, EPI_MIX = 3 };

template<int BM, int BN, int EPI, int OUTH>
__global__ void __launch_bounds__(256, 2)
gemmh(const __half* __restrict__ A, const __half* __restrict__ B,
      void* __restrict__ C, int nT, int lda, int ldb, int ldc,
      const float* __restrict__ bias,
      const float* __restrict__ px, const float* __restrict__ pxx)
{
    constexpr int S    = 4;
    constexpr int ASTR = 40;           // u16 per A row (32 data + 8 pad)
    constexpr int BSTR = BN + 8;       // u16 per B row
    constexpr int ABYT = BM * ASTR * 2;
    constexpr int BBYT = 32 * BSTR * 2;
    constexpr int MFR  = BM / 32;
    constexpr int NFR  = BN / 32;
    constexpr int A_CH = BM * 4 / 256;
    constexpr int B_CH = 32 * (BN / 8) / 256;
    constexpr int BSH  = (BN == 128) ? 4 : 3;

    extern __shared__ char smem[];
    char* As = smem;
    char* Bs = smem + S * ABYT;

    const int tid  = threadIdx.x;
    const int wid  = tid >> 5;
    const int lane = tid & 31;
    const int warpM = (wid >> 2) * (BM / 2);
    const int warpN = (wid & 3) * (BN / 4);
    const int rowBase = blockIdx.x * BM;
    const int colBase = blockIdx.y * BN;

    const uint32_t aBase = smem_u32(As);
    const uint32_t bBase = smem_u32(Bs);
    const int lrow  = lane & 15;
    const int lhalf = (lane >> 4) * 8;
    const uint32_t aLane = (uint32_t)((warpM + lrow) * ASTR + lhalf) * 2;
    const uint32_t bLane = (uint32_t)(lrow * BSTR + warpN + lhalf) * 2;

    float acc[MFR][NFR][4];
#pragma unroll
    for (int i = 0; i < MFR; i++)
#pragma unroll
        for (int j = 0; j < NFR; j++)
#pragma unroll
            for (int e = 0; e < 4; e++) acc[i][j][e] = 0.f;

    auto issue = [&](int t) {
        const int kt = t * 32;
        const int sb = t & (S - 1);
        uint32_t ad = aBase + sb * ABYT;
        uint32_t bd = bBase + sb * BBYT;
#pragma unroll
        for (int i = 0; i < A_CH; i++) {
            int idx = i * 256 + tid;
            int r = idx >> 2, ch = idx & 3;
            cp16(ad + (uint32_t)(r * ASTR + ch * 8) * 2,
                 A + (size_t)(rowBase + r) * lda + kt + ch * 8);
        }
#pragma unroll
        for (int i = 0; i < B_CH; i++) {
            int idx = i * 256 + tid;
            int r = idx >> BSH, ch = idx & ((1 << BSH) - 1);
            cp16(bd + (uint32_t)(r * BSTR + ch * 8) * 2,
                 B + (size_t)(kt + r) * ldb + colBase + ch * 8);
        }
    };

#pragma unroll
    for (int s = 0; s < S - 1; ++s) {
        if (s < nT) issue(s);
        CP_COMMIT();
    }

    for (int t = 0; t < nT; ++t) {
        CP_WAIT2();
        __syncthreads();
        if (t + S - 1 < nT) issue(t + S - 1);
        CP_COMMIT();

        const int sb = t & (S - 1);
        const uint32_t ad = aBase + sb * ABYT;
        const uint32_t bd = bBase + sb * BBYT;
#pragma unroll
        for (int k16 = 0; k16 < 2; ++k16) {
            uint32_t af[MFR][4];
            uint32_t bf[NFR][2];
#pragma unroll
            for (int mi = 0; mi < MFR; mi++)
                ldsm4(af[mi], ad + aLane + (uint32_t)(mi * 16 * ASTR + k16 * 16) * 2);
#pragma unroll
            for (int p = 0; p < NFR / 2; p++)
                ldsm4t(&bf[p * 2][0], bd + bLane + (uint32_t)(k16 * 16 * BSTR + p * 16) * 2);
#pragma unroll
            for (int mi = 0; mi < MFR; mi++)
#pragma unroll
                for (int ni = 0; ni < NFR; ni++)
                    mma16816(acc[mi][ni], af[mi], bf[ni]);
        }
    }

    // ---- epilogue ----
    const int row0 = rowBase + warpM + (lane >> 2);
    const int col0 = colBase + warpN + (lane & 3) * 2;
#pragma unroll
    for (int mi = 0; mi < MFR; mi++) {
#pragma unroll
        for (int ni = 0; ni < NFR; ni++) {
#pragma unroll
            for (int half = 0; half < 2; half++) {
                int row = row0 + mi * 16 + half * 8;
                int col = col0 + ni * 8;
                float v0 = acc[mi][ni][half * 2 + 0];
                float v1 = acc[mi][ni][half * 2 + 1];
                if (EPI == EPI_TANH) {
                    v0 = tanhf(v0); v1 = tanhf(v1);
                } else if (EPI == EPI_WEXP) {
                    v0 = expf(-expf(bias[col] + v0));
                    v1 = expf(-expf(bias[col + 1] + v1));
                } else if (EPI == EPI_MIX) {
                    float2 xv  = *(const float2*)(px  + (size_t)row * ldc + col);
                    float2 xxv = *(const float2*)(pxx + (size_t)row * ldc + col);
                    v0 = fmaf(xxv.x, bias[col] + v0, xv.x);
                    v1 = fmaf(xxv.y, bias[col + 1] + v1, xv.y);
                }
                if (OUTH) {
                    *(uint32_t*)((__half*)C + (size_t)row * ldc + col) = h2u(v0, v1);
                } else {
                    float* co = (float*)C + (size_t)row * ldc + col;
                    co[0] = v0; co[1] = v1;
                }
            }
        }
    }
}

// ---------------- token shift: xx fp32 + xxx fp16 ----------------
__global__ void __launch_bounds__(256) k_shift(const float4* __restrict__ x,
                                               const float4* __restrict__ tmx,
                                               float4* __restrict__ oxx,
                                               uint2* __restrict__ oxxx)
{
    int i = blockIdx.x * 256 + threadIdx.x;
    int c4 = i & (C4 - 1);
    int n  = i >> 8;
    int t  = n & (Tc - 1);
    float4 xv = x[i];
    float4 xp = make_float4(0.f, 0.f, 0.f, 0.f);
    if (t != 0) xp = x[i - C4];
    float4 d;
    d.x = xp.x - xv.x; d.y = xp.y - xv.y; d.z = xp.z - xv.z; d.w = xp.w - xv.w;
    float4 tm = tmx[c4];
    float4 o;
    o.x = fmaf(d.x, tm.x, xv.x); o.y = fmaf(d.y, tm.y, xv.y);
    o.z = fmaf(d.z, tm.z, xv.z); o.w = fmaf(d.w, tm.w, xv.w);
    oxx[i]  = d;
    oxxx[i] = f4toh(o);
}

// ---------------- WKV6 recurrence ----------------
#define WKV_CT 64
__global__ void __launch_bounds__(32) k_wkv(const float* __restrict__ u_faaaa,
                                            const float* __restrict__ r,
                                            const float* __restrict__ k,
                                            const float* __restrict__ v,
                                            const float* __restrict__ w,
                                            float* __restrict__ y)
{
    const int head_id = blockIdx.x;
    const int b = head_id >> 6;
    const int h = head_id & 63;
    const int lane = threadIdx.x;
    const int ih = lane >> 4;
    const int j  = lane & 15;
    const int base = (b * Tc) * (Hc * HSc) + h * HSc;

    float S[8];
#pragma unroll
    for (int q = 0; q < 8; q++) S[q] = 0.f;
    float u[8];
#pragma unroll
    for (int q = 0; q < 8; q++) u[q] = u_faaaa[h * HSc + ih * 8 + q];

    __shared__ float4 rkw[WKV_CT][HSc];
    __shared__ float  vsh[WKV_CT][HSc];

    for (int t0 = 0; t0 < Tc; t0 += WKV_CT) {
#pragma unroll 4
        for (int idx = lane; idx < WKV_CT * HSc; idx += 32) {
            int tt = idx >> 4;
            int i  = idx & 15;
            int off = base + (t0 + tt) * (Hc * HSc) + i;
            rkw[tt][i] = make_float4(r[off], k[off], w[off], 0.f);
            vsh[tt][i] = v[off];
        }
        __syncwarp();
        for (int tt = 0; tt < WKV_CT; ++tt) {
            float vj  = vsh[tt][j];
            float acc = 0.f;
#pragma unroll
            for (int q = 0; q < 8; q++) {
                float4 e = rkw[tt][ih * 8 + q];
                float kv = e.y * vj;
                acc  = fmaf(e.x, fmaf(u[q], kv, S[q]), acc);
                S[q] = fmaf(e.z, S[q], kv);
            }
            acc += __shfl_xor_sync(0xffffffffu, acc, 16);
            if (ih == 0) y[base + (t0 + tt) * (Hc * HSc) + j] = acc;
        }
        __syncwarp();
    }
}

// ---------------- LayerNorm -> fp16 ----------------
__global__ void __launch_bounds__(256) k_ln(const float* __restrict__ y,
                                            const float* __restrict__ g,
                                            const float* __restrict__ bb,
                                            uint2* __restrict__ out16)
{
    const int n   = blockIdx.x;
    const int tid = threadIdx.x;
    const float4* yr = (const float4*)(y + (size_t)n * Cc);
    float4 vv = yr[tid];
    float s = vv.x + vv.y + vv.z + vv.w;
    float q = vv.x * vv.x + vv.y * vv.y + vv.z * vv.z + vv.w * vv.w;
#pragma unroll
    for (int o = 16; o > 0; o >>= 1) {
        s += __shfl_xor_sync(0xffffffffu, s, o);
        q += __shfl_xor_sync(0xffffffffu, q, o);
    }
    __shared__ float ssh[8], qsh[8];
    if ((tid & 31) == 0) { ssh[tid >> 5] = s; qsh[tid >> 5] = q; }
    __syncthreads();
    float st = 0.f, qt = 0.f;
#pragma unroll
    for (int wix = 0; wix < 8; wix++) { st += ssh[wix]; qt += qsh[wix]; }
    float mean = st * (1.0f / Cc);
    float var  = qt * (1.0f / Cc) - mean * mean;
    float rstd = rsqrtf(var + 1e-5f);
    float4 gg = ((const float4*)g)[tid];
    float4 b4 = ((const float4*)bb)[tid];
    float4 o;
    o.x = (vv.x - mean) * rstd * gg.x + b4.x;
    o.y = (vv.y - mean) * rstd * gg.y + b4.y;
    o.z = (vv.z - mean) * rstd * gg.z + b4.z;
    o.w = (vv.w - mean) * rstd * gg.w + b4.w;
    out16[(size_t)n * (Cc / 4) + tid] = f4toh(o);
}

// ---------------- launcher ----------------
#define SM128 (4*(128*40*2 + 32*136*2))
#define SM64  (4*(64*40*2 + 32*72*2))

extern "C" void kernel_launch(void* const* d_in, const int* in_sizes, int n_in,
                              void* d_out, int out_size)
{
    (void)in_sizes; (void)n_in; (void)out_size;
    const float* x     = (const float*)d_in[0];
    const float* tmx   = (const float*)d_in[1];
    const float* tmw   = (const float*)d_in[2];
    const float* tmk   = (const float*)d_in[3];
    const float* tmv   = (const float*)d_in[4];
    const float* tmr   = (const float*)d_in[5];
    const float* w1    = (const float*)d_in[6];
    const float* w2    = (const float*)d_in[7];
    const float* tdec  = (const float*)d_in[8];
    const float* dw1   = (const float*)d_in[9];
    const float* dw2   = (const float*)d_in[10];
    const float* faaaa = (const float*)d_in[11];
    const float* Wr    = (const float*)d_in[12];
    const float* Wk    = (const float*)d_in[13];
    const float* Wv    = (const float*)d_in[14];
    const float* Wo    = (const float*)d_in[15];
    const float* lng   = (const float*)d_in[16];
    const float* lnb   = (const float*)d_in[17];
    float* out = (float*)d_out;

    static float *p_xx = nullptr, *p_r, *p_k, *p_v, *p_we;
    static __half *p16_xxx, *p16_xw, *p16_xk, *p16_xv, *p16_xr, *p16_h, *p16_t1,
                  *p16_wr, *p16_wk, *p16_wv, *p16_wo, *p16_w1, *p16_dw1, *p16_dw2, *p16_w2;
    if (!p_xx) {
        cudaGetSymbolAddress((void**)&p_xx,    g_xx);
        cudaGetSymbolAddress((void**)&p_r,     g_r);
        cudaGetSymbolAddress((void**)&p_k,     g_k);
        cudaGetSymbolAddress((void**)&p_v,     g_v);
        cudaGetSymbolAddress((void**)&p_we,    g_we);
        cudaGetSymbolAddress((void**)&p16_xxx, g16_xxx);
        cudaGetSymbolAddress((void**)&p16_xw,  g16_xw);
        cudaGetSymbolAddress((void**)&p16_xk,  g16_xk);
        cudaGetSymbolAddress((void**)&p16_xv,  g16_xv);
        cudaGetSymbolAddress((void**)&p16_xr,  g16_xr);
        cudaGetSymbolAddress((void**)&p16_h,   g16_h);
        cudaGetSymbolAddress((void**)&p16_t1,  g16_t1);
        cudaGetSymbolAddress((void**)&p16_wr,  g16_wr);
        cudaGetSymbolAddress((void**)&p16_wk,  g16_wk);
        cudaGetSymbolAddress((void**)&p16_wv,  g16_wv);
        cudaGetSymbolAddress((void**)&p16_wo,  g16_wo);
        cudaGetSymbolAddress((void**)&p16_w1,  g16_w1);
        cudaGetSymbolAddress((void**)&p16_dw1, g16_dw1);
        cudaGetSymbolAddress((void**)&p16_dw2, g16_dw2);
        cudaGetSymbolAddress((void**)&p16_w2,  g16_w2);
        cudaFuncSetAttribute(gemmh<128,128,EPI_NONE,0>, cudaFuncAttributeMaxDynamicSharedMemorySize, SM128);
        cudaFuncSetAttribute(gemmh<128,128,EPI_WEXP,0>, cudaFuncAttributeMaxDynamicSharedMemorySize, SM128);
        cudaFuncSetAttribute(gemmh<128,128,EPI_MIX,1>,  cudaFuncAttributeMaxDynamicSharedMemorySize, SM128);
        cudaFuncSetAttribute(gemmh<64,64,EPI_TANH,1>,   cudaFuncAttributeMaxDynamicSharedMemorySize, SM64);
    }
    float* p_y = p_xx;             // y overwrites xx (dead after mix epilogues)
    __half* p16_yn = p16_xxx;      // yn overwrites xxx (dead after h gemm)

    // 0) weight converts — single launch, 8 segments (counts in float4)
    {
        CvtArgs a;
        const float* srcs[8] = { Wr, Wk, Wv, Wo, w1, dw1, dw2, w2 };
        __half* dsts[8] = { p16_wr, p16_wk, p16_wv, p16_wo, p16_w1, p16_dw1, p16_dw2, p16_w2 };
        int cnts[8] = { Cc*Cc/4, Cc*Cc/4, Cc*Cc/4, Cc*Cc/4, Cc*DM4/4, Cc*DDEC/4, DDEC*Cc/4, 4*32*Cc/4 };
        int cum = 0;
        for (int i = 0; i < 8; i++) {
            a.s[i] = (const float4*)srcs[i];
            a.d[i] = (uint2*)dsts[i];
            a.off[i] = cum;
            cum += cnts[i];
        }
        a.off[8] = cum;
        k_cvt<<<(cum + 255) / 256, 256>>>(a);
    }

    // 1) token shift
    k_shift<<<NTOK, 256>>>((const float4*)x, (const float4*)tmx,
                           (float4*)p_xx, (uint2*)p16_xxx);

    // 2) h = tanh(xxx @ w1)  [8192,1024]x[1024,128]
    gemmh<64,64,EPI_TANH,1><<<dim3(NTOK/64, DM4/64), 256, SM64>>>(
        p16_xxx, p16_w1, p16_h, Cc/32, Cc, DM4, DM4, nullptr, nullptr, nullptr);

    // 3) x{w,k,v,r} = x + xx*(tm + h_f @ w2[f])  K=32
    {
        const float* tms[4] = { tmw, tmk, tmv, tmr };
        __half* outs[4] = { p16_xw, p16_xk, p16_xv, p16_xr };
        for (int f = 0; f < 4; ++f)
            gemmh<128,128,EPI_MIX,1><<<dim3(NTOK/128, Cc/128), 256, SM128>>>(
                p16_h + 32*f, p16_w2 + (size_t)f*32*Cc, outs[f],
                1, DM4, Cc, Cc, tms[f], x, p_xx);
    }

    // 4) t1 = tanh(xw @ dw1)  K=1024, N=64
    gemmh<64,64,EPI_TANH,1><<<dim3(NTOK/64, 1), 256, SM64>>>(
        p16_xw, p16_dw1, p16_t1, Cc/32, Cc, DDEC, DDEC, nullptr, nullptr, nullptr);

    // 5) we = exp(-exp(tdec + t1 @ dw2))  K=64
    gemmh<128,128,EPI_WEXP,0><<<dim3(NTOK/128, Cc/128), 256, SM128>>>(
        p16_t1, p16_dw2, p_we, DDEC/32, DDEC, Cc, Cc, tdec, nullptr, nullptr);

    // 6) r/k/v projections  K=1024
    gemmh<128,128,EPI_NONE,0><<<dim3(NTOK/128, Cc/128), 256, SM128>>>(
        p16_xr, p16_wr, p_r, Cc/32, Cc, Cc, Cc, nullptr, nullptr, nullptr);
    gemmh<128,128,EPI_NONE,0><<<dim3(NTOK/128, Cc/128), 256, SM128>>>(
        p16_xk, p16_wk, p_k, Cc/32, Cc, Cc, Cc, nullptr, nullptr, nullptr);
    gemmh<128,128,EPI_NONE,0><<<dim3(NTOK/128, Cc/128), 256, SM128>>>(
        p16_xv, p16_wv, p_v, Cc/32, Cc, Cc, Cc, nullptr, nullptr, nullptr);

    // 7) WKV6
    k_wkv<<<Bc * Hc, 32>>>(faaaa, p_r, p_k, p_v, p_we, p_y);

    // 8) LayerNorm -> fp16
    k_ln<<<NTOK, 256>>>(p_y, lng, lnb, (uint2*)p16_yn);

    // 9) out = yn @ Wo  K=1024
    gemmh<128,128,EPI_NONE,0><<<dim3(NTOK/128, Cc/128), 256, SM128>>>(
        p16_yn, p16_wo, out, Cc/32, Cc, Cc, Cc, nullptr, nullptr, nullptr);
}

// round 6
// speedup vs baseline: 2.5436x; 1.3966x over previous
#include <cuda_runtime.h>
#include <cuda_fp16.h>
#include <math.h>
#include <cstdint>

// ---------------- problem constants ----------------
#define Bc    4
#define Tc    2048
#define Cc    1024
#define Hc    64
#define HSc   16
#define NTOK  (Bc*Tc)            // 8192
#define C4    (Cc/4)             // 256
#define NC    (NTOK*Cc)
#define DM4   128
#define DDEC  64

// ---------------- scratch ----------------
// fp32
__device__ __align__(16) float g_y  [NC];
__device__ __align__(16) float g_r  [NC];
__device__ __align__(16) float g_k  [NC];
__device__ __align__(16) float g_v  [NC];
__device__ __align__(16) float g_we [NC];
// fp16 activations
__device__ __align__(16) __half g16_x  [NC];
__device__ __align__(16) __half g16_xx [NC];
__device__ __align__(16) __half g16_xxx[NC];       // reused as yn
__device__ __align__(16) __half g16_xw [NC];
__device__ __align__(16) __half g16_xk [NC];
__device__ __align__(16) __half g16_xv [NC];
__device__ __align__(16) __half g16_xr [NC];
__device__ __align__(16) __half g16_h  [NTOK*DM4];
__device__ __align__(16) __half g16_t1 [NTOK*DDEC];
// fp16 weights
__device__ __align__(16) __half g16_wr [Cc*Cc];
__device__ __align__(16) __half g16_wk [Cc*Cc];
__device__ __align__(16) __half g16_wv [Cc*Cc];
__device__ __align__(16) __half g16_wo [Cc*Cc];
__device__ __align__(16) __half g16_w1 [Cc*DM4];
__device__ __align__(16) __half g16_dw1[Cc*DDEC];
__device__ __align__(16) __half g16_dw2[DDEC*Cc];
__device__ __align__(16) __half g16_w2 [4*32*Cc];

// ---------------- helpers ----------------
__device__ __forceinline__ uint32_t smem_u32(const void* p) {
    uint32_t a;
    asm("{ .reg .u64 t; cvta.to.shared.u64 t, %1; cvt.u32.u64 %0, t; }" : "=r"(a) : "l"(p));
    return a;
}
__device__ __forceinline__ void ldsm4(uint32_t* r, uint32_t addr) {
    asm volatile("ldmatrix.sync.aligned.m8n8.x4.shared.b16 {%0,%1,%2,%3}, [%4];"
        : "=r"(r[0]), "=r"(r[1]), "=r"(r[2]), "=r"(r[3]) : "r"(addr));
}
__device__ __forceinline__ void ldsm4t(uint32_t* r, uint32_t addr) {
    asm volatile("ldmatrix.sync.aligned.m8n8.x4.trans.shared.b16 {%0,%1,%2,%3}, [%4];"
        : "=r"(r[0]), "=r"(r[1]), "=r"(r[2]), "=r"(r[3]) : "r"(addr));
}
__device__ __forceinline__ void mma16816(float* d, const uint32_t* a, const uint32_t* b) {
    asm volatile(
        "mma.sync.aligned.m16n8k16.row.col.f32.f16.f16.f32 "
        "{%0,%1,%2,%3}, {%4,%5,%6,%7}, {%8,%9}, {%0,%1,%2,%3};"
        : "+f"(d[0]), "+f"(d[1]), "+f"(d[2]), "+f"(d[3])
        : "r"(a[0]), "r"(a[1]), "r"(a[2]), "r"(a[3]), "r"(b[0]), "r"(b[1]));
}
__device__ __forceinline__ void cp16(uint32_t sdst, const void* gsrc) {
    asm volatile("cp.async.cg.shared.global [%0], [%1], 16;" :: "r"(sdst), "l"(gsrc));
}
#define CP_COMMIT() asm volatile("cp.async.commit_group;")
#define CP_WAIT2()  asm volatile("cp.async.wait_group 2;")
#define CP_WAIT1()  asm volatile("cp.async.wait_group 1;")
#define CP_WAIT0()  asm volatile("cp.async.wait_group 0;")

__device__ __forceinline__ uint32_t h2u(float a, float b) {
    __half2 h = __floats2half2_rn(a, b);
    return *reinterpret_cast<uint32_t*>(&h);
}
__device__ __forceinline__ uint2 f4toh(float4 v) {
    return make_uint2(h2u(v.x, v.y), h2u(v.z, v.w));
}

// ---------------- one-shot weight convert (8 segments) ----------------
struct CvtArgs {
    const float4* s[8];
    uint2* d[8];
    int off[9];
};
__global__ void __launch_bounds__(256) k_cvt(CvtArgs a) {
    int i = blockIdx.x * 256 + threadIdx.x;
    if (i >= a.off[8]) return;
#pragma unroll
    for (int sg = 0; sg < 8; sg++) {
        if (i < a.off[sg + 1]) {
            int j = i - a.off[sg];
            a.d[sg][j] = f4toh(a.s[sg][j]);
            return;
        }
    }
}

// ---------------- GEMM: fp16, cp.async 4-stage, mma.sync ----------------
enum { EPI_NONE = 0, EPI_TANH = 1, EPI_WEXP = 2 };

template<int BM, int BN, int EPI, int OUTH>
__global__ void __launch_bounds__(256, 2)
gemmh(const __half* __restrict__ A, const __half* __restrict__ B,
      void* __restrict__ C, int nT, int lda, int ldb, int ldc,
      const float* __restrict__ bias)
{
    constexpr int S    = 4;
    constexpr int ASTR = 40;
    constexpr int BSTR = BN + 8;
    constexpr int ABYT = BM * ASTR * 2;
    constexpr int BBYT = 32 * BSTR * 2;
    constexpr int MFR  = BM / 32;
    constexpr int NFR  = BN / 32;
    constexpr int A_CH = BM * 4 / 256;
    constexpr int B_CH = 32 * (BN / 8) / 256;
    constexpr int BSH  = (BN == 128) ? 4 : 3;

    extern __shared__ char smem[];
    char* As = smem;
    char* Bs = smem + S * ABYT;

    const int tid  = threadIdx.x;
    const int wid  = tid >> 5;
    const int lane = tid & 31;
    const int warpM = (wid >> 2) * (BM / 2);
    const int warpN = (wid & 3) * (BN / 4);
    const int rowBase = blockIdx.x * BM;
    const int colBase = blockIdx.y * BN;

    const uint32_t aBase = smem_u32(As);
    const uint32_t bBase = smem_u32(Bs);
    const int lrow  = lane & 15;
    const int lhalf = (lane >> 4) * 8;
    const uint32_t aLane = (uint32_t)((warpM + lrow) * ASTR + lhalf) * 2;
    const uint32_t bLane = (uint32_t)(lrow * BSTR + warpN + lhalf) * 2;

    float acc[MFR][NFR][4];
#pragma unroll
    for (int i = 0; i < MFR; i++)
#pragma unroll
        for (int j = 0; j < NFR; j++)
#pragma unroll
            for (int e = 0; e < 4; e++) acc[i][j][e] = 0.f;

    auto issue = [&](int t) {
        const int kt = t * 32;
        const int sb = t & (S - 1);
        uint32_t ad = aBase + sb * ABYT;
        uint32_t bd = bBase + sb * BBYT;
#pragma unroll
        for (int i = 0; i < A_CH; i++) {
            int idx = i * 256 + tid;
            int r = idx >> 2, ch = idx & 3;
            cp16(ad + (uint32_t)(r * ASTR + ch * 8) * 2,
                 A + (size_t)(rowBase + r) * lda + kt + ch * 8);
        }
#pragma unroll
        for (int i = 0; i < B_CH; i++) {
            int idx = i * 256 + tid;
            int r = idx >> BSH, ch = idx & ((1 << BSH) - 1);
            cp16(bd + (uint32_t)(r * BSTR + ch * 8) * 2,
                 B + (size_t)(kt + r) * ldb + colBase + ch * 8);
        }
    };

#pragma unroll
    for (int s = 0; s < S - 1; ++s) {
        if (s < nT) issue(s);
        CP_COMMIT();
    }

    for (int t = 0; t < nT; ++t) {
        CP_WAIT2();
        __syncthreads();
        if (t + S - 1 < nT) issue(t + S - 1);
        CP_COMMIT();

        const int sb = t & (S - 1);
        const uint32_t ad = aBase + sb * ABYT;
        const uint32_t bd = bBase + sb * BBYT;
#pragma unroll
        for (int k16 = 0; k16 < 2; ++k16) {
            uint32_t af[MFR][4];
            uint32_t bf[NFR][2];
#pragma unroll
            for (int mi = 0; mi < MFR; mi++)
                ldsm4(af[mi], ad + aLane + (uint32_t)(mi * 16 * ASTR + k16 * 16) * 2);
#pragma unroll
            for (int p = 0; p < NFR / 2; p++)
                ldsm4t(&bf[p * 2][0], bd + bLane + (uint32_t)(k16 * 16 * BSTR + p * 16) * 2);
#pragma unroll
            for (int mi = 0; mi < MFR; mi++)
#pragma unroll
                for (int ni = 0; ni < NFR; ni++)
                    mma16816(acc[mi][ni], af[mi], bf[ni]);
        }
    }

    // ---- epilogue ----
    const int row0 = rowBase + warpM + (lane >> 2);
    const int col0 = colBase + warpN + (lane & 3) * 2;
#pragma unroll
    for (int mi = 0; mi < MFR; mi++) {
#pragma unroll
        for (int ni = 0; ni < NFR; ni++) {
#pragma unroll
            for (int half = 0; half < 2; half++) {
                int row = row0 + mi * 16 + half * 8;
                int col = col0 + ni * 8;
                float v0 = acc[mi][ni][half * 2 + 0];
                float v1 = acc[mi][ni][half * 2 + 1];
                if (EPI == EPI_TANH) {
                    v0 = tanhf(v0); v1 = tanhf(v1);
                } else if (EPI == EPI_WEXP) {
                    v0 = expf(-expf(bias[col] + v0));
                    v1 = expf(-expf(bias[col + 1] + v1));
                }
                if (OUTH) {
                    *(uint32_t*)((__half*)C + (size_t)row * ldc + col) = h2u(v0, v1);
                } else {
                    float* co = (float*)C + (size_t)row * ldc + col;
                    co[0] = v0; co[1] = v1;
                }
            }
        }
    }
}

// ---------------- fused mix kernel: all 4 f in one pass ----------------
// For each 128x128 output tile: smem h-tile (128x128) + 4 w2 tiles (32x128);
// loop f, reuse acc; epilogue out_f = x16 + xx16*(tm_f + acc).
#define HST 136
#define MIX_SMEM ((128*HST + 4*32*HST) * 2)

__global__ void __launch_bounds__(256, 2)
k_mix(const __half* __restrict__ h16, const __half* __restrict__ w2h,
      const __half* __restrict__ x16, const __half* __restrict__ xx16,
      const float* __restrict__ tmw, const float* __restrict__ tmk,
      const float* __restrict__ tmv, const float* __restrict__ tmr,
      __half* __restrict__ oxw, __half* __restrict__ oxk,
      __half* __restrict__ oxv, __half* __restrict__ oxr)
{
    extern __shared__ char smem[];
    uint16_t* hs  = (uint16_t*)smem;
    uint16_t* wsm = (uint16_t*)(smem + 128 * HST * 2);

    const int tid  = threadIdx.x;
    const int wid  = tid >> 5;
    const int lane = tid & 31;
    const int warpM = (wid >> 2) * 64;
    const int warpN = (wid & 3) * 32;
    const int rowBase = blockIdx.x * 128;
    const int colBase = blockIdx.y * 128;

    const uint32_t hsB = smem_u32(hs);
    const uint32_t wB  = smem_u32(wsm);

    // loads: h tile 128x128 halfs, w2 4x32x128 halfs
#pragma unroll
    for (int i = 0; i < 8; i++) {
        int idx = i * 256 + tid;
        int r = idx >> 4, ch = idx & 15;
        cp16(hsB + (uint32_t)(r * HST + ch * 8) * 2,
             h16 + (size_t)(rowBase + r) * DM4 + ch * 8);
    }
#pragma unroll
    for (int i = 0; i < 8; i++) {
        int idx = i * 256 + tid;
        int f = idx >> 9, rem = idx & 511;
        int r = rem >> 4, ch = rem & 15;
        cp16(wB + (uint32_t)((f * 32 + r) * HST + ch * 8) * 2,
             w2h + (size_t)(f * 32 + r) * Cc + colBase + ch * 8);
    }
    CP_COMMIT();
    CP_WAIT0();
    __syncthreads();

    const int lrow  = lane & 15;
    const int lhalf = (lane >> 4) * 8;
    const uint32_t aLane = (uint32_t)((warpM + lrow) * HST + lhalf) * 2;
    const uint32_t bLane = (uint32_t)(lrow * HST + warpN + lhalf) * 2;

    const int row0 = rowBase + warpM + (lane >> 2);
    const int col0 = colBase + warpN + (lane & 3) * 2;

#pragma unroll
    for (int f = 0; f < 4; f++) {
        const float* tmf = (f == 0) ? tmw : (f == 1) ? tmk : (f == 2) ? tmv : tmr;
        __half* of = (f == 0) ? oxw : (f == 1) ? oxk : (f == 2) ? oxv : oxr;

        float acc[4][4][4];
#pragma unroll
        for (int i = 0; i < 4; i++)
#pragma unroll
            for (int j = 0; j < 4; j++)
#pragma unroll
                for (int e = 0; e < 4; e++) acc[i][j][e] = 0.f;

#pragma unroll
        for (int k16 = 0; k16 < 2; ++k16) {
            uint32_t af[4][4];
            uint32_t bf[4][2];
#pragma unroll
            for (int mi = 0; mi < 4; mi++)
                ldsm4(af[mi], hsB + aLane + (uint32_t)(mi * 16 * HST + f * 32 + k16 * 16) * 2);
#pragma unroll
            for (int p = 0; p < 2; p++)
                ldsm4t(&bf[p * 2][0], wB + bLane + (uint32_t)((f * 32 + k16 * 16) * HST + p * 16) * 2);
#pragma unroll
            for (int mi = 0; mi < 4; mi++)
#pragma unroll
                for (int ni = 0; ni < 4; ni++)
                    mma16816(acc[mi][ni], af[mi], bf[ni]);
        }

#pragma unroll
        for (int mi = 0; mi < 4; mi++) {
#pragma unroll
            for (int ni = 0; ni < 4; ni++) {
#pragma unroll
                for (int half = 0; half < 2; half++) {
                    int row = row0 + mi * 16 + half * 8;
                    int col = col0 + ni * 8;
                    size_t off = (size_t)row * Cc + col;
                    __half2 xv2  = *(const __half2*)(x16 + off);
                    __half2 xxv2 = *(const __half2*)(xx16 + off);
                    float2 tm2 = *(const float2*)(tmf + col);
                    float v0 = fmaf(__low2float(xxv2),  tm2.x + acc[mi][ni][half * 2 + 0], __low2float(xv2));
                    float v1 = fmaf(__high2float(xxv2), tm2.y + acc[mi][ni][half * 2 + 1], __high2float(xv2));
                    *(uint32_t*)(of + off) = h2u(v0, v1);
                }
            }
        }
    }
}

// ---------------- token shift: x16, xx16, xxx16 ----------------
__global__ void __launch_bounds__(256) k_shift(const float4* __restrict__ x,
                                               const float4* __restrict__ tmx,
                                               uint2* __restrict__ ox16,
                                               uint2* __restrict__ oxx16,
                                               uint2* __restrict__ oxxx16)
{
    int i = blockIdx.x * 256 + threadIdx.x;
    int c4 = i & (C4 - 1);
    int n  = i >> 8;
    int t  = n & (Tc - 1);
    float4 xv = x[i];
    float4 xp = make_float4(0.f, 0.f, 0.f, 0.f);
    if (t != 0) xp = x[i - C4];
    float4 d;
    d.x = xp.x - xv.x; d.y = xp.y - xv.y; d.z = xp.z - xv.z; d.w = xp.w - xv.w;
    float4 tm = tmx[c4];
    float4 o;
    o.x = fmaf(d.x, tm.x, xv.x); o.y = fmaf(d.y, tm.y, xv.y);
    o.z = fmaf(d.z, tm.z, xv.z); o.w = fmaf(d.w, tm.w, xv.w);
    ox16[i]   = f4toh(xv);
    oxx16[i]  = f4toh(d);
    oxxx16[i] = f4toh(o);
}

// ---------------- WKV6: cp.async double-buffered, dual acc ----------------
#define WKV_CT 64
__global__ void __launch_bounds__(32) k_wkv(const float* __restrict__ u_faaaa,
                                            const float* __restrict__ r,
                                            const float* __restrict__ k,
                                            const float* __restrict__ v,
                                            const float* __restrict__ w,
                                            float* __restrict__ y)
{
    const int head_id = blockIdx.x;
    const int b = head_id >> 6;
    const int h = head_id & 63;
    const int lane = threadIdx.x;
    const int ih = lane >> 4;
    const int j  = lane & 15;
    const int base = (b * Tc) * (Hc * HSc) + h * HSc;

    __shared__ __align__(16) float rs [2][WKV_CT][16];
    __shared__ __align__(16) float ks [2][WKV_CT][16];
    __shared__ __align__(16) float wds[2][WKV_CT][16];
    __shared__ __align__(16) float vs [2][WKV_CT][16];

    float S[8];
#pragma unroll
    for (int q = 0; q < 8; q++) S[q] = 0.f;
    float u[8];
#pragma unroll
    for (int q = 0; q < 8; q++) u[q] = u_faaaa[h * HSc + ih * 8 + q];

    auto issue_chunk = [&](int t0, int buf) {
#pragma unroll
        for (int i = 0; i < 8; i++) {
            int idx = i * 32 + lane;      // 0..255
            int tt = idx >> 2;
            int i4 = (idx & 3) * 4;
            int off = base + (t0 + tt) * (Hc * HSc) + i4;
            cp16(smem_u32(&rs [buf][tt][i4]), r + off);
            cp16(smem_u32(&ks [buf][tt][i4]), k + off);
            cp16(smem_u32(&wds[buf][tt][i4]), w + off);
            cp16(smem_u32(&vs [buf][tt][i4]), v + off);
        }
        CP_COMMIT();
    };

    issue_chunk(0, 0);
    const int nChunks = Tc / WKV_CT;
    for (int c = 0; c < nChunks; ++c) {
        const int buf = c & 1;
        if (c + 1 < nChunks) {
            issue_chunk((c + 1) * WKV_CT, buf ^ 1);
            CP_WAIT1();
        } else {
            CP_WAIT0();
        }
        __syncwarp();

        const int ybase = base + c * WKV_CT * (Hc * HSc) + j;
        for (int tt = 0; tt < WKV_CT; ++tt) {
            float4 ra = *(const float4*)&rs [buf][tt][ih * 8];
            float4 rb = *(const float4*)&rs [buf][tt][ih * 8 + 4];
            float4 ka = *(const float4*)&ks [buf][tt][ih * 8];
            float4 kb = *(const float4*)&ks [buf][tt][ih * 8 + 4];
            float4 wa = *(const float4*)&wds[buf][tt][ih * 8];
            float4 wb = *(const float4*)&wds[buf][tt][ih * 8 + 4];
            float vj = vs[buf][tt][j];
            float acc0 = 0.f, acc1 = 0.f;
#define QSTEP(A, RQ, KQ, WQ, Q) { float kv = KQ * vj;                       \
            A = fmaf(RQ, fmaf(u[Q], kv, S[Q]), A);                          \
            S[Q] = fmaf(WQ, S[Q], kv); }
            QSTEP(acc0, ra.x, ka.x, wa.x, 0)
            QSTEP(acc1, ra.y, ka.y, wa.y, 1)
            QSTEP(acc0, ra.z, ka.z, wa.z, 2)
            QSTEP(acc1, ra.w, ka.w, wa.w, 3)
            QSTEP(acc0, rb.x, kb.x, wb.x, 4)
            QSTEP(acc1, rb.y, kb.y, wb.y, 5)
            QSTEP(acc0, rb.z, kb.z, wb.z, 6)
            QSTEP(acc1, rb.w, kb.w, wb.w, 7)
#undef QSTEP
            float accs = acc0 + acc1;
            accs += __shfl_xor_sync(0xffffffffu, accs, 16);
            if (ih == 0) y[ybase + tt * (Hc * HSc)] = accs;
        }
        __syncwarp();
    }
}

// ---------------- LayerNorm -> fp16 ----------------
__global__ void __launch_bounds__(256) k_ln(const float* __restrict__ y,
                                            const float* __restrict__ g,
                                            const float* __restrict__ bb,
                                            uint2* __restrict__ out16)
{
    const int n   = blockIdx.x;
    const int tid = threadIdx.x;
    const float4* yr = (const float4*)(y + (size_t)n * Cc);
    float4 vv = yr[tid];
    float s = vv.x + vv.y + vv.z + vv.w;
    float q = vv.x * vv.x + vv.y * vv.y + vv.z * vv.z + vv.w * vv.w;
#pragma unroll
    for (int o = 16; o > 0; o >>= 1) {
        s += __shfl_xor_sync(0xffffffffu, s, o);
        q += __shfl_xor_sync(0xffffffffu, q, o);
    }
    __shared__ float ssh[8], qsh[8];
    if ((tid & 31) == 0) { ssh[tid >> 5] = s; qsh[tid >> 5] = q; }
    __syncthreads();
    float st = 0.f, qt = 0.f;
#pragma unroll
    for (int wix = 0; wix < 8; wix++) { st += ssh[wix]; qt += qsh[wix]; }
    float mean = st * (1.0f / Cc);
    float var  = qt * (1.0f / Cc) - mean * mean;
    float rstd = rsqrtf(var + 1e-5f);
    float4 gg = ((const float4*)g)[tid];
    float4 b4 = ((const float4*)bb)[tid];
    float4 o;
    o.x = (vv.x - mean) * rstd * gg.x + b4.x;
    o.y = (vv.y - mean) * rstd * gg.y + b4.y;
    o.z = (vv.z - mean) * rstd * gg.z + b4.z;
    o.w = (vv.w - mean) * rstd * gg.w + b4.w;
    out16[(size_t)n * (Cc / 4) + tid] = f4toh(o);
}

// ---------------- launcher ----------------
#define SM128 (4*(128*40*2 + 32*136*2))
#define SM64  (4*(64*40*2 + 32*72*2))

extern "C" void kernel_launch(void* const* d_in, const int* in_sizes, int n_in,
                              void* d_out, int out_size)
{
    (void)in_sizes; (void)n_in; (void)out_size;
    const float* x     = (const float*)d_in[0];
    const float* tmx   = (const float*)d_in[1];
    const float* tmw   = (const float*)d_in[2];
    const float* tmk   = (const float*)d_in[3];
    const float* tmv   = (const float*)d_in[4];
    const float* tmr   = (const float*)d_in[5];
    const float* w1    = (const float*)d_in[6];
    const float* w2    = (const float*)d_in[7];
    const float* tdec  = (const float*)d_in[8];
    const float* dw1   = (const float*)d_in[9];
    const float* dw2   = (const float*)d_in[10];
    const float* faaaa = (const float*)d_in[11];
    const float* Wr    = (const float*)d_in[12];
    const float* Wk    = (const float*)d_in[13];
    const float* Wv    = (const float*)d_in[14];
    const float* Wo    = (const float*)d_in[15];
    const float* lng   = (const float*)d_in[16];
    const float* lnb   = (const float*)d_in[17];
    float* out = (float*)d_out;

    static float *p_y = nullptr, *p_r, *p_k, *p_v, *p_we;
    static __half *p16_x, *p16_xx, *p16_xxx, *p16_xw, *p16_xk, *p16_xv, *p16_xr,
                  *p16_h, *p16_t1,
                  *p16_wr, *p16_wk, *p16_wv, *p16_wo, *p16_w1, *p16_dw1, *p16_dw2, *p16_w2;
    if (!p_y) {
        cudaGetSymbolAddress((void**)&p_y,     g_y);
        cudaGetSymbolAddress((void**)&p_r,     g_r);
        cudaGetSymbolAddress((void**)&p_k,     g_k);
        cudaGetSymbolAddress((void**)&p_v,     g_v);
        cudaGetSymbolAddress((void**)&p_we,    g_we);
        cudaGetSymbolAddress((void**)&p16_x,   g16_x);
        cudaGetSymbolAddress((void**)&p16_xx,  g16_xx);
        cudaGetSymbolAddress((void**)&p16_xxx, g16_xxx);
        cudaGetSymbolAddress((void**)&p16_xw,  g16_xw);
        cudaGetSymbolAddress((void**)&p16_xk,  g16_xk);
        cudaGetSymbolAddress((void**)&p16_xv,  g16_xv);
        cudaGetSymbolAddress((void**)&p16_xr,  g16_xr);
        cudaGetSymbolAddress((void**)&p16_h,   g16_h);
        cudaGetSymbolAddress((void**)&p16_t1,  g16_t1);
        cudaGetSymbolAddress((void**)&p16_wr,  g16_wr);
        cudaGetSymbolAddress((void**)&p16_wk,  g16_wk);
        cudaGetSymbolAddress((void**)&p16_wv,  g16_wv);
        cudaGetSymbolAddress((void**)&p16_wo,  g16_wo);
        cudaGetSymbolAddress((void**)&p16_w1,  g16_w1);
        cudaGetSymbolAddress((void**)&p16_dw1, g16_dw1);
        cudaGetSymbolAddress((void**)&p16_dw2, g16_dw2);
        cudaGetSymbolAddress((void**)&p16_w2,  g16_w2);
        cudaFuncSetAttribute(gemmh<128,128,EPI_NONE,0>, cudaFuncAttributeMaxDynamicSharedMemorySize, SM128);
        cudaFuncSetAttribute(gemmh<128,128,EPI_WEXP,0>, cudaFuncAttributeMaxDynamicSharedMemorySize, SM128);
        cudaFuncSetAttribute(gemmh<64,64,EPI_TANH,1>,   cudaFuncAttributeMaxDynamicSharedMemorySize, SM64);
        cudaFuncSetAttribute(k_mix, cudaFuncAttributeMaxDynamicSharedMemorySize, MIX_SMEM);
    }
    __half* p16_yn = p16_xxx;      // yn overwrites xxx (dead after h gemm)

    // 0) weight converts — single launch, 8 segments (counts in float4)
    {
        CvtArgs a;
        const float* srcs[8] = { Wr, Wk, Wv, Wo, w1, dw1, dw2, w2 };
        __half* dsts[8] = { p16_wr, p16_wk, p16_wv, p16_wo, p16_w1, p16_dw1, p16_dw2, p16_w2 };
        int cnts[8] = { Cc*Cc/4, Cc*Cc/4, Cc*Cc/4, Cc*Cc/4, Cc*DM4/4, Cc*DDEC/4, DDEC*Cc/4, 4*32*Cc/4 };
        int cum = 0;
        for (int i = 0; i < 8; i++) {
            a.s[i] = (const float4*)srcs[i];
            a.d[i] = (uint2*)dsts[i];
            a.off[i] = cum;
            cum += cnts[i];
        }
        a.off[8] = cum;
        k_cvt<<<(cum + 255) / 256, 256>>>(a);
    }

    // 1) token shift -> x16, xx16, xxx16
    k_shift<<<NTOK, 256>>>((const float4*)x, (const float4*)tmx,
                           (uint2*)p16_x, (uint2*)p16_xx, (uint2*)p16_xxx);

    // 2) h = tanh(xxx @ w1)  [8192,1024]x[1024,128]
    gemmh<64,64,EPI_TANH,1><<<dim3(NTOK/64, DM4/64), 256, SM64>>>(
        p16_xxx, p16_w1, p16_h, Cc/32, Cc, DM4, DM4, nullptr);

    // 3) fused mix: xw/xk/xv/xr in one launch
    k_mix<<<dim3(NTOK/128, Cc/128), 256, MIX_SMEM>>>(
        p16_h, p16_w2, p16_x, p16_xx,
        tmw, tmk, tmv, tmr,
        p16_xw, p16_xk, p16_xv, p16_xr);

    // 4) t1 = tanh(xw @ dw1)  K=1024, N=64
    gemmh<64,64,EPI_TANH,1><<<dim3(NTOK/64, 1), 256, SM64>>>(
        p16_xw, p16_dw1, p16_t1, Cc/32, Cc, DDEC, DDEC, nullptr);

    // 5) we = exp(-exp(tdec + t1 @ dw2))  K=64
    gemmh<128,128,EPI_WEXP,0><<<dim3(NTOK/128, Cc/128), 256, SM128>>>(
        p16_t1, p16_dw2, p_we, DDEC/32, DDEC, Cc, Cc, tdec);

    // 6) r/k/v projections  K=1024
    gemmh<128,128,EPI_NONE,0><<<dim3(NTOK/128, Cc/128), 256, SM128>>>(
        p16_xr, p16_wr, p_r, Cc/32, Cc, Cc, Cc, nullptr);
    gemmh<128,128,EPI_NONE,0><<<dim3(NTOK/128, Cc/128), 256, SM128>>>(
        p16_xk, p16_wk, p_k, Cc/32, Cc, Cc, Cc, nullptr);
    gemmh<128,128,EPI_NONE,0><<<dim3(NTOK/128, Cc/128), 256, SM128>>>(
        p16_xv, p16_wv, p_v, Cc/32, Cc, Cc, Cc, nullptr);

    // 7) WKV6
    k_wkv<<<Bc * Hc, 32>>>(faaaa, p_r, p_k, p_v, p_we, p_y);

    // 8) LayerNorm -> fp16
    k_ln<<<NTOK, 256>>>(p_y, lng, lnb, (uint2*)p16_yn);

    // 9) out = yn @ Wo  K=1024
    gemmh<128,128,EPI_NONE,0><<<dim3(NTOK/128, Cc/128), 256, SM128>>>(
        p16_yn, p16_wo, out, Cc/32, Cc, Cc, Cc, nullptr);
}

// round 7
// speedup vs baseline: 2.8049x; 1.1027x over previous
#include <cuda_runtime.h>
#include <cuda_fp16.h>
#include <math.h>
#include <cstdint>

// ---------------- problem constants ----------------
#define Bc    4
#define Tc    2048
#define Cc    1024
#define Hc    64
#define HSc   16
#define NTOK  (Bc*Tc)            // 8192
#define C4    (Cc/4)             // 256
#define NC    (NTOK*Cc)
#define DM4   128
#define DDEC  64

// ---------------- scratch ----------------
// fp32
__device__ __align__(16) float g_xx [NC];
__device__ __align__(16) float g_y  [NC];
__device__ __align__(16) float g_r  [NC];
__device__ __align__(16) float g_k  [NC];
__device__ __align__(16) float g_v  [NC];
__device__ __align__(16) float g_we [NC];
// fp16 activations
__device__ __align__(16) __half g16_xxx[NC];       // reused as yn
__device__ __align__(16) __half g16_xw [NC];
__device__ __align__(16) __half g16_xk [NC];
__device__ __align__(16) __half g16_xv [NC];
__device__ __align__(16) __half g16_xr [NC];
__device__ __align__(16) __half g16_h  [NTOK*DM4];
__device__ __align__(16) __half g16_t1 [NTOK*DDEC];
// fp16 weights
__device__ __align__(16) __half g16_wr [Cc*Cc];
__device__ __align__(16) __half g16_wk [Cc*Cc];
__device__ __align__(16) __half g16_wv [Cc*Cc];
__device__ __align__(16) __half g16_wo [Cc*Cc];
__device__ __align__(16) __half g16_w1 [Cc*DM4];
__device__ __align__(16) __half g16_dw1[Cc*DDEC];
__device__ __align__(16) __half g16_dw2[DDEC*Cc];
__device__ __align__(16) __half g16_w2 [4*32*Cc];

// ---------------- helpers ----------------
__device__ __forceinline__ uint32_t smem_u32(const void* p) {
    uint32_t a;
    asm("{ .reg .u64 t; cvta.to.shared.u64 t, %1; cvt.u32.u64 %0, t; }" : "=r"(a) : "l"(p));
    return a;
}
__device__ __forceinline__ void ldsm4(uint32_t* r, uint32_t addr) {
    asm volatile("ldmatrix.sync.aligned.m8n8.x4.shared.b16 {%0,%1,%2,%3}, [%4];"
        : "=r"(r[0]), "=r"(r[1]), "=r"(r[2]), "=r"(r[3]) : "r"(addr));
}
__device__ __forceinline__ void ldsm4t(uint32_t* r, uint32_t addr) {
    asm volatile("ldmatrix.sync.aligned.m8n8.x4.trans.shared.b16 {%0,%1,%2,%3}, [%4];"
        : "=r"(r[0]), "=r"(r[1]), "=r"(r[2]), "=r"(r[3]) : "r"(addr));
}
__device__ __forceinline__ void mma16816(float* d, const uint32_t* a, const uint32_t* b) {
    asm volatile(
        "mma.sync.aligned.m16n8k16.row.col.f32.f16.f16.f32 "
        "{%0,%1,%2,%3}, {%4,%5,%6,%7}, {%8,%9}, {%0,%1,%2,%3};"
        : "+f"(d[0]), "+f"(d[1]), "+f"(d[2]), "+f"(d[3])
        : "r"(a[0]), "r"(a[1]), "r"(a[2]), "r"(a[3]), "r"(b[0]), "r"(b[1]));
}
__device__ __forceinline__ void cp16(uint32_t sdst, const void* gsrc) {
    asm volatile("cp.async.cg.shared.global [%0], [%1], 16;" :: "r"(sdst), "l"(gsrc));
}
#define CP_COMMIT() asm volatile("cp.async.commit_group;")
#define CP_WAIT2()  asm volatile("cp.async.wait_group 2;")
#define CP_WAIT1()  asm volatile("cp.async.wait_group 1;")
#define CP_WAIT0()  asm volatile("cp.async.wait_group 0;")

__device__ __forceinline__ uint32_t h2u(float a, float b) {
    __half2 h = __floats2half2_rn(a, b);
    return *reinterpret_cast<uint32_t*>(&h);
}
__device__ __forceinline__ uint2 f4toh(float4 v) {
    return make_uint2(h2u(v.x, v.y), h2u(v.z, v.w));
}

// ---------------- one-shot weight convert (8 segments) ----------------
struct CvtArgs {
    const float4* s[8];
    uint2* d[8];
    int off[9];
};
__global__ void __launch_bounds__(256) k_cvt(CvtArgs a) {
    int i = blockIdx.x * 256 + threadIdx.x;
    if (i >= a.off[8]) return;
#pragma unroll
    for (int sg = 0; sg < 8; sg++) {
        if (i < a.off[sg + 1]) {
            int j = i - a.off[sg];
            a.d[sg][j] = f4toh(a.s[sg][j]);
            return;
        }
    }
}

// ---------------- GEMM: fp16, cp.async 4-stage, mma.sync ----------------
enum { EPI_NONE = 0, EPI_TANH = 1, EPI_WEXP = 2 };

template<int BM, int BN, int EPI, int OUTH>
__global__ void __launch_bounds__(256, 2)
gemmh(const __half* __restrict__ A, const __half* __restrict__ B,
      void* __restrict__ C, int nT, int lda, int ldb, int ldc,
      const float* __restrict__ bias)
{
    constexpr int S    = 4;
    constexpr int ASTR = 40;
    constexpr int BSTR = BN + 8;
    constexpr int ABYT = BM * ASTR * 2;
    constexpr int BBYT = 32 * BSTR * 2;
    constexpr int MFR  = BM / 32;
    constexpr int NFR  = BN / 32;
    constexpr int A_CH = BM * 4 / 256;
    constexpr int B_CH = 32 * (BN / 8) / 256;
    constexpr int BSH  = (BN == 128) ? 4 : 3;

    extern __shared__ char smem[];
    char* As = smem;
    char* Bs = smem + S * ABYT;

    const int tid  = threadIdx.x;
    const int wid  = tid >> 5;
    const int lane = tid & 31;
    const int warpM = (wid >> 2) * (BM / 2);
    const int warpN = (wid & 3) * (BN / 4);
    const int rowBase = blockIdx.x * BM;
    const int colBase = blockIdx.y * BN;

    const uint32_t aBase = smem_u32(As);
    const uint32_t bBase = smem_u32(Bs);
    const int lrow  = lane & 15;
    const int lhalf = (lane >> 4) * 8;
    const uint32_t aLane = (uint32_t)((warpM + lrow) * ASTR + lhalf) * 2;
    const uint32_t bLane = (uint32_t)(lrow * BSTR + warpN + lhalf) * 2;

    float acc[MFR][NFR][4];
#pragma unroll
    for (int i = 0; i < MFR; i++)
#pragma unroll
        for (int j = 0; j < NFR; j++)
#pragma unroll
            for (int e = 0; e < 4; e++) acc[i][j][e] = 0.f;

    auto issue = [&](int t) {
        const int kt = t * 32;
        const int sb = t & (S - 1);
        uint32_t ad = aBase + sb * ABYT;
        uint32_t bd = bBase + sb * BBYT;
#pragma unroll
        for (int i = 0; i < A_CH; i++) {
            int idx = i * 256 + tid;
            int r = idx >> 2, ch = idx & 3;
            cp16(ad + (uint32_t)(r * ASTR + ch * 8) * 2,
                 A + (size_t)(rowBase + r) * lda + kt + ch * 8);
        }
#pragma unroll
        for (int i = 0; i < B_CH; i++) {
            int idx = i * 256 + tid;
            int r = idx >> BSH, ch = idx & ((1 << BSH) - 1);
            cp16(bd + (uint32_t)(r * BSTR + ch * 8) * 2,
                 B + (size_t)(kt + r) * ldb + colBase + ch * 8);
        }
    };

#pragma unroll
    for (int s = 0; s < S - 1; ++s) {
        if (s < nT) issue(s);
        CP_COMMIT();
    }

    for (int t = 0; t < nT; ++t) {
        CP_WAIT2();
        __syncthreads();
        if (t + S - 1 < nT) issue(t + S - 1);
        CP_COMMIT();

        const int sb = t & (S - 1);
        const uint32_t ad = aBase + sb * ABYT;
        const uint32_t bd = bBase + sb * BBYT;
#pragma unroll
        for (int k16 = 0; k16 < 2; ++k16) {
            uint32_t af[MFR][4];
            uint32_t bf[NFR][2];
#pragma unroll
            for (int mi = 0; mi < MFR; mi++)
                ldsm4(af[mi], ad + aLane + (uint32_t)(mi * 16 * ASTR + k16 * 16) * 2);
#pragma unroll
            for (int p = 0; p < NFR / 2; p++)
                ldsm4t(&bf[p * 2][0], bd + bLane + (uint32_t)(k16 * 16 * BSTR + p * 16) * 2);
#pragma unroll
            for (int mi = 0; mi < MFR; mi++)
#pragma unroll
                for (int ni = 0; ni < NFR; ni++)
                    mma16816(acc[mi][ni], af[mi], bf[ni]);
        }
    }

    // ---- epilogue ----
    const int row0 = rowBase + warpM + (lane >> 2);
    const int col0 = colBase + warpN + (lane & 3) * 2;
#pragma unroll
    for (int mi = 0; mi < MFR; mi++) {
#pragma unroll
        for (int ni = 0; ni < NFR; ni++) {
#pragma unroll
            for (int half = 0; half < 2; half++) {
                int row = row0 + mi * 16 + half * 8;
                int col = col0 + ni * 8;
                float v0 = acc[mi][ni][half * 2 + 0];
                float v1 = acc[mi][ni][half * 2 + 1];
                if (EPI == EPI_TANH) {
                    v0 = tanhf(v0); v1 = tanhf(v1);
                } else if (EPI == EPI_WEXP) {
                    v0 = expf(-expf(bias[col] + v0));
                    v1 = expf(-expf(bias[col + 1] + v1));
                }
                if (OUTH) {
                    *(uint32_t*)((__half*)C + (size_t)row * ldc + col) = h2u(v0, v1);
                } else {
                    float* co = (float*)C + (size_t)row * ldc + col;
                    co[0] = v0; co[1] = v1;
                }
            }
        }
    }
}

// ---------------- fused mix kernel: all 4 f, smem-staged epilogue ----------------
#define HST 136
#define MIX_SMEM ((128*HST + 128*HST + 128*HST) * 2)

__global__ void __launch_bounds__(256, 2)
k_mix(const __half* __restrict__ h16, const __half* __restrict__ w2h,
      const float* __restrict__ xf, const float* __restrict__ xxf,
      const float* __restrict__ tmw, const float* __restrict__ tmk,
      const float* __restrict__ tmv, const float* __restrict__ tmr,
      __half* __restrict__ oxw, __half* __restrict__ oxk,
      __half* __restrict__ oxv, __half* __restrict__ oxr)
{
    extern __shared__ char smem[];
    uint16_t* hs  = (uint16_t*)smem;
    uint16_t* wsm = (uint16_t*)(smem + 128 * HST * 2);
    uint16_t* st  = (uint16_t*)(smem + 2 * 128 * HST * 2);

    const int tid  = threadIdx.x;
    const int wid  = tid >> 5;
    const int lane = tid & 31;
    const int warpM = (wid >> 2) * 64;
    const int warpN = (wid & 3) * 32;
    const int rowBase = blockIdx.x * 128;
    const int colBase = blockIdx.y * 128;

    const uint32_t hsB = smem_u32(hs);
    const uint32_t wB  = smem_u32(wsm);

#pragma unroll
    for (int i = 0; i < 8; i++) {
        int idx = i * 256 + tid;
        int r = idx >> 4, ch = idx & 15;
        cp16(hsB + (uint32_t)(r * HST + ch * 8) * 2,
             h16 + (size_t)(rowBase + r) * DM4 + ch * 8);
    }
#pragma unroll
    for (int i = 0; i < 8; i++) {
        int idx = i * 256 + tid;
        int f = idx >> 9, rem = idx & 511;
        int r = rem >> 4, ch = rem & 15;
        cp16(wB + (uint32_t)((f * 32 + r) * HST + ch * 8) * 2,
             w2h + (size_t)(f * 32 + r) * Cc + colBase + ch * 8);
    }
    CP_COMMIT();
    CP_WAIT0();
    __syncthreads();

    const int lrow  = lane & 15;
    const int lhalf = (lane >> 4) * 8;
    const uint32_t aLane = (uint32_t)((warpM + lrow) * HST + lhalf) * 2;
    const uint32_t bLane = (uint32_t)(lrow * HST + warpN + lhalf) * 2;

#pragma unroll
    for (int f = 0; f < 4; f++) {
        const float* tmf = (f == 0) ? tmw : (f == 1) ? tmk : (f == 2) ? tmv : tmr;
        __half* of = (f == 0) ? oxw : (f == 1) ? oxk : (f == 2) ? oxv : oxr;

        float acc[4][4][4];
#pragma unroll
        for (int i = 0; i < 4; i++)
#pragma unroll
            for (int j = 0; j < 4; j++)
#pragma unroll
                for (int e = 0; e < 4; e++) acc[i][j][e] = 0.f;

#pragma unroll
        for (int k16 = 0; k16 < 2; ++k16) {
            uint32_t af[4][4];
            uint32_t bf[4][2];
#pragma unroll
            for (int mi = 0; mi < 4; mi++)
                ldsm4(af[mi], hsB + aLane + (uint32_t)(mi * 16 * HST + f * 32 + k16 * 16) * 2);
#pragma unroll
            for (int p = 0; p < 2; p++)
                ldsm4t(&bf[p * 2][0], wB + bLane + (uint32_t)((f * 32 + k16 * 16) * HST + p * 16) * 2);
#pragma unroll
            for (int mi = 0; mi < 4; mi++)
#pragma unroll
                for (int ni = 0; ni < 4; ni++)
                    mma16816(acc[mi][ni], af[mi], bf[ni]);
        }

        __syncthreads();   // prior f's stage reads done
        // stage acc -> smem (fp16)
#pragma unroll
        for (int mi = 0; mi < 4; mi++)
#pragma unroll
            for (int ni = 0; ni < 4; ni++)
#pragma unroll
                for (int half = 0; half < 2; half++) {
                    int srow = warpM + mi * 16 + half * 8 + (lane >> 2);
                    int scol = warpN + ni * 8 + (lane & 3) * 2;
                    *(uint32_t*)&st[srow * HST + scol] =
                        h2u(acc[mi][ni][half * 2], acc[mi][ni][half * 2 + 1]);
                }
        __syncthreads();

        // coalesced epilogue: 8 uint4 per thread
#pragma unroll
        for (int it = 0; it < 8; ++it) {
            int idx = it * 256 + tid;
            int row = idx >> 4, seg = idx & 15;
            int gcol = colBase + seg * 8;
            size_t goff = (size_t)(rowBase + row) * Cc + gcol;
            uint4 mv = *(uint4*)&st[row * HST + seg * 8];
            float4 xa  = *(const float4*)(xf + goff);
            float4 xb  = *(const float4*)(xf + goff + 4);
            float4 xxa = *(const float4*)(xxf + goff);
            float4 xxb = *(const float4*)(xxf + goff + 4);
            float4 ta  = *(const float4*)(tmf + gcol);
            float4 tb  = *(const float4*)(tmf + gcol + 4);
            __half2 m0 = *(__half2*)&mv.x;
            __half2 m1 = *(__half2*)&mv.y;
            __half2 m2 = *(__half2*)&mv.z;
            __half2 m3 = *(__half2*)&mv.w;
            float v0 = fmaf(xxa.x, ta.x + __low2float(m0),  xa.x);
            float v1 = fmaf(xxa.y, ta.y + __high2float(m0), xa.y);
            float v2 = fmaf(xxa.z, ta.z + __low2float(m1),  xa.z);
            float v3 = fmaf(xxa.w, ta.w + __high2float(m1), xa.w);
            float v4 = fmaf(xxb.x, tb.x + __low2float(m2),  xb.x);
            float v5 = fmaf(xxb.y, tb.y + __high2float(m2), xb.y);
            float v6 = fmaf(xxb.z, tb.z + __low2float(m3),  xb.z);
            float v7 = fmaf(xxb.w, tb.w + __high2float(m3), xb.w);
            uint4 o;
            o.x = h2u(v0, v1); o.y = h2u(v2, v3);
            o.z = h2u(v4, v5); o.w = h2u(v6, v7);
            *(uint4*)(of + goff) = o;
        }
    }
}

// ---------------- token shift: xx fp32 + xxx fp16 ----------------
__global__ void __launch_bounds__(256) k_shift(const float4* __restrict__ x,
                                               const float4* __restrict__ tmx,
                                               float4* __restrict__ oxx,
                                               uint2* __restrict__ oxxx16)
{
    int i = blockIdx.x * 256 + threadIdx.x;
    int c4 = i & (C4 - 1);
    int n  = i >> 8;
    int t  = n & (Tc - 1);
    float4 xv = x[i];
    float4 xp = make_float4(0.f, 0.f, 0.f, 0.f);
    if (t != 0) xp = x[i - C4];
    float4 d;
    d.x = xp.x - xv.x; d.y = xp.y - xv.y; d.z = xp.z - xv.z; d.w = xp.w - xv.w;
    float4 tm = tmx[c4];
    float4 o;
    o.x = fmaf(d.x, tm.x, xv.x); o.y = fmaf(d.y, tm.y, xv.y);
    o.z = fmaf(d.z, tm.z, xv.z); o.w = fmaf(d.w, tm.w, xv.w);
    oxx[i]    = d;
    oxxx16[i] = f4toh(o);
}

// ---------------- WKV6: 64 threads/head, cp.async double-buffered ----------------
#define WKV_CT 64
__global__ void __launch_bounds__(64) k_wkv(const float* __restrict__ u_faaaa,
                                            const float* __restrict__ r,
                                            const float* __restrict__ k,
                                            const float* __restrict__ v,
                                            const float* __restrict__ w,
                                            float* __restrict__ y)
{
    const int head_id = blockIdx.x;
    const int b = head_id >> 6;
    const int h = head_id & 63;
    const int tid  = threadIdx.x;
    const int wq   = tid >> 5;          // warp: j-half
    const int lane = tid & 31;
    const int j  = wq * 8 + (lane & 7); // column 0..15
    const int ig = lane >> 3;           // row group 0..3 (rows ig*4..ig*4+3)
    const int base = (b * Tc) * (Hc * HSc) + h * HSc;

    __shared__ __align__(16) float rs[2][WKV_CT][16];
    __shared__ __align__(16) float ks[2][WKV_CT][16];
    __shared__ __align__(16) float ws[2][WKV_CT][16];
    __shared__ __align__(16) float vs[2][WKV_CT][16];

    float S0 = 0.f, S1 = 0.f, S2 = 0.f, S3 = 0.f;
    const float4 u4 = *(const float4*)(u_faaaa + h * HSc + ig * 4);

    auto issue_chunk = [&](int t0, int buf) {
#pragma unroll
        for (int i = 0; i < 4; i++) {
            int idx = i * 64 + tid;        // 0..255
            int tt = idx >> 2;
            int i4 = (idx & 3) * 4;
            int off = base + (t0 + tt) * (Hc * HSc) + i4;
            cp16(smem_u32(&rs[buf][tt][i4]), r + off);
            cp16(smem_u32(&ks[buf][tt][i4]), k + off);
            cp16(smem_u32(&ws[buf][tt][i4]), w + off);
            cp16(smem_u32(&vs[buf][tt][i4]), v + off);
        }
        CP_COMMIT();
    };

    issue_chunk(0, 0);
    const int nChunks = Tc / WKV_CT;
    for (int c = 0; c < nChunks; ++c) {
        const int buf = c & 1;
        if (c + 1 < nChunks) {
            issue_chunk((c + 1) * WKV_CT, buf ^ 1);
            CP_WAIT1();
        } else {
            CP_WAIT0();
        }
        __syncthreads();

        const int ybase = base + c * WKV_CT * (Hc * HSc) + j;
        for (int tt = 0; tt < WKV_CT; ++tt) {
            float4 rr = *(const float4*)&rs[buf][tt][ig * 4];
            float4 kk = *(const float4*)&ks[buf][tt][ig * 4];
            float4 ww = *(const float4*)&ws[buf][tt][ig * 4];
            float vj = vs[buf][tt][j];
            float kv, acc;
            kv = kk.x * vj; acc = rr.x * fmaf(u4.x, kv, S0);        S0 = fmaf(ww.x, S0, kv);
            kv = kk.y * vj; acc = fmaf(rr.y, fmaf(u4.y, kv, S1), acc); S1 = fmaf(ww.y, S1, kv);
            kv = kk.z * vj; acc = fmaf(rr.z, fmaf(u4.z, kv, S2), acc); S2 = fmaf(ww.z, S2, kv);
            kv = kk.w * vj; acc = fmaf(rr.w, fmaf(u4.w, kv, S3), acc); S3 = fmaf(ww.w, S3, kv);
            acc += __shfl_xor_sync(0xffffffffu, acc, 8);
            acc += __shfl_xor_sync(0xffffffffu, acc, 16);
            if (ig == 0) y[ybase + tt * (Hc * HSc)] = acc;
        }
        __syncthreads();
    }
}

// ---------------- LayerNorm -> fp16 ----------------
__global__ void __launch_bounds__(256) k_ln(const float* __restrict__ y,
                                            const float* __restrict__ g,
                                            const float* __restrict__ bb,
                                            uint2* __restrict__ out16)
{
    const int n   = blockIdx.x;
    const int tid = threadIdx.x;
    const float4* yr = (const float4*)(y + (size_t)n * Cc);
    float4 vv = yr[tid];
    float s = vv.x + vv.y + vv.z + vv.w;
    float q = vv.x * vv.x + vv.y * vv.y + vv.z * vv.z + vv.w * vv.w;
#pragma unroll
    for (int o = 16; o > 0; o >>= 1) {
        s += __shfl_xor_sync(0xffffffffu, s, o);
        q += __shfl_xor_sync(0xffffffffu, q, o);
    }
    __shared__ float ssh[8], qsh[8];
    if ((tid & 31) == 0) { ssh[tid >> 5] = s; qsh[tid >> 5] = q; }
    __syncthreads();
    float st = 0.f, qt = 0.f;
#pragma unroll
    for (int wix = 0; wix < 8; wix++) { st += ssh[wix]; qt += qsh[wix]; }
    float mean = st * (1.0f / Cc);
    float var  = qt * (1.0f / Cc) - mean * mean;
    float rstd = rsqrtf(var + 1e-5f);
    float4 gg = ((const float4*)g)[tid];
    float4 b4 = ((const float4*)bb)[tid];
    float4 o;
    o.x = (vv.x - mean) * rstd * gg.x + b4.x;
    o.y = (vv.y - mean) * rstd * gg.y + b4.y;
    o.z = (vv.z - mean) * rstd * gg.z + b4.z;
    o.w = (vv.w - mean) * rstd * gg.w + b4.w;
    out16[(size_t)n * (Cc / 4) + tid] = f4toh(o);
}

// ---------------- launcher ----------------
#define SM128 (4*(128*40*2 + 32*136*2))
#define SM64  (4*(64*40*2 + 32*72*2))

extern "C" void kernel_launch(void* const* d_in, const int* in_sizes, int n_in,
                              void* d_out, int out_size)
{
    (void)in_sizes; (void)n_in; (void)out_size;
    const float* x     = (const float*)d_in[0];
    const float* tmx   = (const float*)d_in[1];
    const float* tmw   = (const float*)d_in[2];
    const float* tmk   = (const float*)d_in[3];
    const float* tmv   = (const float*)d_in[4];
    const float* tmr   = (const float*)d_in[5];
    const float* w1    = (const float*)d_in[6];
    const float* w2    = (const float*)d_in[7];
    const float* tdec  = (const float*)d_in[8];
    const float* dw1   = (const float*)d_in[9];
    const float* dw2   = (const float*)d_in[10];
    const float* faaaa = (const float*)d_in[11];
    const float* Wr    = (const float*)d_in[12];
    const float* Wk    = (const float*)d_in[13];
    const float* Wv    = (const float*)d_in[14];
    const float* Wo    = (const float*)d_in[15];
    const float* lng   = (const float*)d_in[16];
    const float* lnb   = (const float*)d_in[17];
    float* out = (float*)d_out;

    static float *p_xx = nullptr, *p_y, *p_r, *p_k, *p_v, *p_we;
    static __half *p16_xxx, *p16_xw, *p16_xk, *p16_xv, *p16_xr, *p16_h, *p16_t1,
                  *p16_wr, *p16_wk, *p16_wv, *p16_wo, *p16_w1, *p16_dw1, *p16_dw2, *p16_w2;
    if (!p_xx) {
        cudaGetSymbolAddress((void**)&p_xx,    g_xx);
        cudaGetSymbolAddress((void**)&p_y,     g_y);
        cudaGetSymbolAddress((void**)&p_r,     g_r);
        cudaGetSymbolAddress((void**)&p_k,     g_k);
        cudaGetSymbolAddress((void**)&p_v,     g_v);
        cudaGetSymbolAddress((void**)&p_we,    g_we);
        cudaGetSymbolAddress((void**)&p16_xxx, g16_xxx);
        cudaGetSymbolAddress((void**)&p16_xw,  g16_xw);
        cudaGetSymbolAddress((void**)&p16_xk,  g16_xk);
        cudaGetSymbolAddress((void**)&p16_xv,  g16_xv);
        cudaGetSymbolAddress((void**)&p16_xr,  g16_xr);
        cudaGetSymbolAddress((void**)&p16_h,   g16_h);
        cudaGetSymbolAddress((void**)&p16_t1,  g16_t1);
        cudaGetSymbolAddress((void**)&p16_wr,  g16_wr);
        cudaGetSymbolAddress((void**)&p16_wk,  g16_wk);
        cudaGetSymbolAddress((void**)&p16_wv,  g16_wv);
        cudaGetSymbolAddress((void**)&p16_wo,  g16_wo);
        cudaGetSymbolAddress((void**)&p16_w1,  g16_w1);
        cudaGetSymbolAddress((void**)&p16_dw1, g16_dw1);
        cudaGetSymbolAddress((void**)&p16_dw2, g16_dw2);
        cudaGetSymbolAddress((void**)&p16_w2,  g16_w2);
        cudaFuncSetAttribute(gemmh<128,128,EPI_NONE,0>, cudaFuncAttributeMaxDynamicSharedMemorySize, SM128);
        cudaFuncSetAttribute(gemmh<128,128,EPI_WEXP,0>, cudaFuncAttributeMaxDynamicSharedMemorySize, SM128);
        cudaFuncSetAttribute(gemmh<64,64,EPI_TANH,1>,   cudaFuncAttributeMaxDynamicSharedMemorySize, SM64);
        cudaFuncSetAttribute(k_mix, cudaFuncAttributeMaxDynamicSharedMemorySize, MIX_SMEM);
    }
    __half* p16_yn = p16_xxx;      // yn overwrites xxx (dead after h gemm)

    // 0) weight converts — single launch, 8 segments (counts in float4)
    {
        CvtArgs a;
        const float* srcs[8] = { Wr, Wk, Wv, Wo, w1, dw1, dw2, w2 };
        __half* dsts[8] = { p16_wr, p16_wk, p16_wv, p16_wo, p16_w1, p16_dw1, p16_dw2, p16_w2 };
        int cnts[8] = { Cc*Cc/4, Cc*Cc/4, Cc*Cc/4, Cc*Cc/4, Cc*DM4/4, Cc*DDEC/4, DDEC*Cc/4, 4*32*Cc/4 };
        int cum = 0;
        for (int i = 0; i < 8; i++) {
            a.s[i] = (const float4*)srcs[i];
            a.d[i] = (uint2*)dsts[i];
            a.off[i] = cum;
            cum += cnts[i];
        }
        a.off[8] = cum;
        k_cvt<<<(cum + 255) / 256, 256>>>(a);
    }

    // 1) token shift -> xx fp32, xxx fp16
    k_shift<<<NTOK, 256>>>((const float4*)x, (const float4*)tmx,
                           (float4*)p_xx, (uint2*)p16_xxx);

    // 2) h = tanh(xxx @ w1)  [8192,1024]x[1024,128]
    gemmh<64,64,EPI_TANH,1><<<dim3(NTOK/64, DM4/64), 256, SM64>>>(
        p16_xxx, p16_w1, p16_h, Cc/32, Cc, DM4, DM4, nullptr);

    // 3) fused mix: xw/xk/xv/xr in one launch (fp32 x/xx in epilogue)
    k_mix<<<dim3(NTOK/128, Cc/128), 256, MIX_SMEM>>>(
        p16_h, p16_w2, x, p_xx,
        tmw, tmk, tmv, tmr,
        p16_xw, p16_xk, p16_xv, p16_xr);

    // 4) t1 = tanh(xw @ dw1)  K=1024, N=64
    gemmh<64,64,EPI_TANH,1><<<dim3(NTOK/64, 1), 256, SM64>>>(
        p16_xw, p16_dw1, p16_t1, Cc/32, Cc, DDEC, DDEC, nullptr);

    // 5) we = exp(-exp(tdec + t1 @ dw2))  K=64
    gemmh<128,128,EPI_WEXP,0><<<dim3(NTOK/128, Cc/128), 256, SM128>>>(
        p16_t1, p16_dw2, p_we, DDEC/32, DDEC, Cc, Cc, tdec);

    // 6) r/k/v projections  K=1024
    gemmh<128,128,EPI_NONE,0><<<dim3(NTOK/128, Cc/128), 256, SM128>>>(
        p16_xr, p16_wr, p_r, Cc/32, Cc, Cc, Cc, nullptr);
    gemmh<128,128,EPI_NONE,0><<<dim3(NTOK/128, Cc/128), 256, SM128>>>(
        p16_xk, p16_wk, p_k, Cc/32, Cc, Cc, Cc, nullptr);
    gemmh<128,128,EPI_NONE,0><<<dim3(NTOK/128, Cc/128), 256, SM128>>>(
        p16_xv, p16_wv, p_v, Cc/32, Cc, Cc, Cc, nullptr);

    // 7) WKV6 — 64 threads per head
    k_wkv<<<Bc * Hc, 64>>>(faaaa, p_r, p_k, p_v, p_we, p_y);

    // 8) LayerNorm -> fp16
    k_ln<<<NTOK, 256>>>(p_y, lng, lnb, (uint2*)p16_yn);

    // 9) out = yn @ Wo  K=1024
    gemmh<128,128,EPI_NONE,0><<<dim3(NTOK/128, Cc/128), 256, SM128>>>(
        p16_yn, p16_wo, out, Cc/32, Cc, Cc, Cc, nullptr);
}

// round 8
// speedup vs baseline: 2.8261x; 1.0076x over previous
#include <cuda_runtime.h>
#include <cuda_fp16.h>
#include <math.h>
#include <cstdint>

// ---------------- problem constants ----------------
#define Bc    4
#define Tc    2048
#define Cc    1024
#define Hc    64
#define HSc   16
#define NTOK  (Bc*Tc)            // 8192
#define C4    (Cc/4)             // 256
#define NC    (NTOK*Cc)
#define DM4   128
#define DDEC  64
#define P_SEG 16
#define TSEG  (Tc/P_SEG)         // 128
#define NSEG  (Bc*Hc*P_SEG)      // 4096

// ---------------- scratch ----------------
// fp32
__device__ __align__(16) float g_xx [NC];
__device__ __align__(16) float g_y  [NC];
__device__ __align__(16) float g_r  [NC];
__device__ __align__(16) float g_k  [NC];
__device__ __align__(16) float g_v  [NC];
__device__ __align__(16) float g_we [NC];
__device__ __align__(16) float g_sseg[NSEG*256];
__device__ __align__(16) float g_sin [NSEG*256];
__device__ __align__(16) float g_wp  [NSEG*16];
// fp16 activations
__device__ __align__(16) __half g16_xxx[NC];       // reused as yn
__device__ __align__(16) __half g16_xw [NC];
__device__ __align__(16) __half g16_xk [NC];
__device__ __align__(16) __half g16_xv [NC];
__device__ __align__(16) __half g16_xr [NC];
__device__ __align__(16) __half g16_h  [NTOK*DM4];
__device__ __align__(16) __half g16_t1 [NTOK*DDEC];
// fp16 weights
__device__ __align__(16) __half g16_wr [Cc*Cc];
__device__ __align__(16) __half g16_wk [Cc*Cc];
__device__ __align__(16) __half g16_wv [Cc*Cc];
__device__ __align__(16) __half g16_wo [Cc*Cc];
__device__ __align__(16) __half g16_w1 [Cc*DM4];
__device__ __align__(16) __half g16_dw1[Cc*DDEC];
__device__ __align__(16) __half g16_dw2[DDEC*Cc];
__device__ __align__(16) __half g16_w2 [4*32*Cc];

// ---------------- helpers ----------------
__device__ __forceinline__ uint32_t smem_u32(const void* p) {
    uint32_t a;
    asm("{ .reg .u64 t; cvta.to.shared.u64 t, %1; cvt.u32.u64 %0, t; }" : "=r"(a) : "l"(p));
    return a;
}
__device__ __forceinline__ void ldsm4(uint32_t* r, uint32_t addr) {
    asm volatile("ldmatrix.sync.aligned.m8n8.x4.shared.b16 {%0,%1,%2,%3}, [%4];"
        : "=r"(r[0]), "=r"(r[1]), "=r"(r[2]), "=r"(r[3]) : "r"(addr));
}
__device__ __forceinline__ void ldsm4t(uint32_t* r, uint32_t addr) {
    asm volatile("ldmatrix.sync.aligned.m8n8.x4.trans.shared.b16 {%0,%1,%2,%3}, [%4];"
        : "=r"(r[0]), "=r"(r[1]), "=r"(r[2]), "=r"(r[3]) : "r"(addr));
}
__device__ __forceinline__ void mma16816(float* d, const uint32_t* a, const uint32_t* b) {
    asm volatile(
        "mma.sync.aligned.m16n8k16.row.col.f32.f16.f16.f32 "
        "{%0,%1,%2,%3}, {%4,%5,%6,%7}, {%8,%9}, {%0,%1,%2,%3};"
        : "+f"(d[0]), "+f"(d[1]), "+f"(d[2]), "+f"(d[3])
        : "r"(a[0]), "r"(a[1]), "r"(a[2]), "r"(a[3]), "r"(b[0]), "r"(b[1]));
}
__device__ __forceinline__ void cp16(uint32_t sdst, const void* gsrc) {
    asm volatile("cp.async.cg.shared.global [%0], [%1], 16;" :: "r"(sdst), "l"(gsrc));
}
#define CP_COMMIT() asm volatile("cp.async.commit_group;")
#define CP_WAIT2()  asm volatile("cp.async.wait_group 2;")
#define CP_WAIT1()  asm volatile("cp.async.wait_group 1;")
#define CP_WAIT0()  asm volatile("cp.async.wait_group 0;")

__device__ __forceinline__ uint32_t h2u(float a, float b) {
    __half2 h = __floats2half2_rn(a, b);
    return *reinterpret_cast<uint32_t*>(&h);
}
__device__ __forceinline__ uint2 f4toh(float4 v) {
    return make_uint2(h2u(v.x, v.y), h2u(v.z, v.w));
}

// ---------------- one-shot weight convert (8 segments) ----------------
struct CvtArgs {
    const float4* s[8];
    uint2* d[8];
    int off[9];
};
__global__ void __launch_bounds__(256) k_cvt(CvtArgs a) {
    int i = blockIdx.x * 256 + threadIdx.x;
    if (i >= a.off[8]) return;
#pragma unroll
    for (int sg = 0; sg < 8; sg++) {
        if (i < a.off[sg + 1]) {
            int j = i - a.off[sg];
            a.d[sg][j] = f4toh(a.s[sg][j]);
            return;
        }
    }
}

// ---------------- GEMM: fp16, cp.async 4-stage, mma.sync ----------------
enum { EPI_NONE = 0, EPI_TANH = 1, EPI_WEXP = 2 };

template<int BM, int BN, int EPI, int OUTH>
__global__ void __launch_bounds__(256, 2)
gemmh(const __half* __restrict__ A, const __half* __restrict__ B,
      void* __restrict__ C, int nT, int lda, int ldb, int ldc,
      const float* __restrict__ bias)
{
    constexpr int S    = 4;
    constexpr int ASTR = 40;
    constexpr int BSTR = BN + 8;
    constexpr int ABYT = BM * ASTR * 2;
    constexpr int BBYT = 32 * BSTR * 2;
    constexpr int MFR  = BM / 32;
    constexpr int NFR  = BN / 32;
    constexpr int A_CH = BM * 4 / 256;
    constexpr int B_CH = 32 * (BN / 8) / 256;
    constexpr int BSH  = (BN == 128) ? 4 : 3;

    extern __shared__ char smem[];
    char* As = smem;
    char* Bs = smem + S * ABYT;

    const int tid  = threadIdx.x;
    const int wid  = tid >> 5;
    const int lane = tid & 31;
    const int warpM = (wid >> 2) * (BM / 2);
    const int warpN = (wid & 3) * (BN / 4);
    const int rowBase = blockIdx.x * BM;
    const int colBase = blockIdx.y * BN;

    const uint32_t aBase = smem_u32(As);
    const uint32_t bBase = smem_u32(Bs);
    const int lrow  = lane & 15;
    const int lhalf = (lane >> 4) * 8;
    const uint32_t aLane = (uint32_t)((warpM + lrow) * ASTR + lhalf) * 2;
    const uint32_t bLane = (uint32_t)(lrow * BSTR + warpN + lhalf) * 2;

    float acc[MFR][NFR][4];
#pragma unroll
    for (int i = 0; i < MFR; i++)
#pragma unroll
        for (int j = 0; j < NFR; j++)
#pragma unroll
            for (int e = 0; e < 4; e++) acc[i][j][e] = 0.f;

    auto issue = [&](int t) {
        const int kt = t * 32;
        const int sb = t & (S - 1);
        uint32_t ad = aBase + sb * ABYT;
        uint32_t bd = bBase + sb * BBYT;
#pragma unroll
        for (int i = 0; i < A_CH; i++) {
            int idx = i * 256 + tid;
            int r = idx >> 2, ch = idx & 3;
            cp16(ad + (uint32_t)(r * ASTR + ch * 8) * 2,
                 A + (size_t)(rowBase + r) * lda + kt + ch * 8);
        }
#pragma unroll
        for (int i = 0; i < B_CH; i++) {
            int idx = i * 256 + tid;
            int r = idx >> BSH, ch = idx & ((1 << BSH) - 1);
            cp16(bd + (uint32_t)(r * BSTR + ch * 8) * 2,
                 B + (size_t)(kt + r) * ldb + colBase + ch * 8);
        }
    };

#pragma unroll
    for (int s = 0; s < S - 1; ++s) {
        if (s < nT) issue(s);
        CP_COMMIT();
    }

    for (int t = 0; t < nT; ++t) {
        CP_WAIT2();
        __syncthreads();
        if (t + S - 1 < nT) issue(t + S - 1);
        CP_COMMIT();

        const int sb = t & (S - 1);
        const uint32_t ad = aBase + sb * ABYT;
        const uint32_t bd = bBase + sb * BBYT;
#pragma unroll
        for (int k16 = 0; k16 < 2; ++k16) {
            uint32_t af[MFR][4];
            uint32_t bf[NFR][2];
#pragma unroll
            for (int mi = 0; mi < MFR; mi++)
                ldsm4(af[mi], ad + aLane + (uint32_t)(mi * 16 * ASTR + k16 * 16) * 2);
#pragma unroll
            for (int p = 0; p < NFR / 2; p++)
                ldsm4t(&bf[p * 2][0], bd + bLane + (uint32_t)(k16 * 16 * BSTR + p * 16) * 2);
#pragma unroll
            for (int mi = 0; mi < MFR; mi++)
#pragma unroll
                for (int ni = 0; ni < NFR; ni++)
                    mma16816(acc[mi][ni], af[mi], bf[ni]);
        }
    }

    // ---- epilogue ----
    const int row0 = rowBase + warpM + (lane >> 2);
    const int col0 = colBase + warpN + (lane & 3) * 2;
#pragma unroll
    for (int mi = 0; mi < MFR; mi++) {
#pragma unroll
        for (int ni = 0; ni < NFR; ni++) {
#pragma unroll
            for (int half = 0; half < 2; half++) {
                int row = row0 + mi * 16 + half * 8;
                int col = col0 + ni * 8;
                float v0 = acc[mi][ni][half * 2 + 0];
                float v1 = acc[mi][ni][half * 2 + 1];
                if (EPI == EPI_TANH) {
                    v0 = tanhf(v0); v1 = tanhf(v1);
                } else if (EPI == EPI_WEXP) {
                    v0 = expf(-expf(bias[col] + v0));
                    v1 = expf(-expf(bias[col + 1] + v1));
                }
                if (OUTH) {
                    *(uint32_t*)((__half*)C + (size_t)row * ldc + col) = h2u(v0, v1);
                } else {
                    float* co = (float*)C + (size_t)row * ldc + col;
                    co[0] = v0; co[1] = v1;
                }
            }
        }
    }
}

// ---------------- fused mix kernel: BM=64, 3 CTA/SM ----------------
#define HST 136
#define MIX_SMEM ((64*HST + 128*HST + 64*HST) * 2)

__global__ void __launch_bounds__(256, 3)
k_mix(const __half* __restrict__ h16, const __half* __restrict__ w2h,
      const float* __restrict__ xf, const float* __restrict__ xxf,
      const float* __restrict__ tmw, const float* __restrict__ tmk,
      const float* __restrict__ tmv, const float* __restrict__ tmr,
      __half* __restrict__ oxw, __half* __restrict__ oxk,
      __half* __restrict__ oxv, __half* __restrict__ oxr)
{
    extern __shared__ char smem[];
    uint16_t* hs  = (uint16_t*)smem;
    uint16_t* wsm = (uint16_t*)(smem + 64 * HST * 2);
    uint16_t* st  = (uint16_t*)(smem + (64 + 128) * HST * 2);

    const int tid  = threadIdx.x;
    const int wid  = tid >> 5;
    const int lane = tid & 31;
    const int warpM = (wid >> 2) * 32;
    const int warpN = (wid & 3) * 32;
    const int rowBase = blockIdx.x * 64;
    const int colBase = blockIdx.y * 128;

    const uint32_t hsB = smem_u32(hs);
    const uint32_t wB  = smem_u32(wsm);

#pragma unroll
    for (int i = 0; i < 4; i++) {
        int idx = i * 256 + tid;
        int r = idx >> 4, ch = idx & 15;
        cp16(hsB + (uint32_t)(r * HST + ch * 8) * 2,
             h16 + (size_t)(rowBase + r) * DM4 + ch * 8);
    }
#pragma unroll
    for (int i = 0; i < 8; i++) {
        int idx = i * 256 + tid;
        int f = idx >> 9, rem = idx & 511;
        int r = rem >> 4, ch = rem & 15;
        cp16(wB + (uint32_t)((f * 32 + r) * HST + ch * 8) * 2,
             w2h + (size_t)(f * 32 + r) * Cc + colBase + ch * 8);
    }
    CP_COMMIT();
    CP_WAIT0();
    __syncthreads();

    const int lrow  = lane & 15;
    const int lhalf = (lane >> 4) * 8;
    const uint32_t aLane = (uint32_t)((warpM + lrow) * HST + lhalf) * 2;
    const uint32_t bLane = (uint32_t)(lrow * HST + warpN + lhalf) * 2;

#pragma unroll
    for (int f = 0; f < 4; f++) {
        const float* tmf = (f == 0) ? tmw : (f == 1) ? tmk : (f == 2) ? tmv : tmr;
        __half* of = (f == 0) ? oxw : (f == 1) ? oxk : (f == 2) ? oxv : oxr;

        float acc[2][4][4];
#pragma unroll
        for (int i = 0; i < 2; i++)
#pragma unroll
            for (int j = 0; j < 4; j++)
#pragma unroll
                for (int e = 0; e < 4; e++) acc[i][j][e] = 0.f;

#pragma unroll
        for (int k16 = 0; k16 < 2; ++k16) {
            uint32_t af[2][4];
            uint32_t bf[4][2];
#pragma unroll
            for (int mi = 0; mi < 2; mi++)
                ldsm4(af[mi], hsB + aLane + (uint32_t)(mi * 16 * HST + f * 32 + k16 * 16) * 2);
#pragma unroll
            for (int p = 0; p < 2; p++)
                ldsm4t(&bf[p * 2][0], wB + bLane + (uint32_t)((f * 32 + k16 * 16) * HST + p * 16) * 2);
#pragma unroll
            for (int mi = 0; mi < 2; mi++)
#pragma unroll
                for (int ni = 0; ni < 4; ni++)
                    mma16816(acc[mi][ni], af[mi], bf[ni]);
        }

        __syncthreads();   // prior f's stage reads done
#pragma unroll
        for (int mi = 0; mi < 2; mi++)
#pragma unroll
            for (int ni = 0; ni < 4; ni++)
#pragma unroll
                for (int half = 0; half < 2; half++) {
                    int srow = warpM + mi * 16 + half * 8 + (lane >> 2);
                    int scol = warpN + ni * 8 + (lane & 3) * 2;
                    *(uint32_t*)&st[srow * HST + scol] =
                        h2u(acc[mi][ni][half * 2], acc[mi][ni][half * 2 + 1]);
                }
        __syncthreads();

        // coalesced epilogue: 4 uint4 per thread
#pragma unroll
        for (int it = 0; it < 4; ++it) {
            int idx = it * 256 + tid;
            int row = idx >> 4, seg = idx & 15;
            int gcol = colBase + seg * 8;
            size_t goff = (size_t)(rowBase + row) * Cc + gcol;
            uint4 mv = *(uint4*)&st[row * HST + seg * 8];
            float4 xa  = *(const float4*)(xf + goff);
            float4 xb  = *(const float4*)(xf + goff + 4);
            float4 xxa = *(const float4*)(xxf + goff);
            float4 xxb = *(const float4*)(xxf + goff + 4);
            float4 ta  = *(const float4*)(tmf + gcol);
            float4 tb  = *(const float4*)(tmf + gcol + 4);
            __half2 m0 = *(__half2*)&mv.x;
            __half2 m1 = *(__half2*)&mv.y;
            __half2 m2 = *(__half2*)&mv.z;
            __half2 m3 = *(__half2*)&mv.w;
            float v0 = fmaf(xxa.x, ta.x + __low2float(m0),  xa.x);
            float v1 = fmaf(xxa.y, ta.y + __high2float(m0), xa.y);
            float v2 = fmaf(xxa.z, ta.z + __low2float(m1),  xa.z);
            float v3 = fmaf(xxa.w, ta.w + __high2float(m1), xa.w);
            float v4 = fmaf(xxb.x, tb.x + __low2float(m2),  xb.x);
            float v5 = fmaf(xxb.y, tb.y + __high2float(m2), xb.y);
            float v6 = fmaf(xxb.z, tb.z + __low2float(m3),  xb.z);
            float v7 = fmaf(xxb.w, tb.w + __high2float(m3), xb.w);
            uint4 o;
            o.x = h2u(v0, v1); o.y = h2u(v2, v3);
            o.z = h2u(v4, v5); o.w = h2u(v6, v7);
            *(uint4*)(of + goff) = o;
        }
    }
}

// ---------------- token shift: xx fp32 + xxx fp16 ----------------
__global__ void __launch_bounds__(256) k_shift(const float4* __restrict__ x,
                                               const float4* __restrict__ tmx,
                                               float4* __restrict__ oxx,
                                               uint2* __restrict__ oxxx16)
{
    int i = blockIdx.x * 256 + threadIdx.x;
    int c4 = i & (C4 - 1);
    int n  = i >> 8;
    int t  = n & (Tc - 1);
    float4 xv = x[i];
    float4 xp = make_float4(0.f, 0.f, 0.f, 0.f);
    if (t != 0) xp = x[i - C4];
    float4 d;
    d.x = xp.x - xv.x; d.y = xp.y - xv.y; d.z = xp.z - xv.z; d.w = xp.w - xv.w;
    float4 tm = tmx[c4];
    float4 o;
    o.x = fmaf(d.x, tm.x, xv.x); o.y = fmaf(d.y, tm.y, xv.y);
    o.z = fmaf(d.z, tm.z, xv.z); o.w = fmaf(d.w, tm.w, xv.w);
    oxx[i]    = d;
    oxxx16[i] = f4toh(o);
}

// ---------------- WKV6 chunked scan ----------------
#define WKV_CT 64

// pass 1: per-segment local end state + decay product (no y)
__global__ void __launch_bounds__(64) k_wkv1(const float* __restrict__ k,
                                             const float* __restrict__ v,
                                             const float* __restrict__ w,
                                             float* __restrict__ Sseg,
                                             float* __restrict__ Wseg)
{
    const int p  = blockIdx.x;
    const int bh = blockIdx.y;
    const int b = bh >> 6, h = bh & 63;
    const int tid  = threadIdx.x;
    const int wq   = tid >> 5;
    const int lane = tid & 31;
    const int j  = wq * 8 + (lane & 7);
    const int ig = lane >> 3;
    const int base = (b * Tc + p * TSEG) * (Hc * HSc) + h * HSc;

    __shared__ __align__(16) float ks[2][WKV_CT][16];
    __shared__ __align__(16) float ws[2][WKV_CT][16];
    __shared__ __align__(16) float vs[2][WKV_CT][16];

    float S0 = 0.f, S1 = 0.f, S2 = 0.f, S3 = 0.f;
    float wp0 = 1.f, wp1 = 1.f, wp2 = 1.f, wp3 = 1.f;

    auto issue_chunk = [&](int t0, int buf) {
#pragma unroll
        for (int i = 0; i < 4; i++) {
            int idx = i * 64 + tid;
            int tt = idx >> 2;
            int i4 = (idx & 3) * 4;
            int off = base + (t0 + tt) * (Hc * HSc) + i4;
            cp16(smem_u32(&ks[buf][tt][i4]), k + off);
            cp16(smem_u32(&ws[buf][tt][i4]), w + off);
            cp16(smem_u32(&vs[buf][tt][i4]), v + off);
        }
        CP_COMMIT();
    };

    issue_chunk(0, 0);
    const int nChunks = TSEG / WKV_CT;   // 2
    for (int c = 0; c < nChunks; ++c) {
        const int buf = c & 1;
        if (c + 1 < nChunks) {
            issue_chunk((c + 1) * WKV_CT, buf ^ 1);
            CP_WAIT1();
        } else {
            CP_WAIT0();
        }
        __syncthreads();
        for (int tt = 0; tt < WKV_CT; ++tt) {
            float4 kk = *(const float4*)&ks[buf][tt][ig * 4];
            float4 ww = *(const float4*)&ws[buf][tt][ig * 4];
            float vj = vs[buf][tt][j];
            S0 = fmaf(ww.x, S0, kk.x * vj);
            S1 = fmaf(ww.y, S1, kk.y * vj);
            S2 = fmaf(ww.z, S2, kk.z * vj);
            S3 = fmaf(ww.w, S3, kk.w * vj);
            wp0 *= ww.x; wp1 *= ww.y; wp2 *= ww.z; wp3 *= ww.w;
        }
        __syncthreads();
    }

    const size_t so = ((size_t)(bh * P_SEG + p) << 8) + (ig * 4) * 16 + j;
    Sseg[so]      = S0;
    Sseg[so + 16] = S1;
    Sseg[so + 32] = S2;
    Sseg[so + 48] = S3;
    if (wq == 0 && (lane & 7) == 0) {
        float* wo = Wseg + (size_t)(bh * P_SEG + p) * 16 + ig * 4;
        wo[0] = wp0; wo[1] = wp1; wo[2] = wp2; wo[3] = wp3;
    }
}

// scan: initial state per segment
__global__ void __launch_bounds__(256) k_wscan(const float* __restrict__ Sseg,
                                               const float* __restrict__ Wseg,
                                               float* __restrict__ Sin)
{
    const int bh = blockIdx.x;
    const int tid = threadIdx.x;
    const int i = tid >> 4;
    float s = 0.f;
#pragma unroll
    for (int p = 0; p < P_SEG; ++p) {
        size_t o = (size_t)(bh * P_SEG + p) << 8;
        Sin[o + tid] = s;
        s = fmaf(Wseg[(size_t)(bh * P_SEG + p) * 16 + i], s, Sseg[o + tid]);
    }
}

// pass 2: replay with scanned initial state, emit y
__global__ void __launch_bounds__(64) k_wkv2(const float* __restrict__ u_faaaa,
                                             const float* __restrict__ r,
                                             const float* __restrict__ k,
                                             const float* __restrict__ v,
                                             const float* __restrict__ w,
                                             const float* __restrict__ Sin,
                                             float* __restrict__ y)
{
    const int p  = blockIdx.x;
    const int bh = blockIdx.y;
    const int b = bh >> 6, h = bh & 63;
    const int tid  = threadIdx.x;
    const int wq   = tid >> 5;
    const int lane = tid & 31;
    const int j  = wq * 8 + (lane & 7);
    const int ig = lane >> 3;
    const int base = (b * Tc + p * TSEG) * (Hc * HSc) + h * HSc;

    __shared__ __align__(16) float rs[2][WKV_CT][16];
    __shared__ __align__(16) float ks[2][WKV_CT][16];
    __shared__ __align__(16) float ws[2][WKV_CT][16];
    __shared__ __align__(16) float vs[2][WKV_CT][16];

    const size_t so = ((size_t)(bh * P_SEG + p) << 8) + (ig * 4) * 16 + j;
    float S0 = Sin[so], S1 = Sin[so + 16], S2 = Sin[so + 32], S3 = Sin[so + 48];
    const float4 u4 = *(const float4*)(u_faaaa + h * HSc + ig * 4);

    auto issue_chunk = [&](int t0, int buf) {
#pragma unroll
        for (int i = 0; i < 4; i++) {
            int idx = i * 64 + tid;
            int tt = idx >> 2;
            int i4 = (idx & 3) * 4;
            int off = base + (t0 + tt) * (Hc * HSc) + i4;
            cp16(smem_u32(&rs[buf][tt][i4]), r + off);
            cp16(smem_u32(&ks[buf][tt][i4]), k + off);
            cp16(smem_u32(&ws[buf][tt][i4]), w + off);
            cp16(smem_u32(&vs[buf][tt][i4]), v + off);
        }
        CP_COMMIT();
    };

    issue_chunk(0, 0);
    const int nChunks = TSEG / WKV_CT;   // 2
    for (int c = 0; c < nChunks; ++c) {
        const int buf = c & 1;
        if (c + 1 < nChunks) {
            issue_chunk((c + 1) * WKV_CT, buf ^ 1);
            CP_WAIT1();
        } else {
            CP_WAIT0();
        }
        __syncthreads();

        const int ybase = base + c * WKV_CT * (Hc * HSc) + j;
        for (int tt = 0; tt < WKV_CT; ++tt) {
            float4 rr = *(const float4*)&rs[buf][tt][ig * 4];
            float4 kk = *(const float4*)&ks[buf][tt][ig * 4];
            float4 ww = *(const float4*)&ws[buf][tt][ig * 4];
            float vj = vs[buf][tt][j];
            float kv, acc;
            kv = kk.x * vj; acc = rr.x * fmaf(u4.x, kv, S0);           S0 = fmaf(ww.x, S0, kv);
            kv = kk.y * vj; acc = fmaf(rr.y, fmaf(u4.y, kv, S1), acc); S1 = fmaf(ww.y, S1, kv);
            kv = kk.z * vj; acc = fmaf(rr.z, fmaf(u4.z, kv, S2), acc); S2 = fmaf(ww.z, S2, kv);
            kv = kk.w * vj; acc = fmaf(rr.w, fmaf(u4.w, kv, S3), acc); S3 = fmaf(ww.w, S3, kv);
            acc += __shfl_xor_sync(0xffffffffu, acc, 8);
            acc += __shfl_xor_sync(0xffffffffu, acc, 16);
            if (ig == 0) y[ybase + tt * (Hc * HSc)] = acc;
        }
        __syncthreads();
    }
}

// ---------------- LayerNorm -> fp16 ----------------
__global__ void __launch_bounds__(256) k_ln(const float* __restrict__ y,
                                            const float* __restrict__ g,
                                            const float* __restrict__ bb,
                                            uint2* __restrict__ out16)
{
    const int n   = blockIdx.x;
    const int tid = threadIdx.x;
    const float4* yr = (const float4*)(y + (size_t)n * Cc);
    float4 vv = yr[tid];
    float s = vv.x + vv.y + vv.z + vv.w;
    float q = vv.x * vv.x + vv.y * vv.y + vv.z * vv.z + vv.w * vv.w;
#pragma unroll
    for (int o = 16; o > 0; o >>= 1) {
        s += __shfl_xor_sync(0xffffffffu, s, o);
        q += __shfl_xor_sync(0xffffffffu, q, o);
    }
    __shared__ float ssh[8], qsh[8];
    if ((tid & 31) == 0) { ssh[tid >> 5] = s; qsh[tid >> 5] = q; }
    __syncthreads();
    float st = 0.f, qt = 0.f;
#pragma unroll
    for (int wix = 0; wix < 8; wix++) { st += ssh[wix]; qt += qsh[wix]; }
    float mean = st * (1.0f / Cc);
    float var  = qt * (1.0f / Cc) - mean * mean;
    float rstd = rsqrtf(var + 1e-5f);
    float4 gg = ((const float4*)g)[tid];
    float4 b4 = ((const float4*)bb)[tid];
    float4 o;
    o.x = (vv.x - mean) * rstd * gg.x + b4.x;
    o.y = (vv.y - mean) * rstd * gg.y + b4.y;
    o.z = (vv.z - mean) * rstd * gg.z + b4.z;
    o.w = (vv.w - mean) * rstd * gg.w + b4.w;
    out16[(size_t)n * (Cc / 4) + tid] = f4toh(o);
}

// ---------------- launcher ----------------
#define SM128 (4*(128*40*2 + 32*136*2))
#define SM64  (4*(64*40*2 + 32*72*2))

extern "C" void kernel_launch(void* const* d_in, const int* in_sizes, int n_in,
                              void* d_out, int out_size)
{
    (void)in_sizes; (void)n_in; (void)out_size;
    const float* x     = (const float*)d_in[0];
    const float* tmx   = (const float*)d_in[1];
    const float* tmw   = (const float*)d_in[2];
    const float* tmk   = (const float*)d_in[3];
    const float* tmv   = (const float*)d_in[4];
    const float* tmr   = (const float*)d_in[5];
    const float* w1    = (const float*)d_in[6];
    const float* w2    = (const float*)d_in[7];
    const float* tdec  = (const float*)d_in[8];
    const float* dw1   = (const float*)d_in[9];
    const float* dw2   = (const float*)d_in[10];
    const float* faaaa = (const float*)d_in[11];
    const float* Wr    = (const float*)d_in[12];
    const float* Wk    = (const float*)d_in[13];
    const float* Wv    = (const float*)d_in[14];
    const float* Wo    = (const float*)d_in[15];
    const float* lng   = (const float*)d_in[16];
    const float* lnb   = (const float*)d_in[17];
    float* out = (float*)d_out;

    static float *p_xx = nullptr, *p_y, *p_r, *p_k, *p_v, *p_we,
                 *p_ss, *p_si, *p_wp;
    static __half *p16_xxx, *p16_xw, *p16_xk, *p16_xv, *p16_xr, *p16_h, *p16_t1,
                  *p16_wr, *p16_wk, *p16_wv, *p16_wo, *p16_w1, *p16_dw1, *p16_dw2, *p16_w2;
    if (!p_xx) {
        cudaGetSymbolAddress((void**)&p_xx,    g_xx);
        cudaGetSymbolAddress((void**)&p_y,     g_y);
        cudaGetSymbolAddress((void**)&p_r,     g_r);
        cudaGetSymbolAddress((void**)&p_k,     g_k);
        cudaGetSymbolAddress((void**)&p_v,     g_v);
        cudaGetSymbolAddress((void**)&p_we,    g_we);
        cudaGetSymbolAddress((void**)&p_ss,    g_sseg);
        cudaGetSymbolAddress((void**)&p_si,    g_sin);
        cudaGetSymbolAddress((void**)&p_wp,    g_wp);
        cudaGetSymbolAddress((void**)&p16_xxx, g16_xxx);
        cudaGetSymbolAddress((void**)&p16_xw,  g16_xw);
        cudaGetSymbolAddress((void**)&p16_xk,  g16_xk);
        cudaGetSymbolAddress((void**)&p16_xv,  g16_xv);
        cudaGetSymbolAddress((void**)&p16_xr,  g16_xr);
        cudaGetSymbolAddress((void**)&p16_h,   g16_h);
        cudaGetSymbolAddress((void**)&p16_t1,  g16_t1);
        cudaGetSymbolAddress((void**)&p16_wr,  g16_wr);
        cudaGetSymbolAddress((void**)&p16_wk,  g16_wk);
        cudaGetSymbolAddress((void**)&p16_wv,  g16_wv);
        cudaGetSymbolAddress((void**)&p16_wo,  g16_wo);
        cudaGetSymbolAddress((void**)&p16_w1,  g16_w1);
        cudaGetSymbolAddress((void**)&p16_dw1, g16_dw1);
        cudaGetSymbolAddress((void**)&p16_dw2, g16_dw2);
        cudaGetSymbolAddress((void**)&p16_w2,  g16_w2);
        cudaFuncSetAttribute(gemmh<128,128,EPI_NONE,0>, cudaFuncAttributeMaxDynamicSharedMemorySize, SM128);
        cudaFuncSetAttribute(gemmh<128,128,EPI_WEXP,0>, cudaFuncAttributeMaxDynamicSharedMemorySize, SM128);
        cudaFuncSetAttribute(gemmh<64,64,EPI_TANH,1>,   cudaFuncAttributeMaxDynamicSharedMemorySize, SM64);
        cudaFuncSetAttribute(k_mix, cudaFuncAttributeMaxDynamicSharedMemorySize, MIX_SMEM);
    }
    __half* p16_yn = p16_xxx;      // yn overwrites xxx (dead after h gemm)

    // 0) weight converts — single launch, 8 segments (counts in float4)
    {
        CvtArgs a;
        const float* srcs[8] = { Wr, Wk, Wv, Wo, w1, dw1, dw2, w2 };
        __half* dsts[8] = { p16_wr, p16_wk, p16_wv, p16_wo, p16_w1, p16_dw1, p16_dw2, p16_w2 };
        int cnts[8] = { Cc*Cc/4, Cc*Cc/4, Cc*Cc/4, Cc*Cc/4, Cc*DM4/4, Cc*DDEC/4, DDEC*Cc/4, 4*32*Cc/4 };
        int cum = 0;
        for (int i = 0; i < 8; i++) {
            a.s[i] = (const float4*)srcs[i];
            a.d[i] = (uint2*)dsts[i];
            a.off[i] = cum;
            cum += cnts[i];
        }
        a.off[8] = cum;
        k_cvt<<<(cum + 255) / 256, 256>>>(a);
    }

    // 1) token shift -> xx fp32, xxx fp16
    k_shift<<<NTOK, 256>>>((const float4*)x, (const float4*)tmx,
                           (float4*)p_xx, (uint2*)p16_xxx);

    // 2) h = tanh(xxx @ w1)  [8192,1024]x[1024,128]
    gemmh<64,64,EPI_TANH,1><<<dim3(NTOK/64, DM4/64), 256, SM64>>>(
        p16_xxx, p16_w1, p16_h, Cc/32, Cc, DM4, DM4, nullptr);

    // 3) fused mix: xw/xk/xv/xr in one launch (fp32 x/xx in epilogue)
    k_mix<<<dim3(NTOK/64, Cc/128), 256, MIX_SMEM>>>(
        p16_h, p16_w2, x, p_xx,
        tmw, tmk, tmv, tmr,
        p16_xw, p16_xk, p16_xv, p16_xr);

    // 4) t1 = tanh(xw @ dw1)  K=1024, N=64
    gemmh<64,64,EPI_TANH,1><<<dim3(NTOK/64, 1), 256, SM64>>>(
        p16_xw, p16_dw1, p16_t1, Cc/32, Cc, DDEC, DDEC, nullptr);

    // 5) we = exp(-exp(tdec + t1 @ dw2))  K=64
    gemmh<128,128,EPI_WEXP,0><<<dim3(NTOK/128, Cc/128), 256, SM128>>>(
        p16_t1, p16_dw2, p_we, DDEC/32, DDEC, Cc, Cc, tdec);

    // 6) r/k/v projections  K=1024
    gemmh<128,128,EPI_NONE,0><<<dim3(NTOK/128, Cc/128), 256, SM128>>>(
        p16_xr, p16_wr, p_r, Cc/32, Cc, Cc, Cc, nullptr);
    gemmh<128,128,EPI_NONE,0><<<dim3(NTOK/128, Cc/128), 256, SM128>>>(
        p16_xk, p16_wk, p_k, Cc/32, Cc, Cc, Cc, nullptr);
    gemmh<128,128,EPI_NONE,0><<<dim3(NTOK/128, Cc/128), 256, SM128>>>(
        p16_xv, p16_wv, p_v, Cc/32, Cc, Cc, Cc, nullptr);

    // 7) WKV6 chunked scan: pass1 -> scan -> pass2
    k_wkv1<<<dim3(P_SEG, Bc * Hc), 64>>>(p_k, p_v, p_we, p_ss, p_wp);
    k_wscan<<<Bc * Hc, 256>>>(p_ss, p_wp, p_si);
    k_wkv2<<<dim3(P_SEG, Bc * Hc), 64>>>(faaaa, p_r, p_k, p_v, p_we, p_si, p_y);

    // 8) LayerNorm -> fp16
    k_ln<<<NTOK, 256>>>(p_y, lng, lnb, (uint2*)p16_yn);

    // 9) out = yn @ Wo  K=1024
    gemmh<128,128,EPI_NONE,0><<<dim3(NTOK/128, Cc/128), 256, SM128>>>(
        p16_yn, p16_wo, out, Cc/32, Cc, Cc, Cc, nullptr);
}

// round 9
// speedup vs baseline: 3.0839x; 1.0912x over previous
#include <cuda_runtime.h>
#include <cuda_fp16.h>
#include <math.h>
#include <cstdint>

// ---------------- problem constants ----------------
#define Bc    4
#define Tc    2048
#define Cc    1024
#define Hc    64
#define HSc   16
#define NTOK  (Bc*Tc)            // 8192
#define C4    (Cc/4)             // 256
#define NC    (NTOK*Cc)
#define DM4   128
#define DDEC  64
#define P_SEG 16
#define TSEG  (Tc/P_SEG)         // 128
#define NSEG  (Bc*Hc*P_SEG)      // 4096

// ---------------- scratch ----------------
// fp32
__device__ __align__(16) float g_xx [NC];
__device__ __align__(16) float g_y  [NC];
__device__ __align__(16) float g_r  [NC];
__device__ __align__(16) float g_k  [NC];
__device__ __align__(16) float g_v  [NC];
__device__ __align__(16) float g_we [NC];
__device__ __align__(16) float g_sseg[NSEG*256];
__device__ __align__(16) float g_sin [NSEG*256];
__device__ __align__(16) float g_wp  [NSEG*16];
// fp16 activations
__device__ __align__(16) __half g16_xxx[NC];       // reused as yn
__device__ __align__(16) __half g16_xw [NC];
__device__ __align__(16) __half g16_xk [NC];
__device__ __align__(16) __half g16_xv [NC];
__device__ __align__(16) __half g16_xr [NC];
__device__ __align__(16) __half g16_h  [NTOK*DM4];
__device__ __align__(16) __half g16_t1 [NTOK*DDEC];
// fp16 weights
__device__ __align__(16) __half g16_wr [Cc*Cc];
__device__ __align__(16) __half g16_wk [Cc*Cc];
__device__ __align__(16) __half g16_wv [Cc*Cc];
__device__ __align__(16) __half g16_wo [Cc*Cc];
__device__ __align__(16) __half g16_w1 [Cc*DM4];
__device__ __align__(16) __half g16_dw1[Cc*DDEC];
__device__ __align__(16) __half g16_dw2[DDEC*Cc];
__device__ __align__(16) __half g16_w2 [4*32*Cc];

// ---------------- helpers ----------------
__device__ __forceinline__ uint32_t smem_u32(const void* p) {
    uint32_t a;
    asm("{ .reg .u64 t; cvta.to.shared.u64 t, %1; cvt.u32.u64 %0, t; }" : "=r"(a) : "l"(p));
    return a;
}
__device__ __forceinline__ void ldsm4(uint32_t* r, uint32_t addr) {
    asm volatile("ldmatrix.sync.aligned.m8n8.x4.shared.b16 {%0,%1,%2,%3}, [%4];"
        : "=r"(r[0]), "=r"(r[1]), "=r"(r[2]), "=r"(r[3]) : "r"(addr));
}
__device__ __forceinline__ void ldsm4t(uint32_t* r, uint32_t addr) {
    asm volatile("ldmatrix.sync.aligned.m8n8.x4.trans.shared.b16 {%0,%1,%2,%3}, [%4];"
        : "=r"(r[0]), "=r"(r[1]), "=r"(r[2]), "=r"(r[3]) : "r"(addr));
}
__device__ __forceinline__ void mma16816(float* d, const uint32_t* a, const uint32_t* b) {
    asm volatile(
        "mma.sync.aligned.m16n8k16.row.col.f32.f16.f16.f32 "
        "{%0,%1,%2,%3}, {%4,%5,%6,%7}, {%8,%9}, {%0,%1,%2,%3};"
        : "+f"(d[0]), "+f"(d[1]), "+f"(d[2]), "+f"(d[3])
        : "r"(a[0]), "r"(a[1]), "r"(a[2]), "r"(a[3]), "r"(b[0]), "r"(b[1]));
}
__device__ __forceinline__ void cp16(uint32_t sdst, const void* gsrc) {
    asm volatile("cp.async.cg.shared.global [%0], [%1], 16;" :: "r"(sdst), "l"(gsrc));
}
#define CP_COMMIT() asm volatile("cp.async.commit_group;")
#define CP_WAIT2()  asm volatile("cp.async.wait_group 2;")
#define CP_WAIT1()  asm volatile("cp.async.wait_group 1;")
#define CP_WAIT0()  asm volatile("cp.async.wait_group 0;")

__device__ __forceinline__ uint32_t h2u(float a, float b) {
    __half2 h = __floats2half2_rn(a, b);
    return *reinterpret_cast<uint32_t*>(&h);
}
__device__ __forceinline__ uint2 f4toh(float4 v) {
    return make_uint2(h2u(v.x, v.y), h2u(v.z, v.w));
}

// ---------------- one-shot weight convert (8 segments) ----------------
struct CvtArgs {
    const float4* s[8];
    uint2* d[8];
    int off[9];
};
__global__ void __launch_bounds__(256) k_cvt(CvtArgs a) {
    int i = blockIdx.x * 256 + threadIdx.x;
    if (i >= a.off[8]) return;
#pragma unroll
    for (int sg = 0; sg < 8; sg++) {
        if (i < a.off[sg + 1]) {
            int j = i - a.off[sg];
            a.d[sg][j] = f4toh(a.s[sg][j]);
            return;
        }
    }
}

// ---------------- GEMM: fp16, cp.async 4-stage, mma.sync ----------------
enum { EPI_NONE = 0, EPI_TANH = 1, EPI_WEXP = 2 };

template<int BM, int BN, int EPI, int OUTH>
struct GemmBody {
    static __device__ __forceinline__ void run(
        const __half* __restrict__ A, const __half* __restrict__ B,
        void* __restrict__ C, int nT, int lda, int ldb, int ldc,
        const float* __restrict__ bias, char* smem,
        int rowBase, int colBase)
    {
        constexpr int S    = 4;
        constexpr int ASTR = 40;
        constexpr int BSTR = BN + 8;
        constexpr int ABYT = BM * ASTR * 2;
        constexpr int BBYT = 32 * BSTR * 2;
        constexpr int MFR  = BM / 32;
        constexpr int NFR  = BN / 32;
        constexpr int A_CH = BM * 4 / 256;
        constexpr int B_CH = 32 * (BN / 8) / 256;
        constexpr int BSH  = (BN == 128) ? 4 : 3;

        char* As = smem;
        char* Bs = smem + S * ABYT;

        const int tid  = threadIdx.x;
        const int wid  = tid >> 5;
        const int lane = tid & 31;
        const int warpM = (wid >> 2) * (BM / 2);
        const int warpN = (wid & 3) * (BN / 4);

        const uint32_t aBase = smem_u32(As);
        const uint32_t bBase = smem_u32(Bs);
        const int lrow  = lane & 15;
        const int lhalf = (lane >> 4) * 8;
        const uint32_t aLane = (uint32_t)((warpM + lrow) * ASTR + lhalf) * 2;
        const uint32_t bLane = (uint32_t)(lrow * BSTR + warpN + lhalf) * 2;

        float acc[MFR][NFR][4];
#pragma unroll
        for (int i = 0; i < MFR; i++)
#pragma unroll
            for (int j = 0; j < NFR; j++)
#pragma unroll
                for (int e = 0; e < 4; e++) acc[i][j][e] = 0.f;

        auto issue = [&](int t) {
            const int kt = t * 32;
            const int sb = t & (S - 1);
            uint32_t ad = aBase + sb * ABYT;
            uint32_t bd = bBase + sb * BBYT;
#pragma unroll
            for (int i = 0; i < A_CH; i++) {
                int idx = i * 256 + tid;
                int r = idx >> 2, ch = idx & 3;
                cp16(ad + (uint32_t)(r * ASTR + ch * 8) * 2,
                     A + (size_t)(rowBase + r) * lda + kt + ch * 8);
            }
#pragma unroll
            for (int i = 0; i < B_CH; i++) {
                int idx = i * 256 + tid;
                int r = idx >> BSH, ch = idx & ((1 << BSH) - 1);
                cp16(bd + (uint32_t)(r * BSTR + ch * 8) * 2,
                     B + (size_t)(kt + r) * ldb + colBase + ch * 8);
            }
        };

#pragma unroll
        for (int s = 0; s < S - 1; ++s) {
            if (s < nT) issue(s);
            CP_COMMIT();
        }

        for (int t = 0; t < nT; ++t) {
            CP_WAIT2();
            __syncthreads();
            if (t + S - 1 < nT) issue(t + S - 1);
            CP_COMMIT();

            const int sb = t & (S - 1);
            const uint32_t ad = aBase + sb * ABYT;
            const uint32_t bd = bBase + sb * BBYT;
#pragma unroll
            for (int k16 = 0; k16 < 2; ++k16) {
                uint32_t af[MFR][4];
                uint32_t bf[NFR][2];
#pragma unroll
                for (int mi = 0; mi < MFR; mi++)
                    ldsm4(af[mi], ad + aLane + (uint32_t)(mi * 16 * ASTR + k16 * 16) * 2);
#pragma unroll
                for (int p = 0; p < NFR / 2; p++)
                    ldsm4t(&bf[p * 2][0], bd + bLane + (uint32_t)(k16 * 16 * BSTR + p * 16) * 2);
#pragma unroll
                for (int mi = 0; mi < MFR; mi++)
#pragma unroll
                    for (int ni = 0; ni < NFR; ni++)
                        mma16816(acc[mi][ni], af[mi], bf[ni]);
            }
        }

        // ---- epilogue ----
        const int row0 = rowBase + warpM + (lane >> 2);
        const int col0 = colBase + warpN + (lane & 3) * 2;
#pragma unroll
        for (int mi = 0; mi < MFR; mi++) {
#pragma unroll
            for (int ni = 0; ni < NFR; ni++) {
#pragma unroll
                for (int half = 0; half < 2; half++) {
                    int row = row0 + mi * 16 + half * 8;
                    int col = col0 + ni * 8;
                    float v0 = acc[mi][ni][half * 2 + 0];
                    float v1 = acc[mi][ni][half * 2 + 1];
                    if (EPI == EPI_TANH) {
                        v0 = tanhf(v0); v1 = tanhf(v1);
                    } else if (EPI == EPI_WEXP) {
                        v0 = expf(-expf(bias[col] + v0));
                        v1 = expf(-expf(bias[col + 1] + v1));
                    }
                    if (OUTH) {
                        *(uint32_t*)((__half*)C + (size_t)row * ldc + col) = h2u(v0, v1);
                    } else {
                        float* co = (float*)C + (size_t)row * ldc + col;
                        co[0] = v0; co[1] = v1;
                    }
                }
            }
        }
    }
};

template<int BM, int BN, int EPI, int OUTH>
__global__ void __launch_bounds__(256, 2)
gemmh(const __half* __restrict__ A, const __half* __restrict__ B,
      void* __restrict__ C, int nT, int lda, int ldb, int ldc,
      const float* __restrict__ bias)
{
    extern __shared__ char smem[];
    GemmBody<BM, BN, EPI, OUTH>::run(A, B, C, nT, lda, ldb, ldc, bias, smem,
                                     blockIdx.x * BM, blockIdx.y * BN);
}

// batched r/k/v projections: one launch, z selects matrix
struct RkvArgs { const __half* A[3]; const __half* B[3]; float* C[3]; };
__global__ void __launch_bounds__(256, 2)
gemmh_rkv(RkvArgs args)
{
    extern __shared__ char smem[];
    const int z = blockIdx.z;
    GemmBody<128, 128, EPI_NONE, 0>::run(args.A[z], args.B[z], args.C[z],
                                         Cc / 32, Cc, Cc, Cc, nullptr, smem,
                                         blockIdx.x * 128, blockIdx.y * 128);
}

// ---------------- fused mix kernel v3: stage all 4 f, single epilogue ----------------
#define HST2 136
#define BST2 72
#define MIX_SMEM ((64*HST2 + 128*BST2 + 4*64*BST2) * 2)

__global__ void __launch_bounds__(256, 3)
k_mix(const __half* __restrict__ h16, const __half* __restrict__ w2h,
      const float* __restrict__ xf, const float* __restrict__ xxf,
      const float* __restrict__ tmw, const float* __restrict__ tmk,
      const float* __restrict__ tmv, const float* __restrict__ tmr,
      __half* __restrict__ oxw, __half* __restrict__ oxk,
      __half* __restrict__ oxv, __half* __restrict__ oxr)
{
    extern __shared__ char smem[];
    uint16_t* hs  = (uint16_t*)smem;                            // [64][136]
    uint16_t* wsm = (uint16_t*)(smem + 64 * HST2 * 2);          // [128][72]
    uint16_t* st  = (uint16_t*)(smem + (64 * HST2 + 128 * BST2) * 2); // [4][64][72]

    const int tid  = threadIdx.x;
    const int wid  = tid >> 5;
    const int lane = tid & 31;
    const int warpM = (wid >> 2) * 32;
    const int warpN = (wid & 3) * 16;
    const int rowBase = blockIdx.x * 64;
    const int colBase = blockIdx.y * 64;

    const uint32_t hsB = smem_u32(hs);
    const uint32_t wB  = smem_u32(wsm);

    // loads: h tile 64x128, w2 tile 128x64 (rows = f*32+r)
#pragma unroll
    for (int i = 0; i < 4; i++) {
        int idx = i * 256 + tid;
        int r = idx >> 4, ch = idx & 15;
        cp16(hsB + (uint32_t)(r * HST2 + ch * 8) * 2,
             h16 + (size_t)(rowBase + r) * DM4 + ch * 8);
    }
#pragma unroll
    for (int i = 0; i < 4; i++) {
        int idx = i * 256 + tid;
        int r = idx >> 3, ch = idx & 7;
        cp16(wB + (uint32_t)(r * BST2 + ch * 8) * 2,
             w2h + (size_t)r * Cc + colBase + ch * 8);
    }
    CP_COMMIT();
    CP_WAIT0();
    __syncthreads();

    const int lrow  = lane & 15;
    const int lhalf = (lane >> 4) * 8;
    const uint32_t aLane = (uint32_t)((warpM + lrow) * HST2 + lhalf) * 2;
    const uint32_t bLane = (uint32_t)(lrow * BST2 + warpN + lhalf) * 2;

#pragma unroll
    for (int f = 0; f < 4; f++) {
        float acc[2][2][4];
#pragma unroll
        for (int i = 0; i < 2; i++)
#pragma unroll
            for (int j = 0; j < 2; j++)
#pragma unroll
                for (int e = 0; e < 4; e++) acc[i][j][e] = 0.f;

#pragma unroll
        for (int k16 = 0; k16 < 2; ++k16) {
            uint32_t af[2][4];
            uint32_t bf[2][2];
#pragma unroll
            for (int mi = 0; mi < 2; mi++)
                ldsm4(af[mi], hsB + aLane + (uint32_t)(mi * 16 * HST2 + f * 32 + k16 * 16) * 2);
            ldsm4t(&bf[0][0], wB + bLane + (uint32_t)((f * 32 + k16 * 16) * BST2) * 2);
#pragma unroll
            for (int mi = 0; mi < 2; mi++)
#pragma unroll
                for (int ni = 0; ni < 2; ni++)
                    mma16816(acc[mi][ni], af[mi], bf[ni]);
        }

        // stage acc -> st[f]
#pragma unroll
        for (int mi = 0; mi < 2; mi++)
#pragma unroll
            for (int ni = 0; ni < 2; ni++)
#pragma unroll
                for (int half = 0; half < 2; half++) {
                    int srow = warpM + mi * 16 + half * 8 + (lane >> 2);
                    int scol = warpN + ni * 8 + (lane & 3) * 2;
                    *(uint32_t*)&st[(f * 64 + srow) * BST2 + scol] =
                        h2u(acc[mi][ni][half * 2], acc[mi][ni][half * 2 + 1]);
                }
    }
    __syncthreads();

    // single epilogue: read x/xx once, write all 4 outputs
#pragma unroll
    for (int it = 0; it < 2; ++it) {
        int idx = it * 256 + tid;
        int row = idx >> 3, seg = idx & 7;
        int gcol = colBase + seg * 8;
        size_t goff = (size_t)(rowBase + row) * Cc + gcol;
        float4 xa  = *(const float4*)(xf + goff);
        float4 xb  = *(const float4*)(xf + goff + 4);
        float4 xxa = *(const float4*)(xxf + goff);
        float4 xxb = *(const float4*)(xxf + goff + 4);
#pragma unroll
        for (int f = 0; f < 4; f++) {
            const float* tmf = (f == 0) ? tmw : (f == 1) ? tmk : (f == 2) ? tmv : tmr;
            __half* of = (f == 0) ? oxw : (f == 1) ? oxk : (f == 2) ? oxv : oxr;
            uint4 mv = *(uint4*)&st[(f * 64 + row) * BST2 + seg * 8];
            float4 ta = *(const float4*)(tmf + gcol);
            float4 tb = *(const float4*)(tmf + gcol + 4);
            __half2 m0 = *(__half2*)&mv.x;
            __half2 m1 = *(__half2*)&mv.y;
            __half2 m2 = *(__half2*)&mv.z;
            __half2 m3 = *(__half2*)&mv.w;
            float v0 = fmaf(xxa.x, ta.x + __low2float(m0),  xa.x);
            float v1 = fmaf(xxa.y, ta.y + __high2float(m0), xa.y);
            float v2 = fmaf(xxa.z, ta.z + __low2float(m1),  xa.z);
            float v3 = fmaf(xxa.w, ta.w + __high2float(m1), xa.w);
            float v4 = fmaf(xxb.x, tb.x + __low2float(m2),  xb.x);
            float v5 = fmaf(xxb.y, tb.y + __high2float(m2), xb.y);
            float v6 = fmaf(xxb.z, tb.z + __low2float(m3),  xb.z);
            float v7 = fmaf(xxb.w, tb.w + __high2float(m3), xb.w);
            uint4 o;
            o.x = h2u(v0, v1); o.y = h2u(v2, v3);
            o.z = h2u(v4, v5); o.w = h2u(v6, v7);
            *(uint4*)(of + goff) = o;
        }
    }
}

// ---------------- token shift: xx fp32 + xxx fp16 ----------------
__global__ void __launch_bounds__(256) k_shift(const float4* __restrict__ x,
                                               const float4* __restrict__ tmx,
                                               float4* __restrict__ oxx,
                                               uint2* __restrict__ oxxx16)
{
    int i = blockIdx.x * 256 + threadIdx.x;
    int c4 = i & (C4 - 1);
    int n  = i >> 8;
    int t  = n & (Tc - 1);
    float4 xv = x[i];
    float4 xp = make_float4(0.f, 0.f, 0.f, 0.f);
    if (t != 0) xp = x[i - C4];
    float4 d;
    d.x = xp.x - xv.x; d.y = xp.y - xv.y; d.z = xp.z - xv.z; d.w = xp.w - xv.w;
    float4 tm = tmx[c4];
    float4 o;
    o.x = fmaf(d.x, tm.x, xv.x); o.y = fmaf(d.y, tm.y, xv.y);
    o.z = fmaf(d.z, tm.z, xv.z); o.w = fmaf(d.w, tm.w, xv.w);
    oxx[i]    = d;
    oxxx16[i] = f4toh(o);
}

// ---------------- WKV6 chunked scan ----------------
#define WKV_CT 64

__global__ void __launch_bounds__(64) k_wkv1(const float* __restrict__ k,
                                             const float* __restrict__ v,
                                             const float* __restrict__ w,
                                             float* __restrict__ Sseg,
                                             float* __restrict__ Wseg)
{
    const int p  = blockIdx.x;
    const int bh = blockIdx.y;
    const int b = bh >> 6, h = bh & 63;
    const int tid  = threadIdx.x;
    const int wq   = tid >> 5;
    const int lane = tid & 31;
    const int j  = wq * 8 + (lane & 7);
    const int ig = lane >> 3;
    const int base = (b * Tc + p * TSEG) * (Hc * HSc) + h * HSc;

    __shared__ __align__(16) float ks[2][WKV_CT][16];
    __shared__ __align__(16) float ws[2][WKV_CT][16];
    __shared__ __align__(16) float vs[2][WKV_CT][16];

    float S0 = 0.f, S1 = 0.f, S2 = 0.f, S3 = 0.f;
    float wp0 = 1.f, wp1 = 1.f, wp2 = 1.f, wp3 = 1.f;

    auto issue_chunk = [&](int t0, int buf) {
#pragma unroll
        for (int i = 0; i < 4; i++) {
            int idx = i * 64 + tid;
            int tt = idx >> 2;
            int i4 = (idx & 3) * 4;
            int off = base + (t0 + tt) * (Hc * HSc) + i4;
            cp16(smem_u32(&ks[buf][tt][i4]), k + off);
            cp16(smem_u32(&ws[buf][tt][i4]), w + off);
            cp16(smem_u32(&vs[buf][tt][i4]), v + off);
        }
        CP_COMMIT();
    };

    issue_chunk(0, 0);
    const int nChunks = TSEG / WKV_CT;
    for (int c = 0; c < nChunks; ++c) {
        const int buf = c & 1;
        if (c + 1 < nChunks) {
            issue_chunk((c + 1) * WKV_CT, buf ^ 1);
            CP_WAIT1();
        } else {
            CP_WAIT0();
        }
        __syncthreads();
        for (int tt = 0; tt < WKV_CT; ++tt) {
            float4 kk = *(const float4*)&ks[buf][tt][ig * 4];
            float4 ww = *(const float4*)&ws[buf][tt][ig * 4];
            float vj = vs[buf][tt][j];
            S0 = fmaf(ww.x, S0, kk.x * vj);
            S1 = fmaf(ww.y, S1, kk.y * vj);
            S2 = fmaf(ww.z, S2, kk.z * vj);
            S3 = fmaf(ww.w, S3, kk.w * vj);
            wp0 *= ww.x; wp1 *= ww.y; wp2 *= ww.z; wp3 *= ww.w;
        }
        __syncthreads();
    }

    const size_t so = ((size_t)(bh * P_SEG + p) << 8) + (ig * 4) * 16 + j;
    Sseg[so]      = S0;
    Sseg[so + 16] = S1;
    Sseg[so + 32] = S2;
    Sseg[so + 48] = S3;
    if (wq == 0 && (lane & 7) == 0) {
        float* wo = Wseg + (size_t)(bh * P_SEG + p) * 16 + ig * 4;
        wo[0] = wp0; wo[1] = wp1; wo[2] = wp2; wo[3] = wp3;
    }
}

__global__ void __launch_bounds__(256) k_wscan(const float* __restrict__ Sseg,
                                               const float* __restrict__ Wseg,
                                               float* __restrict__ Sin)
{
    const int bh = blockIdx.x;
    const int tid = threadIdx.x;
    const int i = tid >> 4;
    float s = 0.f;
#pragma unroll
    for (int p = 0; p < P_SEG; ++p) {
        size_t o = (size_t)(bh * P_SEG + p) << 8;
        Sin[o + tid] = s;
        s = fmaf(Wseg[(size_t)(bh * P_SEG + p) * 16 + i], s, Sseg[o + tid]);
    }
}

__global__ void __launch_bounds__(64) k_wkv2(const float* __restrict__ u_faaaa,
                                             const float* __restrict__ r,
                                             const float* __restrict__ k,
                                             const float* __restrict__ v,
                                             const float* __restrict__ w,
                                             const float* __restrict__ Sin,
                                             float* __restrict__ y)
{
    const int p  = blockIdx.x;
    const int bh = blockIdx.y;
    const int b = bh >> 6, h = bh & 63;
    const int tid  = threadIdx.x;
    const int wq   = tid >> 5;
    const int lane = tid & 31;
    const int j  = wq * 8 + (lane & 7);
    const int ig = lane >> 3;
    const int base = (b * Tc + p * TSEG) * (Hc * HSc) + h * HSc;

    __shared__ __align__(16) float rs[2][WKV_CT][16];
    __shared__ __align__(16) float ks[2][WKV_CT][16];
    __shared__ __align__(16) float ws[2][WKV_CT][16];
    __shared__ __align__(16) float vs[2][WKV_CT][16];

    const size_t so = ((size_t)(bh * P_SEG + p) << 8) + (ig * 4) * 16 + j;
    float S0 = Sin[so], S1 = Sin[so + 16], S2 = Sin[so + 32], S3 = Sin[so + 48];
    const float4 u4 = *(const float4*)(u_faaaa + h * HSc + ig * 4);

    auto issue_chunk = [&](int t0, int buf) {
#pragma unroll
        for (int i = 0; i < 4; i++) {
            int idx = i * 64 + tid;
            int tt = idx >> 2;
            int i4 = (idx & 3) * 4;
            int off = base + (t0 + tt) * (Hc * HSc) + i4;
            cp16(smem_u32(&rs[buf][tt][i4]), r + off);
            cp16(smem_u32(&ks[buf][tt][i4]), k + off);
            cp16(smem_u32(&ws[buf][tt][i4]), w + off);
            cp16(smem_u32(&vs[buf][tt][i4]), v + off);
        }
        CP_COMMIT();
    };

    issue_chunk(0, 0);
    const int nChunks = TSEG / WKV_CT;
    for (int c = 0; c < nChunks; ++c) {
        const int buf = c & 1;
        if (c + 1 < nChunks) {
            issue_chunk((c + 1) * WKV_CT, buf ^ 1);
            CP_WAIT1();
        } else {
            CP_WAIT0();
        }
        __syncthreads();

        const int ybase = base + c * WKV_CT * (Hc * HSc) + j;
        for (int tt = 0; tt < WKV_CT; ++tt) {
            float4 rr = *(const float4*)&rs[buf][tt][ig * 4];
            float4 kk = *(const float4*)&ks[buf][tt][ig * 4];
            float4 ww = *(const float4*)&ws[buf][tt][ig * 4];
            float vj = vs[buf][tt][j];
            float kv, acc;
            kv = kk.x * vj; acc = rr.x * fmaf(u4.x, kv, S0);           S0 = fmaf(ww.x, S0, kv);
            kv = kk.y * vj; acc = fmaf(rr.y, fmaf(u4.y, kv, S1), acc); S1 = fmaf(ww.y, S1, kv);
            kv = kk.z * vj; acc = fmaf(rr.z, fmaf(u4.z, kv, S2), acc); S2 = fmaf(ww.z, S2, kv);
            kv = kk.w * vj; acc = fmaf(rr.w, fmaf(u4.w, kv, S3), acc); S3 = fmaf(ww.w, S3, kv);
            acc += __shfl_xor_sync(0xffffffffu, acc, 8);
            acc += __shfl_xor_sync(0xffffffffu, acc, 16);
            if (ig == 0) y[ybase + tt * (Hc * HSc)] = acc;
        }
        __syncthreads();
    }
}

// ---------------- LayerNorm -> fp16 ----------------
__global__ void __launch_bounds__(256) k_ln(const float* __restrict__ y,
                                            const float* __restrict__ g,
                                            const float* __restrict__ bb,
                                            uint2* __restrict__ out16)
{
    const int n   = blockIdx.x;
    const int tid = threadIdx.x;
    const float4* yr = (const float4*)(y + (size_t)n * Cc);
    float4 vv = yr[tid];
    float s = vv.x + vv.y + vv.z + vv.w;
    float q = vv.x * vv.x + vv.y * vv.y + vv.z * vv.z + vv.w * vv.w;
#pragma unroll
    for (int o = 16; o > 0; o >>= 1) {
        s += __shfl_xor_sync(0xffffffffu, s, o);
        q += __shfl_xor_sync(0xffffffffu, q, o);
    }
    __shared__ float ssh[8], qsh[8];
    if ((tid & 31) == 0) { ssh[tid >> 5] = s; qsh[tid >> 5] = q; }
    __syncthreads();
    float st = 0.f, qt = 0.f;
#pragma unroll
    for (int wix = 0; wix < 8; wix++) { st += ssh[wix]; qt += qsh[wix]; }
    float mean = st * (1.0f / Cc);
    float var  = qt * (1.0f / Cc) - mean * mean;
    float rstd = rsqrtf(var + 1e-5f);
    float4 gg = ((const float4*)g)[tid];
    float4 b4 = ((const float4*)bb)[tid];
    float4 o;
    o.x = (vv.x - mean) * rstd * gg.x + b4.x;
    o.y = (vv.y - mean) * rstd * gg.y + b4.y;
    o.z = (vv.z - mean) * rstd * gg.z + b4.z;
    o.w = (vv.w - mean) * rstd * gg.w + b4.w;
    out16[(size_t)n * (Cc / 4) + tid] = f4toh(o);
}

// ---------------- launcher ----------------
#define SM128 (4*(128*40*2 + 32*136*2))
#define SM64  (4*(64*40*2 + 32*72*2))

extern "C" void kernel_launch(void* const* d_in, const int* in_sizes, int n_in,
                              void* d_out, int out_size)
{
    (void)in_sizes; (void)n_in; (void)out_size;
    const float* x     = (const float*)d_in[0];
    const float* tmx   = (const float*)d_in[1];
    const float* tmw   = (const float*)d_in[2];
    const float* tmk   = (const float*)d_in[3];
    const float* tmv   = (const float*)d_in[4];
    const float* tmr   = (const float*)d_in[5];
    const float* w1    = (const float*)d_in[6];
    const float* w2    = (const float*)d_in[7];
    const float* tdec  = (const float*)d_in[8];
    const float* dw1   = (const float*)d_in[9];
    const float* dw2   = (const float*)d_in[10];
    const float* faaaa = (const float*)d_in[11];
    const float* Wr    = (const float*)d_in[12];
    const float* Wk    = (const float*)d_in[13];
    const float* Wv    = (const float*)d_in[14];
    const float* Wo    = (const float*)d_in[15];
    const float* lng   = (const float*)d_in[16];
    const float* lnb   = (const float*)d_in[17];
    float* out = (float*)d_out;

    static float *p_xx = nullptr, *p_y, *p_r, *p_k, *p_v, *p_we,
                 *p_ss, *p_si, *p_wp;
    static __half *p16_xxx, *p16_xw, *p16_xk, *p16_xv, *p16_xr, *p16_h, *p16_t1,
                  *p16_wr, *p16_wk, *p16_wv, *p16_wo, *p16_w1, *p16_dw1, *p16_dw2, *p16_w2;
    if (!p_xx) {
        cudaGetSymbolAddress((void**)&p_xx,    g_xx);
        cudaGetSymbolAddress((void**)&p_y,     g_y);
        cudaGetSymbolAddress((void**)&p_r,     g_r);
        cudaGetSymbolAddress((void**)&p_k,     g_k);
        cudaGetSymbolAddress((void**)&p_v,     g_v);
        cudaGetSymbolAddress((void**)&p_we,    g_we);
        cudaGetSymbolAddress((void**)&p_ss,    g_sseg);
        cudaGetSymbolAddress((void**)&p_si,    g_sin);
        cudaGetSymbolAddress((void**)&p_wp,    g_wp);
        cudaGetSymbolAddress((void**)&p16_xxx, g16_xxx);
        cudaGetSymbolAddress((void**)&p16_xw,  g16_xw);
        cudaGetSymbolAddress((void**)&p16_xk,  g16_xk);
        cudaGetSymbolAddress((void**)&p16_xv,  g16_xv);
        cudaGetSymbolAddress((void**)&p16_xr,  g16_xr);
        cudaGetSymbolAddress((void**)&p16_h,   g16_h);
        cudaGetSymbolAddress((void**)&p16_t1,  g16_t1);
        cudaGetSymbolAddress((void**)&p16_wr,  g16_wr);
        cudaGetSymbolAddress((void**)&p16_wk,  g16_wk);
        cudaGetSymbolAddress((void**)&p16_wv,  g16_wv);
        cudaGetSymbolAddress((void**)&p16_wo,  g16_wo);
        cudaGetSymbolAddress((void**)&p16_w1,  g16_w1);
        cudaGetSymbolAddress((void**)&p16_dw1, g16_dw1);
        cudaGetSymbolAddress((void**)&p16_dw2, g16_dw2);
        cudaGetSymbolAddress((void**)&p16_w2,  g16_w2);
        cudaFuncSetAttribute(gemmh<128,128,EPI_NONE,0>, cudaFuncAttributeMaxDynamicSharedMemorySize, SM128);
        cudaFuncSetAttribute(gemmh<128,128,EPI_WEXP,0>, cudaFuncAttributeMaxDynamicSharedMemorySize, SM128);
        cudaFuncSetAttribute(gemmh<64,64,EPI_TANH,1>,   cudaFuncAttributeMaxDynamicSharedMemorySize, SM64);
        cudaFuncSetAttribute(gemmh_rkv, cudaFuncAttributeMaxDynamicSharedMemorySize, SM128);
        cudaFuncSetAttribute(k_mix, cudaFuncAttributeMaxDynamicSharedMemorySize, MIX_SMEM);
    }
    __half* p16_yn = p16_xxx;      // yn overwrites xxx (dead after h gemm)

    // 0) weight converts — single launch, 8 segments (counts in float4)
    {
        CvtArgs a;
        const float* srcs[8] = { Wr, Wk, Wv, Wo, w1, dw1, dw2, w2 };
        __half* dsts[8] = { p16_wr, p16_wk, p16_wv, p16_wo, p16_w1, p16_dw1, p16_dw2, p16_w2 };
        int cnts[8] = { Cc*Cc/4, Cc*Cc/4, Cc*Cc/4, Cc*Cc/4, Cc*DM4/4, Cc*DDEC/4, DDEC*Cc/4, 4*32*Cc/4 };
        int cum = 0;
        for (int i = 0; i < 8; i++) {
            a.s[i] = (const float4*)srcs[i];
            a.d[i] = (uint2*)dsts[i];
            a.off[i] = cum;
            cum += cnts[i];
        }
        a.off[8] = cum;
        k_cvt<<<(cum + 255) / 256, 256>>>(a);
    }

    // 1) token shift -> xx fp32, xxx fp16
    k_shift<<<NTOK, 256>>>((const float4*)x, (const float4*)tmx,
                           (float4*)p_xx, (uint2*)p16_xxx);

    // 2) h = tanh(xxx @ w1)  [8192,1024]x[1024,128]
    gemmh<64,64,EPI_TANH,1><<<dim3(NTOK/64, DM4/64), 256, SM64>>>(
        p16_xxx, p16_w1, p16_h, Cc/32, Cc, DM4, DM4, nullptr);

    // 3) fused mix v3: xw/xk/xv/xr, x/xx read once
    k_mix<<<dim3(NTOK/64, Cc/64), 256, MIX_SMEM>>>(
        p16_h, p16_w2, x, p_xx,
        tmw, tmk, tmv, tmr,
        p16_xw, p16_xk, p16_xv, p16_xr);

    // 4) t1 = tanh(xw @ dw1)  K=1024, N=64
    gemmh<64,64,EPI_TANH,1><<<dim3(NTOK/64, 1), 256, SM64>>>(
        p16_xw, p16_dw1, p16_t1, Cc/32, Cc, DDEC, DDEC, nullptr);

    // 5) we = exp(-exp(tdec + t1 @ dw2))  K=64
    gemmh<128,128,EPI_WEXP,0><<<dim3(NTOK/128, Cc/128), 256, SM128>>>(
        p16_t1, p16_dw2, p_we, DDEC/32, DDEC, Cc, Cc, tdec);

    // 6) r/k/v projections — one batched launch
    {
        RkvArgs ra;
        ra.A[0] = p16_xr; ra.A[1] = p16_xk; ra.A[2] = p16_xv;
        ra.B[0] = p16_wr; ra.B[1] = p16_wk; ra.B[2] = p16_wv;
        ra.C[0] = p_r;    ra.C[1] = p_k;    ra.C[2] = p_v;
        gemmh_rkv<<<dim3(NTOK/128, Cc/128, 3), 256, SM128>>>(ra);
    }

    // 7) WKV6 chunked scan: pass1 -> scan -> pass2
    k_wkv1<<<dim3(P_SEG, Bc * Hc), 64>>>(p_k, p_v, p_we, p_ss, p_wp);
    k_wscan<<<Bc * Hc, 256>>>(p_ss, p_wp, p_si);
    k_wkv2<<<dim3(P_SEG, Bc * Hc), 64>>>(faaaa, p_r, p_k, p_v, p_we, p_si, p_y);

    // 8) LayerNorm -> fp16
    k_ln<<<NTOK, 256>>>(p_y, lng, lnb, (uint2*)p16_yn);

    // 9) out = yn @ Wo  K=1024
    gemmh<128,128,EPI_NONE,0><<<dim3(NTOK/128, Cc/128), 256, SM128>>>(
        p16_yn, p16_wo, out, Cc/32, Cc, Cc, Cc, nullptr);
}

// round 10
// speedup vs baseline: 3.3588x; 1.0891x over previous
#include <cuda_runtime.h>
#include <cuda_fp16.h>
#include <math.h>
#include <cstdint>

// ---------------- problem constants ----------------
#define Bc    4
#define Tc    2048
#define Cc    1024
#define Hc    64
#define HSc   16
#define NTOK  (Bc*Tc)            // 8192
#define C4    (Cc/4)             // 256
#define NC    (NTOK*Cc)
#define DM4   128
#define DDEC  64
#define P_SEG 16
#define TSEG  (Tc/P_SEG)         // 128
#define NSEG  (Bc*Hc*P_SEG)      // 4096

// ---------------- scratch ----------------
// fp32
__device__ __align__(16) float g_y  [NC];
__device__ __align__(16) float g_we [NC];
__device__ __align__(16) float g_sseg[NSEG*256];
__device__ __align__(16) float g_sin [NSEG*256];
__device__ __align__(16) float g_wp  [NSEG*16];
// fp16 activations
__device__ __align__(16) __half g16_xxx[NC];       // reused as yn
__device__ __align__(16) __half g16_xw [NC];
__device__ __align__(16) __half g16_xk [NC];
__device__ __align__(16) __half g16_xv [NC];
__device__ __align__(16) __half g16_xr [NC];
__device__ __align__(16) __half g16_r  [NC];
__device__ __align__(16) __half g16_k  [NC];
__device__ __align__(16) __half g16_v  [NC];
__device__ __align__(16) __half g16_h  [NTOK*DM4];
__device__ __align__(16) __half g16_t1 [NTOK*DDEC];
// fp16 weights
__device__ __align__(16) __half g16_wr [Cc*Cc];
__device__ __align__(16) __half g16_wk [Cc*Cc];
__device__ __align__(16) __half g16_wv [Cc*Cc];
__device__ __align__(16) __half g16_wo [Cc*Cc];
__device__ __align__(16) __half g16_w1 [Cc*DM4];
__device__ __align__(16) __half g16_dw1[Cc*DDEC];
__device__ __align__(16) __half g16_dw2[DDEC*Cc];
__device__ __align__(16) __half g16_w2 [4*32*Cc];

// ---------------- helpers ----------------
__device__ __forceinline__ uint32_t smem_u32(const void* p) {
    uint32_t a;
    asm("{ .reg .u64 t; cvta.to.shared.u64 t, %1; cvt.u32.u64 %0, t; }" : "=r"(a) : "l"(p));
    return a;
}
__device__ __forceinline__ void ldsm4(uint32_t* r, uint32_t addr) {
    asm volatile("ldmatrix.sync.aligned.m8n8.x4.shared.b16 {%0,%1,%2,%3}, [%4];"
        : "=r"(r[0]), "=r"(r[1]), "=r"(r[2]), "=r"(r[3]) : "r"(addr));
}
__device__ __forceinline__ void ldsm4t(uint32_t* r, uint32_t addr) {
    asm volatile("ldmatrix.sync.aligned.m8n8.x4.trans.shared.b16 {%0,%1,%2,%3}, [%4];"
        : "=r"(r[0]), "=r"(r[1]), "=r"(r[2]), "=r"(r[3]) : "r"(addr));
}
__device__ __forceinline__ void mma16816(float* d, const uint32_t* a, const uint32_t* b) {
    asm volatile(
        "mma.sync.aligned.m16n8k16.row.col.f32.f16.f16.f32 "
        "{%0,%1,%2,%3}, {%4,%5,%6,%7}, {%8,%9}, {%0,%1,%2,%3};"
        : "+f"(d[0]), "+f"(d[1]), "+f"(d[2]), "+f"(d[3])
        : "r"(a[0]), "r"(a[1]), "r"(a[2]), "r"(a[3]), "r"(b[0]), "r"(b[1]));
}
__device__ __forceinline__ void cp16(uint32_t sdst, const void* gsrc) {
    asm volatile("cp.async.cg.shared.global [%0], [%1], 16;" :: "r"(sdst), "l"(gsrc));
}
#define CP_COMMIT() asm volatile("cp.async.commit_group;")
#define CP_WAIT2()  asm volatile("cp.async.wait_group 2;")
#define CP_WAIT1()  asm volatile("cp.async.wait_group 1;")
#define CP_WAIT0()  asm volatile("cp.async.wait_group 0;")

__device__ __forceinline__ uint32_t h2u(float a, float b) {
    __half2 h = __floats2half2_rn(a, b);
    return *reinterpret_cast<uint32_t*>(&h);
}
__device__ __forceinline__ uint2 f4toh(float4 v) {
    return make_uint2(h2u(v.x, v.y), h2u(v.z, v.w));
}

// ---------------- one-shot weight convert (8 segments) ----------------
struct CvtArgs {
    const float4* s[8];
    uint2* d[8];
    int off[9];
};
__global__ void __launch_bounds__(256) k_cvt(CvtArgs a) {
    int i = blockIdx.x * 256 + threadIdx.x;
    if (i >= a.off[8]) return;
#pragma unroll
    for (int sg = 0; sg < 8; sg++) {
        if (i < a.off[sg + 1]) {
            int j = i - a.off[sg];
            a.d[sg][j] = f4toh(a.s[sg][j]);
            return;
        }
    }
}

// ---------------- GEMM: fp16, cp.async 4-stage, mma.sync ----------------
enum { EPI_NONE = 0, EPI_TANH = 1, EPI_WEXP = 2 };

template<int BM, int BN, int EPI, int OUTH>
struct GemmBody {
    static __device__ __forceinline__ void run(
        const __half* __restrict__ A, const __half* __restrict__ B,
        void* __restrict__ C, int nT, int lda, int ldb, int ldc,
        const float* __restrict__ bias, char* smem,
        int rowBase, int colBase)
    {
        constexpr int S    = 4;
        constexpr int ASTR = 40;
        constexpr int BSTR = BN + 8;
        constexpr int ABYT = BM * ASTR * 2;
        constexpr int BBYT = 32 * BSTR * 2;
        constexpr int MFR  = BM / 32;
        constexpr int NFR  = BN / 32;
        constexpr int A_CH = BM * 4 / 256;
        constexpr int B_CH = 32 * (BN / 8) / 256;
        constexpr int BSH  = (BN == 128) ? 4 : 3;

        char* As = smem;
        char* Bs = smem + S * ABYT;

        const int tid  = threadIdx.x;
        const int wid  = tid >> 5;
        const int lane = tid & 31;
        const int warpM = (wid >> 2) * (BM / 2);
        const int warpN = (wid & 3) * (BN / 4);

        const uint32_t aBase = smem_u32(As);
        const uint32_t bBase = smem_u32(Bs);
        const int lrow  = lane & 15;
        const int lhalf = (lane >> 4) * 8;
        const uint32_t aLane = (uint32_t)((warpM + lrow) * ASTR + lhalf) * 2;
        const uint32_t bLane = (uint32_t)(lrow * BSTR + warpN + lhalf) * 2;

        float acc[MFR][NFR][4];
#pragma unroll
        for (int i = 0; i < MFR; i++)
#pragma unroll
            for (int j = 0; j < NFR; j++)
#pragma unroll
                for (int e = 0; e < 4; e++) acc[i][j][e] = 0.f;

        auto issue = [&](int t) {
            const int kt = t * 32;
            const int sb = t & (S - 1);
            uint32_t ad = aBase + sb * ABYT;
            uint32_t bd = bBase + sb * BBYT;
#pragma unroll
            for (int i = 0; i < A_CH; i++) {
                int idx = i * 256 + tid;
                int r = idx >> 2, ch = idx & 3;
                cp16(ad + (uint32_t)(r * ASTR + ch * 8) * 2,
                     A + (size_t)(rowBase + r) * lda + kt + ch * 8);
            }
#pragma unroll
            for (int i = 0; i < B_CH; i++) {
                int idx = i * 256 + tid;
                int r = idx >> BSH, ch = idx & ((1 << BSH) - 1);
                cp16(bd + (uint32_t)(r * BSTR + ch * 8) * 2,
                     B + (size_t)(kt + r) * ldb + colBase + ch * 8);
            }
        };

#pragma unroll
        for (int s = 0; s < S - 1; ++s) {
            if (s < nT) issue(s);
            CP_COMMIT();
        }

        for (int t = 0; t < nT; ++t) {
            CP_WAIT2();
            __syncthreads();
            if (t + S - 1 < nT) issue(t + S - 1);
            CP_COMMIT();

            const int sb = t & (S - 1);
            const uint32_t ad = aBase + sb * ABYT;
            const uint32_t bd = bBase + sb * BBYT;
#pragma unroll
            for (int k16 = 0; k16 < 2; ++k16) {
                uint32_t af[MFR][4];
                uint32_t bf[NFR][2];
#pragma unroll
                for (int mi = 0; mi < MFR; mi++)
                    ldsm4(af[mi], ad + aLane + (uint32_t)(mi * 16 * ASTR + k16 * 16) * 2);
#pragma unroll
                for (int p = 0; p < NFR / 2; p++)
                    ldsm4t(&bf[p * 2][0], bd + bLane + (uint32_t)(k16 * 16 * BSTR + p * 16) * 2);
#pragma unroll
                for (int mi = 0; mi < MFR; mi++)
#pragma unroll
                    for (int ni = 0; ni < NFR; ni++)
                        mma16816(acc[mi][ni], af[mi], bf[ni]);
            }
        }

        // ---- epilogue ----
        const int row0 = rowBase + warpM + (lane >> 2);
        const int col0 = colBase + warpN + (lane & 3) * 2;
#pragma unroll
        for (int mi = 0; mi < MFR; mi++) {
#pragma unroll
            for (int ni = 0; ni < NFR; ni++) {
#pragma unroll
                for (int half = 0; half < 2; half++) {
                    int row = row0 + mi * 16 + half * 8;
                    int col = col0 + ni * 8;
                    float v0 = acc[mi][ni][half * 2 + 0];
                    float v1 = acc[mi][ni][half * 2 + 1];
                    if (EPI == EPI_TANH) {
                        v0 = tanhf(v0); v1 = tanhf(v1);
                    } else if (EPI == EPI_WEXP) {
                        v0 = expf(-expf(bias[col] + v0));
                        v1 = expf(-expf(bias[col + 1] + v1));
                    }
                    if (OUTH) {
                        *(uint32_t*)((__half*)C + (size_t)row * ldc + col) = h2u(v0, v1);
                    } else {
                        float* co = (float*)C + (size_t)row * ldc + col;
                        co[0] = v0; co[1] = v1;
                    }
                }
            }
        }
    }
};

template<int BM, int BN, int EPI, int OUTH>
__global__ void __launch_bounds__(256, 2)
gemmh(const __half* __restrict__ A, const __half* __restrict__ B,
      void* __restrict__ C, int nT, int lda, int ldb, int ldc,
      const float* __restrict__ bias)
{
    extern __shared__ char smem[];
    GemmBody<BM, BN, EPI, OUTH>::run(A, B, C, nT, lda, ldb, ldc, bias, smem,
                                     blockIdx.x * BM, blockIdx.y * BN);
}

// batched: z=0..2 -> r/k/v projections (fp16 out), z=3 -> wexp (fp32 out)
struct BatchArgs {
    const __half* A[4]; const __half* B[4]; void* C[4];
    int nT[4]; int lda[4];
    const float* bias;
};
__global__ void __launch_bounds__(256, 2)
gemmh_batch(BatchArgs args)
{
    extern __shared__ char smem[];
    const int z = blockIdx.z;
    if (z < 3) {
        GemmBody<128, 128, EPI_NONE, 1>::run(args.A[z], args.B[z], args.C[z],
                                             args.nT[z], args.lda[z], Cc, Cc, nullptr, smem,
                                             blockIdx.x * 128, blockIdx.y * 128);
    } else {
        GemmBody<128, 128, EPI_WEXP, 0>::run(args.A[3], args.B[3], args.C[3],
                                             args.nT[3], args.lda[3], Cc, Cc, args.bias, smem,
                                             blockIdx.x * 128, blockIdx.y * 128);
    }
}

// ---------------- fused mix kernel: stage all 4 f, single epilogue ----------------
#define HST2 136
#define BST2 72
#define MIX_SMEM ((64*HST2 + 128*BST2 + 4*64*BST2) * 2)

__global__ void __launch_bounds__(256, 3)
k_mix(const __half* __restrict__ h16, const __half* __restrict__ w2h,
      const float* __restrict__ xf,
      const float* __restrict__ tmw, const float* __restrict__ tmk,
      const float* __restrict__ tmv, const float* __restrict__ tmr,
      __half* __restrict__ oxw, __half* __restrict__ oxk,
      __half* __restrict__ oxv, __half* __restrict__ oxr)
{
    extern __shared__ char smem[];
    uint16_t* hs  = (uint16_t*)smem;                                  // [64][136]
    uint16_t* wsm = (uint16_t*)(smem + 64 * HST2 * 2);                // [128][72]
    uint16_t* st  = (uint16_t*)(smem + (64 * HST2 + 128 * BST2) * 2); // [4][64][72]

    const int tid  = threadIdx.x;
    const int wid  = tid >> 5;
    const int lane = tid & 31;
    const int warpM = (wid >> 2) * 32;
    const int warpN = (wid & 3) * 16;
    const int rowBase = blockIdx.x * 64;
    const int colBase = blockIdx.y * 64;

    const uint32_t hsB = smem_u32(hs);
    const uint32_t wB  = smem_u32(wsm);

#pragma unroll
    for (int i = 0; i < 4; i++) {
        int idx = i * 256 + tid;
        int r = idx >> 4, ch = idx & 15;
        cp16(hsB + (uint32_t)(r * HST2 + ch * 8) * 2,
             h16 + (size_t)(rowBase + r) * DM4 + ch * 8);
    }
#pragma unroll
    for (int i = 0; i < 4; i++) {
        int idx = i * 256 + tid;
        int r = idx >> 3, ch = idx & 7;
        cp16(wB + (uint32_t)(r * BST2 + ch * 8) * 2,
             w2h + (size_t)r * Cc + colBase + ch * 8);
    }
    CP_COMMIT();
    CP_WAIT0();
    __syncthreads();

    const int lrow  = lane & 15;
    const int lhalf = (lane >> 4) * 8;
    const uint32_t aLane = (uint32_t)((warpM + lrow) * HST2 + lhalf) * 2;
    const uint32_t bLane = (uint32_t)(lrow * BST2 + warpN + lhalf) * 2;

#pragma unroll
    for (int f = 0; f < 4; f++) {
        float acc[2][2][4];
#pragma unroll
        for (int i = 0; i < 2; i++)
#pragma unroll
            for (int j = 0; j < 2; j++)
#pragma unroll
                for (int e = 0; e < 4; e++) acc[i][j][e] = 0.f;

#pragma unroll
        for (int k16 = 0; k16 < 2; ++k16) {
            uint32_t af[2][4];
            uint32_t bf[2][2];
#pragma unroll
            for (int mi = 0; mi < 2; mi++)
                ldsm4(af[mi], hsB + aLane + (uint32_t)(mi * 16 * HST2 + f * 32 + k16 * 16) * 2);
            ldsm4t(&bf[0][0], wB + bLane + (uint32_t)((f * 32 + k16 * 16) * BST2) * 2);
#pragma unroll
            for (int mi = 0; mi < 2; mi++)
#pragma unroll
                for (int ni = 0; ni < 2; ni++)
                    mma16816(acc[mi][ni], af[mi], bf[ni]);
        }

#pragma unroll
        for (int mi = 0; mi < 2; mi++)
#pragma unroll
            for (int ni = 0; ni < 2; ni++)
#pragma unroll
                for (int half = 0; half < 2; half++) {
                    int srow = warpM + mi * 16 + half * 8 + (lane >> 2);
                    int scol = warpN + ni * 8 + (lane & 3) * 2;
                    *(uint32_t*)&st[(f * 64 + srow) * BST2 + scol] =
                        h2u(acc[mi][ni][half * 2], acc[mi][ni][half * 2 + 1]);
                }
    }
    __syncthreads();

    // single epilogue: read x (and x_prev) once, write all 4 outputs
#pragma unroll
    for (int it = 0; it < 2; ++it) {
        int idx = it * 256 + tid;
        int row = idx >> 3, seg = idx & 7;
        int gcol = colBase + seg * 8;
        int grow = rowBase + row;
        size_t goff = (size_t)grow * Cc + gcol;
        float4 xa = *(const float4*)(xf + goff);
        float4 xb = *(const float4*)(xf + goff + 4);
        float4 pa, pb;
        if ((grow & (Tc - 1)) == 0) {
            pa = make_float4(0.f, 0.f, 0.f, 0.f);
            pb = pa;
        } else {
            pa = *(const float4*)(xf + goff - Cc);
            pb = *(const float4*)(xf + goff - Cc + 4);
        }
        float4 xxa, xxb;
        xxa.x = pa.x - xa.x; xxa.y = pa.y - xa.y; xxa.z = pa.z - xa.z; xxa.w = pa.w - xa.w;
        xxb.x = pb.x - xb.x; xxb.y = pb.y - xb.y; xxb.z = pb.z - xb.z; xxb.w = pb.w - xb.w;
#pragma unroll
        for (int f = 0; f < 4; f++) {
            const float* tmf = (f == 0) ? tmw : (f == 1) ? tmk : (f == 2) ? tmv : tmr;
            __half* of = (f == 0) ? oxw : (f == 1) ? oxk : (f == 2) ? oxv : oxr;
            uint4 mv = *(uint4*)&st[(f * 64 + row) * BST2 + seg * 8];
            float4 ta = *(const float4*)(tmf + gcol);
            float4 tb = *(const float4*)(tmf + gcol + 4);
            __half2 m0 = *(__half2*)&mv.x;
            __half2 m1 = *(__half2*)&mv.y;
            __half2 m2 = *(__half2*)&mv.z;
            __half2 m3 = *(__half2*)&mv.w;
            float v0 = fmaf(xxa.x, ta.x + __low2float(m0),  xa.x);
            float v1 = fmaf(xxa.y, ta.y + __high2float(m0), xa.y);
            float v2 = fmaf(xxa.z, ta.z + __low2float(m1),  xa.z);
            float v3 = fmaf(xxa.w, ta.w + __high2float(m1), xa.w);
            float v4 = fmaf(xxb.x, tb.x + __low2float(m2),  xb.x);
            float v5 = fmaf(xxb.y, tb.y + __high2float(m2), xb.y);
            float v6 = fmaf(xxb.z, tb.z + __low2float(m3),  xb.z);
            float v7 = fmaf(xxb.w, tb.w + __high2float(m3), xb.w);
            uint4 o;
            o.x = h2u(v0, v1); o.y = h2u(v2, v3);
            o.z = h2u(v4, v5); o.w = h2u(v6, v7);
            *(uint4*)(of + goff) = o;
        }
    }
}

// ---------------- token shift: xxx fp16 only ----------------
__global__ void __launch_bounds__(256) k_shift(const float4* __restrict__ x,
                                               const float4* __restrict__ tmx,
                                               uint2* __restrict__ oxxx16)
{
    int i = blockIdx.x * 256 + threadIdx.x;
    int c4 = i & (C4 - 1);
    int n  = i >> 8;
    int t  = n & (Tc - 1);
    float4 xv = x[i];
    float4 xp = make_float4(0.f, 0.f, 0.f, 0.f);
    if (t != 0) xp = x[i - C4];
    float4 tm = tmx[c4];
    float4 o;
    o.x = fmaf(xp.x - xv.x, tm.x, xv.x);
    o.y = fmaf(xp.y - xv.y, tm.y, xv.y);
    o.z = fmaf(xp.z - xv.z, tm.z, xv.z);
    o.w = fmaf(xp.w - xv.w, tm.w, xv.w);
    oxxx16[i] = f4toh(o);
}

// ---------------- WKV6 chunked scan (k/v/r fp16, w fp32) ----------------
#define WKV_CT 64

__global__ void __launch_bounds__(64) k_wkv1(const __half* __restrict__ k,
                                             const __half* __restrict__ v,
                                             const float* __restrict__ w,
                                             float* __restrict__ Sseg,
                                             float* __restrict__ Wseg)
{
    const int p  = blockIdx.x;
    const int bh = blockIdx.y;
    const int b = bh >> 6, h = bh & 63;
    const int tid  = threadIdx.x;
    const int wq   = tid >> 5;
    const int lane = tid & 31;
    const int j  = wq * 8 + (lane & 7);
    const int ig = lane >> 3;
    const int base = (b * Tc + p * TSEG) * (Hc * HSc) + h * HSc;

    __shared__ __align__(16) __half ks16[2][WKV_CT][16];
    __shared__ __align__(16) __half vs16[2][WKV_CT][16];
    __shared__ __align__(16) float  ws  [2][WKV_CT][16];

    float S0 = 0.f, S1 = 0.f, S2 = 0.f, S3 = 0.f;
    float wp0 = 1.f, wp1 = 1.f, wp2 = 1.f, wp3 = 1.f;

    auto issue_chunk = [&](int t0, int buf) {
#pragma unroll
        for (int i = 0; i < 2; i++) {
            int idx = i * 64 + tid;        // 0..127
            int tt = idx >> 1;
            int i8 = (idx & 1) * 8;
            int off = base + (t0 + tt) * (Hc * HSc) + i8;
            cp16(smem_u32(&ks16[buf][tt][i8]), k + off);
            cp16(smem_u32(&vs16[buf][tt][i8]), v + off);
        }
#pragma unroll
        for (int i = 0; i < 4; i++) {
            int idx = i * 64 + tid;        // 0..255
            int tt = idx >> 2;
            int i4 = (idx & 3) * 4;
            int off = base + (t0 + tt) * (Hc * HSc) + i4;
            cp16(smem_u32(&ws[buf][tt][i4]), w + off);
        }
        CP_COMMIT();
    };

    issue_chunk(0, 0);
    const int nChunks = TSEG / WKV_CT;
    for (int c = 0; c < nChunks; ++c) {
        const int buf = c & 1;
        if (c + 1 < nChunks) {
            issue_chunk((c + 1) * WKV_CT, buf ^ 1);
            CP_WAIT1();
        } else {
            CP_WAIT0();
        }
        __syncthreads();
        for (int tt = 0; tt < WKV_CT; ++tt) {
            uint2 kraw = *(const uint2*)&ks16[buf][tt][ig * 4];
            float2 k01 = __half22float2(*(const __half2*)&kraw.x);
            float2 k23 = __half22float2(*(const __half2*)&kraw.y);
            float4 ww = *(const float4*)&ws[buf][tt][ig * 4];
            float vj = __half2float(vs16[buf][tt][j]);
            S0 = fmaf(ww.x, S0, k01.x * vj);
            S1 = fmaf(ww.y, S1, k01.y * vj);
            S2 = fmaf(ww.z, S2, k23.x * vj);
            S3 = fmaf(ww.w, S3, k23.y * vj);
            wp0 *= ww.x; wp1 *= ww.y; wp2 *= ww.z; wp3 *= ww.w;
        }
        __syncthreads();
    }

    const size_t so = ((size_t)(bh * P_SEG + p) << 8) + (ig * 4) * 16 + j;
    Sseg[so]      = S0;
    Sseg[so + 16] = S1;
    Sseg[so + 32] = S2;
    Sseg[so + 48] = S3;
    if (wq == 0 && (lane & 7) == 0) {
        float* wo = Wseg + (size_t)(bh * P_SEG + p) * 16 + ig * 4;
        wo[0] = wp0; wo[1] = wp1; wo[2] = wp2; wo[3] = wp3;
    }
}

__global__ void __launch_bounds__(256) k_wscan(const float* __restrict__ Sseg,
                                               const float* __restrict__ Wseg,
                                               float* __restrict__ Sin)
{
    const int bh = blockIdx.x;
    const int tid = threadIdx.x;
    const int i = tid >> 4;
    float s = 0.f;
#pragma unroll
    for (int p = 0; p < P_SEG; ++p) {
        size_t o = (size_t)(bh * P_SEG + p) << 8;
        Sin[o + tid] = s;
        s = fmaf(Wseg[(size_t)(bh * P_SEG + p) * 16 + i], s, Sseg[o + tid]);
    }
}

__global__ void __launch_bounds__(64) k_wkv2(const float* __restrict__ u_faaaa,
                                             const __half* __restrict__ r,
                                             const __half* __restrict__ k,
                                             const __half* __restrict__ v,
                                             const float* __restrict__ w,
                                             const float* __restrict__ Sin,
                                             float* __restrict__ y)
{
    const int p  = blockIdx.x;
    const int bh = blockIdx.y;
    const int b = bh >> 6, h = bh & 63;
    const int tid  = threadIdx.x;
    const int wq   = tid >> 5;
    const int lane = tid & 31;
    const int j  = wq * 8 + (lane & 7);
    const int ig = lane >> 3;
    const int base = (b * Tc + p * TSEG) * (Hc * HSc) + h * HSc;

    __shared__ __align__(16) __half rs16[2][WKV_CT][16];
    __shared__ __align__(16) __half ks16[2][WKV_CT][16];
    __shared__ __align__(16) __half vs16[2][WKV_CT][16];
    __shared__ __align__(16) float  ws  [2][WKV_CT][16];

    const size_t so = ((size_t)(bh * P_SEG + p) << 8) + (ig * 4) * 16 + j;
    float S0 = Sin[so], S1 = Sin[so + 16], S2 = Sin[so + 32], S3 = Sin[so + 48];
    const float4 u4 = *(const float4*)(u_faaaa + h * HSc + ig * 4);

    auto issue_chunk = [&](int t0, int buf) {
#pragma unroll
        for (int i = 0; i < 2; i++) {
            int idx = i * 64 + tid;
            int tt = idx >> 1;
            int i8 = (idx & 1) * 8;
            int off = base + (t0 + tt) * (Hc * HSc) + i8;
            cp16(smem_u32(&rs16[buf][tt][i8]), r + off);
            cp16(smem_u32(&ks16[buf][tt][i8]), k + off);
            cp16(smem_u32(&vs16[buf][tt][i8]), v + off);
        }
#pragma unroll
        for (int i = 0; i < 4; i++) {
            int idx = i * 64 + tid;
            int tt = idx >> 2;
            int i4 = (idx & 3) * 4;
            int off = base + (t0 + tt) * (Hc * HSc) + i4;
            cp16(smem_u32(&ws[buf][tt][i4]), w + off);
        }
        CP_COMMIT();
    };

    issue_chunk(0, 0);
    const int nChunks = TSEG / WKV_CT;
    for (int c = 0; c < nChunks; ++c) {
        const int buf = c & 1;
        if (c + 1 < nChunks) {
            issue_chunk((c + 1) * WKV_CT, buf ^ 1);
            CP_WAIT1();
        } else {
            CP_WAIT0();
        }
        __syncthreads();

        const int ybase = base + c * WKV_CT * (Hc * HSc) + j;
        for (int tt = 0; tt < WKV_CT; ++tt) {
            uint2 rraw = *(const uint2*)&rs16[buf][tt][ig * 4];
            uint2 kraw = *(const uint2*)&ks16[buf][tt][ig * 4];
            float2 r01 = __half22float2(*(const __half2*)&rraw.x);
            float2 r23 = __half22float2(*(const __half2*)&rraw.y);
            float2 k01 = __half22float2(*(const __half2*)&kraw.x);
            float2 k23 = __half22float2(*(const __half2*)&kraw.y);
            float4 ww = *(const float4*)&ws[buf][tt][ig * 4];
            float vj = __half2float(vs16[buf][tt][j]);
            float kv, acc;
            kv = k01.x * vj; acc = r01.x * fmaf(u4.x, kv, S0);           S0 = fmaf(ww.x, S0, kv);
            kv = k01.y * vj; acc = fmaf(r01.y, fmaf(u4.y, kv, S1), acc); S1 = fmaf(ww.y, S1, kv);
            kv = k23.x * vj; acc = fmaf(r23.x, fmaf(u4.z, kv, S2), acc); S2 = fmaf(ww.z, S2, kv);
            kv = k23.y * vj; acc = fmaf(r23.y, fmaf(u4.w, kv, S3), acc); S3 = fmaf(ww.w, S3, kv);
            acc += __shfl_xor_sync(0xffffffffu, acc, 8);
            acc += __shfl_xor_sync(0xffffffffu, acc, 16);
            if (ig == 0) y[ybase + tt * (Hc * HSc)] = acc;
        }
        __syncthreads();
    }
}

// ---------------- LayerNorm -> fp16 ----------------
__global__ void __launch_bounds__(256) k_ln(const float* __restrict__ y,
                                            const float* __restrict__ g,
                                            const float* __restrict__ bb,
                                            uint2* __restrict__ out16)
{
    const int n   = blockIdx.x;
    const int tid = threadIdx.x;
    const float4* yr = (const float4*)(y + (size_t)n * Cc);
    float4 vv = yr[tid];
    float s = vv.x + vv.y + vv.z + vv.w;
    float q = vv.x * vv.x + vv.y * vv.y + vv.z * vv.z + vv.w * vv.w;
#pragma unroll
    for (int o = 16; o > 0; o >>= 1) {
        s += __shfl_xor_sync(0xffffffffu, s, o);
        q += __shfl_xor_sync(0xffffffffu, q, o);
    }
    __shared__ float ssh[8], qsh[8];
    if ((tid & 31) == 0) { ssh[tid >> 5] = s; qsh[tid >> 5] = q; }
    __syncthreads();
    float st = 0.f, qt = 0.f;
#pragma unroll
    for (int wix = 0; wix < 8; wix++) { st += ssh[wix]; qt += qsh[wix]; }
    float mean = st * (1.0f / Cc);
    float var  = qt * (1.0f / Cc) - mean * mean;
    float rstd = rsqrtf(var + 1e-5f);
    float4 gg = ((const float4*)g)[tid];
    float4 b4 = ((const float4*)bb)[tid];
    float4 o;
    o.x = (vv.x - mean) * rstd * gg.x + b4.x;
    o.y = (vv.y - mean) * rstd * gg.y + b4.y;
    o.z = (vv.z - mean) * rstd * gg.z + b4.z;
    o.w = (vv.w - mean) * rstd * gg.w + b4.w;
    out16[(size_t)n * (Cc / 4) + tid] = f4toh(o);
}

// ---------------- launcher ----------------
#define SM128 (4*(128*40*2 + 32*136*2))
#define SM64  (4*(64*40*2 + 32*72*2))

extern "C" void kernel_launch(void* const* d_in, const int* in_sizes, int n_in,
                              void* d_out, int out_size)
{
    (void)in_sizes; (void)n_in; (void)out_size;
    const float* x     = (const float*)d_in[0];
    const float* tmx   = (const float*)d_in[1];
    const float* tmw   = (const float*)d_in[2];
    const float* tmk   = (const float*)d_in[3];
    const float* tmv   = (const float*)d_in[4];
    const float* tmr   = (const float*)d_in[5];
    const float* w1    = (const float*)d_in[6];
    const float* w2    = (const float*)d_in[7];
    const float* tdec  = (const float*)d_in[8];
    const float* dw1   = (const float*)d_in[9];
    const float* dw2   = (const float*)d_in[10];
    const float* faaaa = (const float*)d_in[11];
    const float* Wr    = (const float*)d_in[12];
    const float* Wk    = (const float*)d_in[13];
    const float* Wv    = (const float*)d_in[14];
    const float* Wo    = (const float*)d_in[15];
    const float* lng   = (const float*)d_in[16];
    const float* lnb   = (const float*)d_in[17];
    float* out = (float*)d_out;

    static float *p_y = nullptr, *p_we, *p_ss, *p_si, *p_wp;
    static __half *p16_xxx, *p16_xw, *p16_xk, *p16_xv, *p16_xr,
                  *p16_r, *p16_k, *p16_v, *p16_h, *p16_t1,
                  *p16_wr, *p16_wk, *p16_wv, *p16_wo, *p16_w1, *p16_dw1, *p16_dw2, *p16_w2;
    if (!p_y) {
        cudaGetSymbolAddress((void**)&p_y,     g_y);
        cudaGetSymbolAddress((void**)&p_we,    g_we);
        cudaGetSymbolAddress((void**)&p_ss,    g_sseg);
        cudaGetSymbolAddress((void**)&p_si,    g_sin);
        cudaGetSymbolAddress((void**)&p_wp,    g_wp);
        cudaGetSymbolAddress((void**)&p16_xxx, g16_xxx);
        cudaGetSymbolAddress((void**)&p16_xw,  g16_xw);
        cudaGetSymbolAddress((void**)&p16_xk,  g16_xk);
        cudaGetSymbolAddress((void**)&p16_xv,  g16_xv);
        cudaGetSymbolAddress((void**)&p16_xr,  g16_xr);
        cudaGetSymbolAddress((void**)&p16_r,   g16_r);
        cudaGetSymbolAddress((void**)&p16_k,   g16_k);
        cudaGetSymbolAddress((void**)&p16_v,   g16_v);
        cudaGetSymbolAddress((void**)&p16_h,   g16_h);
        cudaGetSymbolAddress((void**)&p16_t1,  g16_t1);
        cudaGetSymbolAddress((void**)&p16_wr,  g16_wr);
        cudaGetSymbolAddress((void**)&p16_wk,  g16_wk);
        cudaGetSymbolAddress((void**)&p16_wv,  g16_wv);
        cudaGetSymbolAddress((void**)&p16_wo,  g16_wo);
        cudaGetSymbolAddress((void**)&p16_w1,  g16_w1);
        cudaGetSymbolAddress((void**)&p16_dw1, g16_dw1);
        cudaGetSymbolAddress((void**)&p16_dw2, g16_dw2);
        cudaGetSymbolAddress((void**)&p16_w2,  g16_w2);
        cudaFuncSetAttribute(gemmh<128,128,EPI_NONE,0>, cudaFuncAttributeMaxDynamicSharedMemorySize, SM128);
        cudaFuncSetAttribute(gemmh<64,64,EPI_TANH,1>,   cudaFuncAttributeMaxDynamicSharedMemorySize, SM64);
        cudaFuncSetAttribute(gemmh_batch, cudaFuncAttributeMaxDynamicSharedMemorySize, SM128);
        cudaFuncSetAttribute(k_mix, cudaFuncAttributeMaxDynamicSharedMemorySize, MIX_SMEM);
    }
    __half* p16_yn = p16_xxx;      // yn overwrites xxx (dead after h gemm)

    // 0) weight converts — single launch, 8 segments (counts in float4)
    {
        CvtArgs a;
        const float* srcs[8] = { Wr, Wk, Wv, Wo, w1, dw1, dw2, w2 };
        __half* dsts[8] = { p16_wr, p16_wk, p16_wv, p16_wo, p16_w1, p16_dw1, p16_dw2, p16_w2 };
        int cnts[8] = { Cc*Cc/4, Cc*Cc/4, Cc*Cc/4, Cc*Cc/4, Cc*DM4/4, Cc*DDEC/4, DDEC*Cc/4, 4*32*Cc/4 };
        int cum = 0;
        for (int i = 0; i < 8; i++) {
            a.s[i] = (const float4*)srcs[i];
            a.d[i] = (uint2*)dsts[i];
            a.off[i] = cum;
            cum += cnts[i];
        }
        a.off[8] = cum;
        k_cvt<<<(cum + 255) / 256, 256>>>(a);
    }

    // 1) token shift -> xxx fp16
    k_shift<<<NTOK, 256>>>((const float4*)x, (const float4*)tmx, (uint2*)p16_xxx);

    // 2) h = tanh(xxx @ w1)
    gemmh<64,64,EPI_TANH,1><<<dim3(NTOK/64, DM4/64), 256, SM64>>>(
        p16_xxx, p16_w1, p16_h, Cc/32, Cc, DM4, DM4, nullptr);

    // 3) fused mix: xw/xk/xv/xr (xx computed inline from x)
    k_mix<<<dim3(NTOK/64, Cc/64), 256, MIX_SMEM>>>(
        p16_h, p16_w2, x, tmw, tmk, tmv, tmr,
        p16_xw, p16_xk, p16_xv, p16_xr);

    // 4) t1 = tanh(xw @ dw1)
    gemmh<64,64,EPI_TANH,1><<<dim3(NTOK/64, 1), 256, SM64>>>(
        p16_xw, p16_dw1, p16_t1, Cc/32, Cc, DDEC, DDEC, nullptr);

    // 5) batched: r/k/v projections (fp16 out) + wexp
    {
        BatchArgs ba;
        ba.A[0] = p16_xr; ba.B[0] = p16_wr; ba.C[0] = p16_r; ba.nT[0] = Cc/32; ba.lda[0] = Cc;
        ba.A[1] = p16_xk; ba.B[1] = p16_wk; ba.C[1] = p16_k; ba.nT[1] = Cc/32; ba.lda[1] = Cc;
        ba.A[2] = p16_xv; ba.B[2] = p16_wv; ba.C[2] = p16_v; ba.nT[2] = Cc/32; ba.lda[2] = Cc;
        ba.A[3] = p16_t1; ba.B[3] = p16_dw2; ba.C[3] = p_we; ba.nT[3] = DDEC/32; ba.lda[3] = DDEC;
        ba.bias = tdec;
        gemmh_batch<<<dim3(NTOK/128, Cc/128, 4), 256, SM128>>>(ba);
    }

    // 6) WKV6 chunked scan
    k_wkv1<<<dim3(P_SEG, Bc * Hc), 64>>>(p16_k, p16_v, p_we, p_ss, p_wp);
    k_wscan<<<Bc * Hc, 256>>>(p_ss, p_wp, p_si);
    k_wkv2<<<dim3(P_SEG, Bc * Hc), 64>>>(faaaa, p16_r, p16_k, p16_v, p_we, p_si, p_y);

    // 7) LayerNorm -> fp16
    k_ln<<<NTOK, 256>>>(p_y, lng, lnb, (uint2*)p16_yn);

    // 8) out = yn @ Wo
    gemmh<128,128,EPI_NONE,0><<<dim3(NTOK/128, Cc/128), 256, SM128>>>(
        p16_yn, p16_wo, out, Cc/32, Cc, Cc, Cc, nullptr);
}

// round 11
// speedup vs baseline: 3.3819x; 1.0069x over previous
#include <cuda_runtime.h>
#include <cuda_fp16.h>
#include <math.h>
#include <cstdint>

// ---------------- problem constants ----------------
#define Bc    4
#define Tc    2048
#define Cc    1024
#define Hc    64
#define HSc   16
#define NTOK  (Bc*Tc)            // 8192
#define C4    (Cc/4)             // 256
#define NC    (NTOK*Cc)
#define DM4   128
#define DDEC  64
#define P_SEG 16
#define TSEG  (Tc/P_SEG)         // 128
#define NSEG  (Bc*Hc*P_SEG)      // 4096

// ---------------- scratch ----------------
// fp32
__device__ __align__(16) float g_y  [NC];
__device__ __align__(16) float g_we [NC];
__device__ __align__(16) float g_sseg[NSEG*256];
__device__ __align__(16) float g_sin [NSEG*256];
__device__ __align__(16) float g_wp  [NSEG*16];
// fp16 activations
__device__ __align__(16) __half g16_xxx[NC];       // reused as yn
__device__ __align__(16) __half g16_xw [NC];
__device__ __align__(16) __half g16_xk [NC];
__device__ __align__(16) __half g16_xv [NC];
__device__ __align__(16) __half g16_xr [NC];
__device__ __align__(16) __half g16_r  [NC];
__device__ __align__(16) __half g16_k  [NC];
__device__ __align__(16) __half g16_v  [NC];
__device__ __align__(16) __half g16_h  [NTOK*DM4];
__device__ __align__(16) __half g16_t1 [NTOK*DDEC];
// fp16 weights
__device__ __align__(16) __half g16_wr [Cc*Cc];
__device__ __align__(16) __half g16_wk [Cc*Cc];
__device__ __align__(16) __half g16_wv [Cc*Cc];
__device__ __align__(16) __half g16_wo [Cc*Cc];
__device__ __align__(16) __half g16_w1 [Cc*DM4];
__device__ __align__(16) __half g16_dw1[Cc*DDEC];
__device__ __align__(16) __half g16_dw2[DDEC*Cc];
__device__ __align__(16) __half g16_w2 [4*32*Cc];

// ---------------- helpers ----------------
__device__ __forceinline__ uint32_t smem_u32(const void* p) {
    uint32_t a;
    asm("{ .reg .u64 t; cvta.to.shared.u64 t, %1; cvt.u32.u64 %0, t; }" : "=r"(a) : "l"(p));
    return a;
}
__device__ __forceinline__ void ldsm4(uint32_t* r, uint32_t addr) {
    asm volatile("ldmatrix.sync.aligned.m8n8.x4.shared.b16 {%0,%1,%2,%3}, [%4];"
        : "=r"(r[0]), "=r"(r[1]), "=r"(r[2]), "=r"(r[3]) : "r"(addr));
}
__device__ __forceinline__ void ldsm4t(uint32_t* r, uint32_t addr) {
    asm volatile("ldmatrix.sync.aligned.m8n8.x4.trans.shared.b16 {%0,%1,%2,%3}, [%4];"
        : "=r"(r[0]), "=r"(r[1]), "=r"(r[2]), "=r"(r[3]) : "r"(addr));
}
__device__ __forceinline__ void mma16816(float* d, const uint32_t* a, const uint32_t* b) {
    asm volatile(
        "mma.sync.aligned.m16n8k16.row.col.f32.f16.f16.f32 "
        "{%0,%1,%2,%3}, {%4,%5,%6,%7}, {%8,%9}, {%0,%1,%2,%3};"
        : "+f"(d[0]), "+f"(d[1]), "+f"(d[2]), "+f"(d[3])
        : "r"(a[0]), "r"(a[1]), "r"(a[2]), "r"(a[3]), "r"(b[0]), "r"(b[1]));
}
__device__ __forceinline__ void cp16(uint32_t sdst, const void* gsrc) {
    asm volatile("cp.async.cg.shared.global [%0], [%1], 16;" :: "r"(sdst), "l"(gsrc));
}
#define CP_COMMIT() asm volatile("cp.async.commit_group;")
#define CP_WAIT1()  asm volatile("cp.async.wait_group 1;")
#define CP_WAIT0()  asm volatile("cp.async.wait_group 0;")

__device__ __forceinline__ uint32_t h2u(float a, float b) {
    __half2 h = __floats2half2_rn(a, b);
    return *reinterpret_cast<uint32_t*>(&h);
}
__device__ __forceinline__ uint2 f4toh(float4 v) {
    return make_uint2(h2u(v.x, v.y), h2u(v.z, v.w));
}

// ---------------- one-shot weight convert (8 segments) ----------------
struct CvtArgs {
    const float4* s[8];
    uint2* d[8];
    int off[9];
};
__global__ void __launch_bounds__(256) k_cvt(CvtArgs a) {
    int i = blockIdx.x * 256 + threadIdx.x;
    if (i >= a.off[8]) return;
#pragma unroll
    for (int sg = 0; sg < 8; sg++) {
        if (i < a.off[sg + 1]) {
            int j = i - a.off[sg];
            a.d[sg][j] = f4toh(a.s[sg][j]);
            return;
        }
    }
}

// ---------------- GEMM: fp16, cp.async 3-stage BK=64, mma.sync ----------------
enum { EPI_NONE = 0, EPI_TANH = 1, EPI_WEXP = 2 };

template<int BM, int BN, int EPI, int OUTH>
struct GemmBody {
    static __device__ __forceinline__ void run(
        const __half* __restrict__ A, const __half* __restrict__ B,
        void* __restrict__ C, int nT, int lda, int ldb, int ldc,
        const float* __restrict__ bias, char* smem,
        int rowBase, int colBase)
    {
        constexpr int BK   = 64;
        constexpr int S    = 3;
        constexpr int ASTR = BK + 8;      // 72
        constexpr int BSTR = BN + 8;
        constexpr int ABYT = BM * ASTR * 2;
        constexpr int BBYT = BK * BSTR * 2;
        constexpr int MFR  = BM / 32;
        constexpr int NFR  = BN / 32;
        constexpr int A_CH = BM * (BK / 8) / 256;
        constexpr int B_CH = BK * (BN / 8) / 256;
        constexpr int ASH  = (BK == 64) ? 3 : 2;
        constexpr int BSH  = (BN == 128) ? 4 : 3;
        constexpr int KH   = BK / 16;

        char* As = smem;
        char* Bs = smem + S * ABYT;

        const int tid  = threadIdx.x;
        const int wid  = tid >> 5;
        const int lane = tid & 31;
        const int warpM = (wid >> 2) * (BM / 2);
        const int warpN = (wid & 3) * (BN / 4);

        const uint32_t aBase = smem_u32(As);
        const uint32_t bBase = smem_u32(Bs);
        const int lrow  = lane & 15;
        const int lhalf = (lane >> 4) * 8;
        const uint32_t aLane = (uint32_t)((warpM + lrow) * ASTR + lhalf) * 2;
        const uint32_t bLane = (uint32_t)(lrow * BSTR + warpN + lhalf) * 2;

        float acc[MFR][NFR][4];
#pragma unroll
        for (int i = 0; i < MFR; i++)
#pragma unroll
            for (int j = 0; j < NFR; j++)
#pragma unroll
                for (int e = 0; e < 4; e++) acc[i][j][e] = 0.f;

        auto issue = [&](int t) {
            const int kt = t * BK;
            const int sb = t % S;
            uint32_t ad = aBase + sb * ABYT;
            uint32_t bd = bBase + sb * BBYT;
#pragma unroll
            for (int i = 0; i < A_CH; i++) {
                int idx = i * 256 + tid;
                int r = idx >> ASH, ch = idx & ((1 << ASH) - 1);
                cp16(ad + (uint32_t)(r * ASTR + ch * 8) * 2,
                     A + (size_t)(rowBase + r) * lda + kt + ch * 8);
            }
#pragma unroll
            for (int i = 0; i < B_CH; i++) {
                int idx = i * 256 + tid;
                int r = idx >> BSH, ch = idx & ((1 << BSH) - 1);
                cp16(bd + (uint32_t)(r * BSTR + ch * 8) * 2,
                     B + (size_t)(kt + r) * ldb + colBase + ch * 8);
            }
        };

#pragma unroll
        for (int s = 0; s < S - 1; ++s) {
            if (s < nT) issue(s);
            CP_COMMIT();
        }

        for (int t = 0; t < nT; ++t) {
            CP_WAIT1();
            __syncthreads();
            if (t + S - 1 < nT) issue(t + S - 1);
            CP_COMMIT();

            const int sb = t % S;
            const uint32_t ad = aBase + sb * ABYT;
            const uint32_t bd = bBase + sb * BBYT;
#pragma unroll
            for (int k16 = 0; k16 < KH; ++k16) {
                uint32_t af[MFR][4];
                uint32_t bf[NFR][2];
#pragma unroll
                for (int mi = 0; mi < MFR; mi++)
                    ldsm4(af[mi], ad + aLane + (uint32_t)(mi * 16 * ASTR + k16 * 16) * 2);
#pragma unroll
                for (int p = 0; p < NFR / 2; p++)
                    ldsm4t(&bf[p * 2][0], bd + bLane + (uint32_t)(k16 * 16 * BSTR + p * 16) * 2);
#pragma unroll
                for (int mi = 0; mi < MFR; mi++)
#pragma unroll
                    for (int ni = 0; ni < NFR; ni++)
                        mma16816(acc[mi][ni], af[mi], bf[ni]);
            }
        }

        // ---- epilogue ----
        const int row0 = rowBase + warpM + (lane >> 2);
        const int col0 = colBase + warpN + (lane & 3) * 2;
#pragma unroll
        for (int mi = 0; mi < MFR; mi++) {
#pragma unroll
            for (int ni = 0; ni < NFR; ni++) {
#pragma unroll
                for (int half = 0; half < 2; half++) {
                    int row = row0 + mi * 16 + half * 8;
                    int col = col0 + ni * 8;
                    float v0 = acc[mi][ni][half * 2 + 0];
                    float v1 = acc[mi][ni][half * 2 + 1];
                    if (EPI == EPI_TANH) {
                        v0 = tanhf(v0); v1 = tanhf(v1);
                    } else if (EPI == EPI_WEXP) {
                        v0 = expf(-expf(bias[col] + v0));
                        v1 = expf(-expf(bias[col + 1] + v1));
                    }
                    if (OUTH) {
                        *(uint32_t*)((__half*)C + (size_t)row * ldc + col) = h2u(v0, v1);
                    } else {
                        float* co = (float*)C + (size_t)row * ldc + col;
                        co[0] = v0; co[1] = v1;
                    }
                }
            }
        }
    }
};

template<int BM, int BN, int EPI, int OUTH>
__global__ void __launch_bounds__(256, 2)
gemmh(const __half* __restrict__ A, const __half* __restrict__ B,
      void* __restrict__ C, int nT, int lda, int ldb, int ldc,
      const float* __restrict__ bias)
{
    extern __shared__ char smem[];
    GemmBody<BM, BN, EPI, OUTH>::run(A, B, C, nT, lda, ldb, ldc, bias, smem,
                                     blockIdx.x * BM, blockIdx.y * BN);
}

// batched: z=0..2 -> r/k/v projections (fp16 out), z=3 -> wexp (fp32 out)
struct BatchArgs {
    const __half* A[4]; const __half* B[4]; void* C[4];
    int nT[4]; int lda[4];
    const float* bias;
};
__global__ void __launch_bounds__(256, 2)
gemmh_batch(BatchArgs args)
{
    extern __shared__ char smem[];
    const int z = blockIdx.z;
    if (z < 3) {
        GemmBody<128, 128, EPI_NONE, 1>::run(args.A[z], args.B[z], args.C[z],
                                             args.nT[z], args.lda[z], Cc, Cc, nullptr, smem,
                                             blockIdx.x * 128, blockIdx.y * 128);
    } else {
        GemmBody<128, 128, EPI_WEXP, 0>::run(args.A[3], args.B[3], args.C[3],
                                             args.nT[3], args.lda[3], Cc, Cc, args.bias, smem,
                                             blockIdx.x * 128, blockIdx.y * 128);
    }
}

// ---------------- fused mix kernel: stage all 4 f, single epilogue ----------------
#define HST2 136
#define BST2 72
#define MIX_SMEM ((64*HST2 + 128*BST2 + 4*64*BST2) * 2)

__global__ void __launch_bounds__(256, 3)
k_mix(const __half* __restrict__ h16, const __half* __restrict__ w2h,
      const float* __restrict__ xf,
      const float* __restrict__ tmw, const float* __restrict__ tmk,
      const float* __restrict__ tmv, const float* __restrict__ tmr,
      __half* __restrict__ oxw, __half* __restrict__ oxk,
      __half* __restrict__ oxv, __half* __restrict__ oxr)
{
    extern __shared__ char smem[];
    uint16_t* hs  = (uint16_t*)smem;                                  // [64][136]
    uint16_t* wsm = (uint16_t*)(smem + 64 * HST2 * 2);                // [128][72]
    uint16_t* st  = (uint16_t*)(smem + (64 * HST2 + 128 * BST2) * 2); // [4][64][72]

    const int tid  = threadIdx.x;
    const int wid  = tid >> 5;
    const int lane = tid & 31;
    const int warpM = (wid >> 2) * 32;
    const int warpN = (wid & 3) * 16;
    const int rowBase = blockIdx.x * 64;
    const int colBase = blockIdx.y * 64;

    const uint32_t hsB = smem_u32(hs);
    const uint32_t wB  = smem_u32(wsm);

#pragma unroll
    for (int i = 0; i < 4; i++) {
        int idx = i * 256 + tid;
        int r = idx >> 4, ch = idx & 15;
        cp16(hsB + (uint32_t)(r * HST2 + ch * 8) * 2,
             h16 + (size_t)(rowBase + r) * DM4 + ch * 8);
    }
#pragma unroll
    for (int i = 0; i < 4; i++) {
        int idx = i * 256 + tid;
        int r = idx >> 3, ch = idx & 7;
        cp16(wB + (uint32_t)(r * BST2 + ch * 8) * 2,
             w2h + (size_t)r * Cc + colBase + ch * 8);
    }
    CP_COMMIT();
    CP_WAIT0();
    __syncthreads();

    const int lrow  = lane & 15;
    const int lhalf = (lane >> 4) * 8;
    const uint32_t aLane = (uint32_t)((warpM + lrow) * HST2 + lhalf) * 2;
    const uint32_t bLane = (uint32_t)(lrow * BST2 + warpN + lhalf) * 2;

#pragma unroll
    for (int f = 0; f < 4; f++) {
        float acc[2][2][4];
#pragma unroll
        for (int i = 0; i < 2; i++)
#pragma unroll
            for (int j = 0; j < 2; j++)
#pragma unroll
                for (int e = 0; e < 4; e++) acc[i][j][e] = 0.f;

#pragma unroll
        for (int k16 = 0; k16 < 2; ++k16) {
            uint32_t af[2][4];
            uint32_t bf[2][2];
#pragma unroll
            for (int mi = 0; mi < 2; mi++)
                ldsm4(af[mi], hsB + aLane + (uint32_t)(mi * 16 * HST2 + f * 32 + k16 * 16) * 2);
            ldsm4t(&bf[0][0], wB + bLane + (uint32_t)((f * 32 + k16 * 16) * BST2) * 2);
#pragma unroll
            for (int mi = 0; mi < 2; mi++)
#pragma unroll
                for (int ni = 0; ni < 2; ni++)
                    mma16816(acc[mi][ni], af[mi], bf[ni]);
        }

#pragma unroll
        for (int mi = 0; mi < 2; mi++)
#pragma unroll
            for (int ni = 0; ni < 2; ni++)
#pragma unroll
                for (int half = 0; half < 2; half++) {
                    int srow = warpM + mi * 16 + half * 8 + (lane >> 2);
                    int scol = warpN + ni * 8 + (lane & 3) * 2;
                    *(uint32_t*)&st[(f * 64 + srow) * BST2 + scol] =
                        h2u(acc[mi][ni][half * 2], acc[mi][ni][half * 2 + 1]);
                }
    }
    __syncthreads();

    // single epilogue: read x (and x_prev) once, write all 4 outputs
#pragma unroll
    for (int it = 0; it < 2; ++it) {
        int idx = it * 256 + tid;
        int row = idx >> 3, seg = idx & 7;
        int gcol = colBase + seg * 8;
        int grow = rowBase + row;
        size_t goff = (size_t)grow * Cc + gcol;
        float4 xa = *(const float4*)(xf + goff);
        float4 xb = *(const float4*)(xf + goff + 4);
        float4 pa, pb;
        if ((grow & (Tc - 1)) == 0) {
            pa = make_float4(0.f, 0.f, 0.f, 0.f);
            pb = pa;
        } else {
            pa = *(const float4*)(xf + goff - Cc);
            pb = *(const float4*)(xf + goff - Cc + 4);
        }
        float4 xxa, xxb;
        xxa.x = pa.x - xa.x; xxa.y = pa.y - xa.y; xxa.z = pa.z - xa.z; xxa.w = pa.w - xa.w;
        xxb.x = pb.x - xb.x; xxb.y = pb.y - xb.y; xxb.z = pb.z - xb.z; xxb.w = pb.w - xb.w;
#pragma unroll
        for (int f = 0; f < 4; f++) {
            const float* tmf = (f == 0) ? tmw : (f == 1) ? tmk : (f == 2) ? tmv : tmr;
            __half* of = (f == 0) ? oxw : (f == 1) ? oxk : (f == 2) ? oxv : oxr;
            uint4 mv = *(uint4*)&st[(f * 64 + row) * BST2 + seg * 8];
            float4 ta = *(const float4*)(tmf + gcol);
            float4 tb = *(const float4*)(tmf + gcol + 4);
            __half2 m0 = *(__half2*)&mv.x;
            __half2 m1 = *(__half2*)&mv.y;
            __half2 m2 = *(__half2*)&mv.z;
            __half2 m3 = *(__half2*)&mv.w;
            float v0 = fmaf(xxa.x, ta.x + __low2float(m0),  xa.x);
            float v1 = fmaf(xxa.y, ta.y + __high2float(m0), xa.y);
            float v2 = fmaf(xxa.z, ta.z + __low2float(m1),  xa.z);
            float v3 = fmaf(xxa.w, ta.w + __high2float(m1), xa.w);
            float v4 = fmaf(xxb.x, tb.x + __low2float(m2),  xb.x);
            float v5 = fmaf(xxb.y, tb.y + __high2float(m2), xb.y);
            float v6 = fmaf(xxb.z, tb.z + __low2float(m3),  xb.z);
            float v7 = fmaf(xxb.w, tb.w + __high2float(m3), xb.w);
            uint4 o;
            o.x = h2u(v0, v1); o.y = h2u(v2, v3);
            o.z = h2u(v4, v5); o.w = h2u(v6, v7);
            *(uint4*)(of + goff) = o;
        }
    }
}

// ---------------- token shift: xxx fp16 only ----------------
__global__ void __launch_bounds__(256) k_shift(const float4* __restrict__ x,
                                               const float4* __restrict__ tmx,
                                               uint2* __restrict__ oxxx16)
{
    int i = blockIdx.x * 256 + threadIdx.x;
    int c4 = i & (C4 - 1);
    int n  = i >> 8;
    int t  = n & (Tc - 1);
    float4 xv = x[i];
    float4 xp = make_float4(0.f, 0.f, 0.f, 0.f);
    if (t != 0) xp = x[i - C4];
    float4 tm = tmx[c4];
    float4 o;
    o.x = fmaf(xp.x - xv.x, tm.x, xv.x);
    o.y = fmaf(xp.y - xv.y, tm.y, xv.y);
    o.z = fmaf(xp.z - xv.z, tm.z, xv.z);
    o.w = fmaf(xp.w - xv.w, tm.w, xv.w);
    oxxx16[i] = f4toh(o);
}

// ---------------- WKV6 chunked scan (k/v/r fp16, w fp32) ----------------
#define WKV_CT 64

__global__ void __launch_bounds__(64) k_wkv1(const __half* __restrict__ k,
                                             const __half* __restrict__ v,
                                             const float* __restrict__ w,
                                             float* __restrict__ Sseg,
                                             float* __restrict__ Wseg)
{
    const int p  = blockIdx.x;
    const int bh = blockIdx.y;
    const int b = bh >> 6, h = bh & 63;
    const int tid  = threadIdx.x;
    const int wq   = tid >> 5;
    const int lane = tid & 31;
    const int j  = wq * 8 + (lane & 7);
    const int ig = lane >> 3;
    const int base = (b * Tc + p * TSEG) * (Hc * HSc) + h * HSc;

    __shared__ __align__(16) __half ks16[2][WKV_CT][16];
    __shared__ __align__(16) __half vs16[2][WKV_CT][16];
    __shared__ __align__(16) float  ws  [2][WKV_CT][16];

    float S0 = 0.f, S1 = 0.f, S2 = 0.f, S3 = 0.f;
    float wp0 = 1.f, wp1 = 1.f, wp2 = 1.f, wp3 = 1.f;

    auto issue_chunk = [&](int t0, int buf) {
#pragma unroll
        for (int i = 0; i < 2; i++) {
            int idx = i * 64 + tid;
            int tt = idx >> 1;
            int i8 = (idx & 1) * 8;
            int off = base + (t0 + tt) * (Hc * HSc) + i8;
            cp16(smem_u32(&ks16[buf][tt][i8]), k + off);
            cp16(smem_u32(&vs16[buf][tt][i8]), v + off);
        }
#pragma unroll
        for (int i = 0; i < 4; i++) {
            int idx = i * 64 + tid;
            int tt = idx >> 2;
            int i4 = (idx & 3) * 4;
            int off = base + (t0 + tt) * (Hc * HSc) + i4;
            cp16(smem_u32(&ws[buf][tt][i4]), w + off);
        }
        CP_COMMIT();
    };

    issue_chunk(0, 0);
    const int nChunks = TSEG / WKV_CT;
    for (int c = 0; c < nChunks; ++c) {
        const int buf = c & 1;
        if (c + 1 < nChunks) {
            issue_chunk((c + 1) * WKV_CT, buf ^ 1);
            CP_WAIT1();
        } else {
            CP_WAIT0();
        }
        __syncthreads();
        for (int tt = 0; tt < WKV_CT; ++tt) {
            uint2 kraw = *(const uint2*)&ks16[buf][tt][ig * 4];
            float2 k01 = __half22float2(*(const __half2*)&kraw.x);
            float2 k23 = __half22float2(*(const __half2*)&kraw.y);
            float4 ww = *(const float4*)&ws[buf][tt][ig * 4];
            float vj = __half2float(vs16[buf][tt][j]);
            S0 = fmaf(ww.x, S0, k01.x * vj);
            S1 = fmaf(ww.y, S1, k01.y * vj);
            S2 = fmaf(ww.z, S2, k23.x * vj);
            S3 = fmaf(ww.w, S3, k23.y * vj);
            wp0 *= ww.x; wp1 *= ww.y; wp2 *= ww.z; wp3 *= ww.w;
        }
        __syncthreads();
    }

    const size_t so = ((size_t)(bh * P_SEG + p) << 8) + (ig * 4) * 16 + j;
    Sseg[so]      = S0;
    Sseg[so + 16] = S1;
    Sseg[so + 32] = S2;
    Sseg[so + 48] = S3;
    if (wq == 0 && (lane & 7) == 0) {
        float* wo = Wseg + (size_t)(bh * P_SEG + p) * 16 + ig * 4;
        wo[0] = wp0; wo[1] = wp1; wo[2] = wp2; wo[3] = wp3;
    }
}

__global__ void __launch_bounds__(256) k_wscan(const float* __restrict__ Sseg,
                                               const float* __restrict__ Wseg,
                                               float* __restrict__ Sin)
{
    const int bh = blockIdx.x;
    const int tid = threadIdx.x;
    const int i = tid >> 4;
    float s = 0.f;
#pragma unroll
    for (int p = 0; p < P_SEG; ++p) {
        size_t o = (size_t)(bh * P_SEG + p) << 8;
        Sin[o + tid] = s;
        s = fmaf(Wseg[(size_t)(bh * P_SEG + p) * 16 + i], s, Sseg[o + tid]);
    }
}

__global__ void __launch_bounds__(64) k_wkv2(const float* __restrict__ u_faaaa,
                                             const __half* __restrict__ r,
                                             const __half* __restrict__ k,
                                             const __half* __restrict__ v,
                                             const float* __restrict__ w,
                                             const float* __restrict__ Sin,
                                             float* __restrict__ y)
{
    const int p  = blockIdx.x;
    const int bh = blockIdx.y;
    const int b = bh >> 6, h = bh & 63;
    const int tid  = threadIdx.x;
    const int wq   = tid >> 5;
    const int lane = tid & 31;
    const int j  = wq * 8 + (lane & 7);
    const int ig = lane >> 3;
    const int base = (b * Tc + p * TSEG) * (Hc * HSc) + h * HSc;

    __shared__ __align__(16) __half rs16[2][WKV_CT][16];
    __shared__ __align__(16) __half ks16[2][WKV_CT][16];
    __shared__ __align__(16) __half vs16[2][WKV_CT][16];
    __shared__ __align__(16) float  ws  [2][WKV_CT][16];

    const size_t so = ((size_t)(bh * P_SEG + p) << 8) + (ig * 4) * 16 + j;
    float S0 = Sin[so], S1 = Sin[so + 16], S2 = Sin[so + 32], S3 = Sin[so + 48];
    const float4 u4 = *(const float4*)(u_faaaa + h * HSc + ig * 4);

    auto issue_chunk = [&](int t0, int buf) {
#pragma unroll
        for (int i = 0; i < 2; i++) {
            int idx = i * 64 + tid;
            int tt = idx >> 1;
            int i8 = (idx & 1) * 8;
            int off = base + (t0 + tt) * (Hc * HSc) + i8;
            cp16(smem_u32(&rs16[buf][tt][i8]), r + off);
            cp16(smem_u32(&ks16[buf][tt][i8]), k + off);
            cp16(smem_u32(&vs16[buf][tt][i8]), v + off);
        }
#pragma unroll
        for (int i = 0; i < 4; i++) {
            int idx = i * 64 + tid;
            int tt = idx >> 2;
            int i4 = (idx & 3) * 4;
            int off = base + (t0 + tt) * (Hc * HSc) + i4;
            cp16(smem_u32(&ws[buf][tt][i4]), w + off);
        }
        CP_COMMIT();
    };

    issue_chunk(0, 0);
    const int nChunks = TSEG / WKV_CT;
    for (int c = 0; c < nChunks; ++c) {
        const int buf = c & 1;
        if (c + 1 < nChunks) {
            issue_chunk((c + 1) * WKV_CT, buf ^ 1);
            CP_WAIT1();
        } else {
            CP_WAIT0();
        }
        __syncthreads();

        const int ybase = base + c * WKV_CT * (Hc * HSc) + j;
        for (int tt = 0; tt < WKV_CT; ++tt) {
            uint2 rraw = *(const uint2*)&rs16[buf][tt][ig * 4];
            uint2 kraw = *(const uint2*)&ks16[buf][tt][ig * 4];
            float2 r01 = __half22float2(*(const __half2*)&rraw.x);
            float2 r23 = __half22float2(*(const __half2*)&rraw.y);
            float2 k01 = __half22float2(*(const __half2*)&kraw.x);
            float2 k23 = __half22float2(*(const __half2*)&kraw.y);
            float4 ww = *(const float4*)&ws[buf][tt][ig * 4];
            float vj = __half2float(vs16[buf][tt][j]);
            float kv, acc;
            kv = k01.x * vj; acc = r01.x * fmaf(u4.x, kv, S0);           S0 = fmaf(ww.x, S0, kv);
            kv = k01.y * vj; acc = fmaf(r01.y, fmaf(u4.y, kv, S1), acc); S1 = fmaf(ww.y, S1, kv);
            kv = k23.x * vj; acc = fmaf(r23.x, fmaf(u4.z, kv, S2), acc); S2 = fmaf(ww.z, S2, kv);
            kv = k23.y * vj; acc = fmaf(r23.y, fmaf(u4.w, kv, S3), acc); S3 = fmaf(ww.w, S3, kv);
            acc += __shfl_xor_sync(0xffffffffu, acc, 8);
            acc += __shfl_xor_sync(0xffffffffu, acc, 16);
            if (ig == 0) y[ybase + tt * (Hc * HSc)] = acc;
        }
        __syncthreads();
    }
}

// ---------------- LayerNorm -> fp16 ----------------
__global__ void __launch_bounds__(256) k_ln(const float* __restrict__ y,
                                            const float* __restrict__ g,
                                            const float* __restrict__ bb,
                                            uint2* __restrict__ out16)
{
    const int n   = blockIdx.x;
    const int tid = threadIdx.x;
    const float4* yr = (const float4*)(y + (size_t)n * Cc);
    float4 vv = yr[tid];
    float s = vv.x + vv.y + vv.z + vv.w;
    float q = vv.x * vv.x + vv.y * vv.y + vv.z * vv.z + vv.w * vv.w;
#pragma unroll
    for (int o = 16; o > 0; o >>= 1) {
        s += __shfl_xor_sync(0xffffffffu, s, o);
        q += __shfl_xor_sync(0xffffffffu, q, o);
    }
    __shared__ float ssh[8], qsh[8];
    if ((tid & 31) == 0) { ssh[tid >> 5] = s; qsh[tid >> 5] = q; }
    __syncthreads();
    float st = 0.f, qt = 0.f;
#pragma unroll
    for (int wix = 0; wix < 8; wix++) { st += ssh[wix]; qt += qsh[wix]; }
    float mean = st * (1.0f / Cc);
    float var  = qt * (1.0f / Cc) - mean * mean;
    float rstd = rsqrtf(var + 1e-5f);
    float4 gg = ((const float4*)g)[tid];
    float4 b4 = ((const float4*)bb)[tid];
    float4 o;
    o.x = (vv.x - mean) * rstd * gg.x + b4.x;
    o.y = (vv.y - mean) * rstd * gg.y + b4.y;
    o.z = (vv.z - mean) * rstd * gg.z + b4.z;
    o.w = (vv.w - mean) * rstd * gg.w + b4.w;
    out16[(size_t)n * (Cc / 4) + tid] = f4toh(o);
}

// ---------------- launcher ----------------
// BK=64, 3 stages
#define SM128_64 (3*(128*72*2 + 64*136*2))
#define SM64_64  (3*(64*72*2 + 64*72*2))

extern "C" void kernel_launch(void* const* d_in, const int* in_sizes, int n_in,
                              void* d_out, int out_size)
{
    (void)in_sizes; (void)n_in; (void)out_size;
    const float* x     = (const float*)d_in[0];
    const float* tmx   = (const float*)d_in[1];
    const float* tmw   = (const float*)d_in[2];
    const float* tmk   = (const float*)d_in[3];
    const float* tmv   = (const float*)d_in[4];
    const float* tmr   = (const float*)d_in[5];
    const float* w1    = (const float*)d_in[6];
    const float* w2    = (const float*)d_in[7];
    const float* tdec  = (const float*)d_in[8];
    const float* dw1   = (const float*)d_in[9];
    const float* dw2   = (const float*)d_in[10];
    const float* faaaa = (const float*)d_in[11];
    const float* Wr    = (const float*)d_in[12];
    const float* Wk    = (const float*)d_in[13];
    const float* Wv    = (const float*)d_in[14];
    const float* Wo    = (const float*)d_in[15];
    const float* lng   = (const float*)d_in[16];
    const float* lnb   = (const float*)d_in[17];
    float* out = (float*)d_out;

    static float *p_y = nullptr, *p_we, *p_ss, *p_si, *p_wp;
    static __half *p16_xxx, *p16_xw, *p16_xk, *p16_xv, *p16_xr,
                  *p16_r, *p16_k, *p16_v, *p16_h, *p16_t1,
                  *p16_wr, *p16_wk, *p16_wv, *p16_wo, *p16_w1, *p16_dw1, *p16_dw2, *p16_w2;
    if (!p_y) {
        cudaGetSymbolAddress((void**)&p_y,     g_y);
        cudaGetSymbolAddress((void**)&p_we,    g_we);
        cudaGetSymbolAddress((void**)&p_ss,    g_sseg);
        cudaGetSymbolAddress((void**)&p_si,    g_sin);
        cudaGetSymbolAddress((void**)&p_wp,    g_wp);
        cudaGetSymbolAddress((void**)&p16_xxx, g16_xxx);
        cudaGetSymbolAddress((void**)&p16_xw,  g16_xw);
        cudaGetSymbolAddress((void**)&p16_xk,  g16_xk);
        cudaGetSymbolAddress((void**)&p16_xv,  g16_xv);
        cudaGetSymbolAddress((void**)&p16_xr,  g16_xr);
        cudaGetSymbolAddress((void**)&p16_r,   g16_r);
        cudaGetSymbolAddress((void**)&p16_k,   g16_k);
        cudaGetSymbolAddress((void**)&p16_v,   g16_v);
        cudaGetSymbolAddress((void**)&p16_h,   g16_h);
        cudaGetSymbolAddress((void**)&p16_t1,  g16_t1);
        cudaGetSymbolAddress((void**)&p16_wr,  g16_wr);
        cudaGetSymbolAddress((void**)&p16_wk,  g16_wk);
        cudaGetSymbolAddress((void**)&p16_wv,  g16_wv);
        cudaGetSymbolAddress((void**)&p16_wo,  g16_wo);
        cudaGetSymbolAddress((void**)&p16_w1,  g16_w1);
        cudaGetSymbolAddress((void**)&p16_dw1, g16_dw1);
        cudaGetSymbolAddress((void**)&p16_dw2, g16_dw2);
        cudaGetSymbolAddress((void**)&p16_w2,  g16_w2);
        cudaFuncSetAttribute(gemmh<128,128,EPI_NONE,0>, cudaFuncAttributeMaxDynamicSharedMemorySize, SM128_64);
        cudaFuncSetAttribute(gemmh<64,64,EPI_TANH,1>,   cudaFuncAttributeMaxDynamicSharedMemorySize, SM64_64);
        cudaFuncSetAttribute(gemmh_batch, cudaFuncAttributeMaxDynamicSharedMemorySize, SM128_64);
        cudaFuncSetAttribute(k_mix, cudaFuncAttributeMaxDynamicSharedMemorySize, MIX_SMEM);
    }
    __half* p16_yn = p16_xxx;      // yn overwrites xxx (dead after h gemm)

    // 0) weight converts — single launch, 8 segments (counts in float4)
    {
        CvtArgs a;
        const float* srcs[8] = { Wr, Wk, Wv, Wo, w1, dw1, dw2, w2 };
        __half* dsts[8] = { p16_wr, p16_wk, p16_wv, p16_wo, p16_w1, p16_dw1, p16_dw2, p16_w2 };
        int cnts[8] = { Cc*Cc/4, Cc*Cc/4, Cc*Cc/4, Cc*Cc/4, Cc*DM4/4, Cc*DDEC/4, DDEC*Cc/4, 4*32*Cc/4 };
        int cum = 0;
        for (int i = 0; i < 8; i++) {
            a.s[i] = (const float4*)srcs[i];
            a.d[i] = (uint2*)dsts[i];
            a.off[i] = cum;
            cum += cnts[i];
        }
        a.off[8] = cum;
        k_cvt<<<(cum + 255) / 256, 256>>>(a);
    }

    // 1) token shift -> xxx fp16
    k_shift<<<NTOK, 256>>>((const float4*)x, (const float4*)tmx, (uint2*)p16_xxx);

    // 2) h = tanh(xxx @ w1)  K=1024 -> nT=16
    gemmh<64,64,EPI_TANH,1><<<dim3(NTOK/64, DM4/64), 256, SM64_64>>>(
        p16_xxx, p16_w1, p16_h, Cc/64, Cc, DM4, DM4, nullptr);

    // 3) fused mix: xw/xk/xv/xr (xx computed inline from x)
    k_mix<<<dim3(NTOK/64, Cc/64), 256, MIX_SMEM>>>(
        p16_h, p16_w2, x, tmw, tmk, tmv, tmr,
        p16_xw, p16_xk, p16_xv, p16_xr);

    // 4) t1 = tanh(xw @ dw1)  K=1024 -> nT=16
    gemmh<64,64,EPI_TANH,1><<<dim3(NTOK/64, 1), 256, SM64_64>>>(
        p16_xw, p16_dw1, p16_t1, Cc/64, Cc, DDEC, DDEC, nullptr);

    // 5) batched: r/k/v projections (fp16 out) + wexp
    {
        BatchArgs ba;
        ba.A[0] = p16_xr; ba.B[0] = p16_wr; ba.C[0] = p16_r; ba.nT[0] = Cc/64; ba.lda[0] = Cc;
        ba.A[1] = p16_xk; ba.B[1] = p16_wk; ba.C[1] = p16_k; ba.nT[1] = Cc/64; ba.lda[1] = Cc;
        ba.A[2] = p16_xv; ba.B[2] = p16_wv; ba.C[2] = p16_v; ba.nT[2] = Cc/64; ba.lda[2] = Cc;
        ba.A[3] = p16_t1; ba.B[3] = p16_dw2; ba.C[3] = p_we; ba.nT[3] = DDEC/64; ba.lda[3] = DDEC;
        ba.bias = tdec;
        gemmh_batch<<<dim3(NTOK/128, Cc/128, 4), 256, SM128_64>>>(ba);
    }

    // 6) WKV6 chunked scan
    k_wkv1<<<dim3(P_SEG, Bc * Hc), 64>>>(p16_k, p16_v, p_we, p_ss, p_wp);
    k_wscan<<<Bc * Hc, 256>>>(p_ss, p_wp, p_si);
    k_wkv2<<<dim3(P_SEG, Bc * Hc), 64>>>(faaaa, p16_r, p16_k, p16_v, p_we, p_si, p_y);

    // 7) LayerNorm -> fp16
    k_ln<<<NTOK, 256>>>(p_y, lng, lnb, (uint2*)p16_yn);

    // 8) out = yn @ Wo  K=1024 -> nT=16
    gemmh<128,128,EPI_NONE,0><<<dim3(NTOK/128, Cc/128), 256, SM128_64>>>(
        p16_yn, p16_wo, out, Cc/64, Cc, Cc, Cc, nullptr);
}